// round 7
// baseline (speedup 1.0000x reference)
#include <cuda_runtime.h>
#include <cstdint>

#define Bq 2
#define Sq 2048
#define Hq 8
#define DEPTHq 64
#define DMq 512
#define NTOK (Bq * Sq)
#define NROWS (2 * NTOK)
#define CC 1536
#define BHq (Bq * Hq)

// ---------------- device scratch ----------------
__device__ float g_C[NROWS * CC];
__device__ float g_Qh[BHq * Sq * 128];
__device__ float g_Kh[BHq * Sq * 128];
__device__ float g_Vh[BHq * Sq * DEPTHq];
__device__ float g_Zp[2][NTOK * DMq];
__device__ float g_rowsum[BHq * Sq];
__device__ float g_attn_fallback[(size_t)BHq * Sq * Sq];

// ---------------- tf32 helpers ----------------
__device__ __forceinline__ uint32_t f2tf32(float f) {
    uint32_t u;
    asm("cvt.rna.tf32.f32 %0, %1;" : "=r"(u) : "f"(f));
    return u;
}
__device__ __forceinline__ float tfbits(float f) {
    return __uint_as_float(f2tf32(f));
}
__device__ __forceinline__ void mma8(float* c, const uint32_t* a, const uint32_t* b) {
    asm volatile(
        "mma.sync.aligned.m16n8k8.row.col.f32.tf32.tf32.f32 "
        "{%0,%1,%2,%3}, {%4,%5,%6,%7}, {%8,%9}, {%0,%1,%2,%3};"
        : "+f"(c[0]), "+f"(c[1]), "+f"(c[2]), "+f"(c[3])
        : "r"(a[0]), "r"(a[1]), "r"(a[2]), "r"(a[3]),
          "r"(b[0]), "r"(b[1]));
}
__device__ __forceinline__ void sts_row8(float2* base, float4 v0, float4 v1) {
    float4 w0 = make_float4(tfbits(v0.x), tfbits(v1.x), tfbits(v0.y), tfbits(v1.y));
    float4 w1 = make_float4(tfbits(v0.z), tfbits(v1.z), tfbits(v0.w), tfbits(v1.w));
    *reinterpret_cast<float4*>(base)     = w0;
    *reinterpret_cast<float4*>(base + 2) = w1;
}

#define TSTRIDE 132
#define DYN_SMEM 67584   // max(32KB stages, 128*132*4 transpose)

// ============================================================
// Kernel 1: proj  C[8192x1536] = [emb;pe] @ [Wq|Wk|Wv] + bias
// 128x128 tile, BK=16 double-buffered. Transpose epilogue.
// ============================================================
__global__ void __launch_bounds__(256, 2)
proj_gemm_tc(const float* __restrict__ emb, const float* __restrict__ pe,
             const float* __restrict__ Wq, const float* __restrict__ bq,
             const float* __restrict__ Wk, const float* __restrict__ bk,
             const float* __restrict__ Wv, const float* __restrict__ bv) {
    extern __shared__ char dsm[];
    float2 (*As2)[2][128][4] = reinterpret_cast<float2 (*)[2][128][4]>(dsm);
    float2 (*Bs2)[2][128][4] = reinterpret_cast<float2 (*)[2][128][4]>(dsm + 16384);
    float* T = reinterpret_cast<float*>(dsm);

    const int m0 = blockIdx.y * 128;
    const int n0 = blockIdx.x * 128;
    const int tid = threadIdx.x;
    const int wid = tid >> 5, lane = tid & 31;
    const int wm = (wid >> 2) * 64, wn = (wid & 3) * 32;
    const int lg = lane >> 2, lt = lane & 3;

    const float* srcA = (m0 < NTOK) ? (emb + (size_t)m0 * DMq)
                                    : (pe + (size_t)(m0 - NTOK) * DMq);
    const float* W    = (n0 < 512) ? Wq : (n0 < 1024 ? Wk : Wv);
    const float* bias = (n0 < 512) ? bq : (n0 < 1024 ? bk : bv);
    const int colbase = n0 & 511;

    const int sm = tid >> 1;
    const int skc = tid & 1;
    const int bk_ = tid >> 4;
    const int bn_ = (tid & 15) * 8;

    float acc[4][4][4];
#pragma unroll
    for (int i = 0; i < 4; i++)
#pragma unroll
        for (int j = 0; j < 4; j++)
#pragma unroll
            for (int r = 0; r < 4; r++) acc[i][j][r] = 0.f;

    const int NIT = DMq / 16;

    {
        const float* ap = srcA + (size_t)sm * DMq + skc * 8;
        sts_row8(&As2[0][skc][sm][0], *(const float4*)ap, *(const float4*)(ap + 4));
        const float* bp = W + (size_t)bk_ * DMq + colbase + bn_;
        float4 b0 = *(const float4*)(bp);
        float4 b1 = *(const float4*)(bp + 4);
        int kc = bk_ >> 3, lts = bk_ & 3, half = (bk_ >> 2) & 1;
        float* d0 = (float*)&Bs2[0][kc][bn_][lts] + half;
        d0[0] = tfbits(b0.x); d0[8] = tfbits(b0.y); d0[16] = tfbits(b0.z); d0[24] = tfbits(b0.w);
        d0[32] = tfbits(b1.x); d0[40] = tfbits(b1.y); d0[48] = tfbits(b1.z); d0[56] = tfbits(b1.w);
    }
    __syncthreads();

    for (int it = 0; it < NIT; it++) {
        const int st = it & 1;
        float4 a0, a1, b0, b1;
        const bool more = (it + 1 < NIT);
        if (more) {
            int k0 = (it + 1) * 16;
            const float* ap = srcA + (size_t)sm * DMq + k0 + skc * 8;
            a0 = *(const float4*)(ap);
            a1 = *(const float4*)(ap + 4);
            const float* bp = W + (size_t)(k0 + bk_) * DMq + colbase + bn_;
            b0 = *(const float4*)(bp);
            b1 = *(const float4*)(bp + 4);
        }
#pragma unroll
        for (int kc = 0; kc < 2; kc++) {
            uint32_t af[4][4], bf[4][2];
#pragma unroll
            for (int mi = 0; mi < 4; mi++) {
                float2 x0 = As2[st][kc][wm + mi * 16 + lg][lt];
                float2 x1 = As2[st][kc][wm + mi * 16 + 8 + lg][lt];
                af[mi][0] = __float_as_uint(x0.x);
                af[mi][1] = __float_as_uint(x1.x);
                af[mi][2] = __float_as_uint(x0.y);
                af[mi][3] = __float_as_uint(x1.y);
            }
#pragma unroll
            for (int ni = 0; ni < 4; ni++) {
                float2 y = Bs2[st][kc][wn + ni * 8 + lg][lt];
                bf[ni][0] = __float_as_uint(y.x);
                bf[ni][1] = __float_as_uint(y.y);
            }
#pragma unroll
            for (int mi = 0; mi < 4; mi++)
#pragma unroll
                for (int ni = 0; ni < 4; ni++) mma8(acc[mi][ni], af[mi], bf[ni]);
        }
        if (more) {
            sts_row8(&As2[st ^ 1][skc][sm][0], a0, a1);
            int kc = bk_ >> 3, lts = bk_ & 3, half = (bk_ >> 2) & 1;
            float* d0 = (float*)&Bs2[st ^ 1][kc][bn_][lts] + half;
            d0[0] = tfbits(b0.x); d0[8] = tfbits(b0.y); d0[16] = tfbits(b0.z); d0[24] = tfbits(b0.w);
            d0[32] = tfbits(b1.x); d0[40] = tfbits(b1.y); d0[48] = tfbits(b1.z); d0[56] = tfbits(b1.w);
        }
        __syncthreads();
    }

    // Transpose epilogue: acc (+bias) -> smem -> coalesced stores
#pragma unroll
    for (int mi = 0; mi < 4; mi++) {
        int r0 = wm + mi * 16 + lg;
#pragma unroll
        for (int ni = 0; ni < 4; ni++) {
            int c0 = wn + ni * 8 + 2 * lt;
            float bv0 = bias[(n0 + c0) & 511], bv1 = bias[(n0 + c0 + 1) & 511];
            *reinterpret_cast<float2*>(&T[r0 * TSTRIDE + c0]) =
                make_float2(acc[mi][ni][0] + bv0, acc[mi][ni][1] + bv1);
            *reinterpret_cast<float2*>(&T[(r0 + 8) * TSTRIDE + c0]) =
                make_float2(acc[mi][ni][2] + bv0, acc[mi][ni][3] + bv1);
        }
    }
    __syncthreads();
#pragma unroll
    for (int pass = 0; pass < 16; pass++) {
        int row = pass * 8 + wid;
        float4 v = *reinterpret_cast<float4*>(&T[row * TSTRIDE + lane * 4]);
        *reinterpret_cast<float4*>(&g_C[(size_t)(m0 + row) * CC + n0 + lane * 4]) = v;
    }
}

// ============================================================
// Kernel 2: rearrange
// ============================================================
__global__ void rearrange_kernel() {
    int idx = blockIdx.x * blockDim.x + threadIdx.x;
    if (idx >= NTOK * DMq) return;
    int n = idx / DMq;
    int c = idx % DMq;
    int b = n / Sq, s = n % Sq;
    int h = c / DEPTHq, d = c % DEPTHq;

    float Qc = g_C[(size_t)n * CC + c];
    float Qr = g_C[(size_t)(NTOK + n) * CC + c];
    float Kc = g_C[(size_t)n * CC + 512 + c];
    float Kr = g_C[(size_t)(NTOK + n) * CC + 512 + c];
    float Vv = g_C[(size_t)n * CC + 1024 + c];

    size_t base = ((size_t)(b * Hq + h) * Sq + s) * 128;
    g_Qh[base + d]      = (Qc + Qr) * 0.125f;
    g_Qh[base + 64 + d] = Qc * 0.125f;
    g_Kh[base + d]      = Kc;
    g_Kh[base + 64 + d] = Kr;
    g_Vh[((size_t)(b * Hq + h) * Sq + s) * DEPTHq + d] = Vv;
}

__global__ void zero_rowsum() {
    int i = blockIdx.x * 256 + threadIdx.x;
    if (i < BHq * Sq) g_rowsum[i] = 0.f;
}

// ============================================================
// Kernel 3: logits + exp + rowsum. 128x128 tile, BK=16 dbl-buf.
// Transpose epilogue for coalesced attn stores.
// ============================================================
__global__ void __launch_bounds__(256, 2)
logits_gemm_tc(float* __restrict__ attn) {
    extern __shared__ char dsm[];
    float2 (*As2)[2][128][4] = reinterpret_cast<float2 (*)[2][128][4]>(dsm);
    float2 (*Bs2)[2][128][4] = reinterpret_cast<float2 (*)[2][128][4]>(dsm + 16384);
    float* T = reinterpret_cast<float*>(dsm);

    const int bh = blockIdx.z;
    const int q0 = blockIdx.y * 128;
    const int t0 = blockIdx.x * 128;
    const float* Q = g_Qh + (size_t)bh * Sq * 128;
    const float* K = g_Kh + (size_t)bh * Sq * 128;
    float* out = attn + (size_t)bh * Sq * Sq;

    const int tid = threadIdx.x;
    const int wid = tid >> 5, lane = tid & 31;
    const int wm = (wid >> 2) * 64, wn = (wid & 3) * 32;
    const int lg = lane >> 2, lt = lane & 3;

    const int sm = tid >> 1;
    const int skc = tid & 1;

    float acc[4][4][4];
#pragma unroll
    for (int i = 0; i < 4; i++)
#pragma unroll
        for (int j = 0; j < 4; j++)
#pragma unroll
            for (int r = 0; r < 4; r++) acc[i][j][r] = 0.f;

    const int NIT = 128 / 16;

    {
        const float* ap = Q + (size_t)(q0 + sm) * 128 + skc * 8;
        sts_row8(&As2[0][skc][sm][0], *(const float4*)ap, *(const float4*)(ap + 4));
        const float* bp = K + (size_t)(t0 + sm) * 128 + skc * 8;
        sts_row8(&Bs2[0][skc][sm][0], *(const float4*)bp, *(const float4*)(bp + 4));
    }
    __syncthreads();

    for (int it = 0; it < NIT; it++) {
        const int st = it & 1;
        float4 a0, a1, b0, b1;
        const bool more = (it + 1 < NIT);
        if (more) {
            int k0 = (it + 1) * 16;
            const float* ap = Q + (size_t)(q0 + sm) * 128 + k0 + skc * 8;
            a0 = *(const float4*)(ap);
            a1 = *(const float4*)(ap + 4);
            const float* bp = K + (size_t)(t0 + sm) * 128 + k0 + skc * 8;
            b0 = *(const float4*)(bp);
            b1 = *(const float4*)(bp + 4);
        }
#pragma unroll
        for (int kc = 0; kc < 2; kc++) {
            uint32_t af[4][4], bf[4][2];
#pragma unroll
            for (int mi = 0; mi < 4; mi++) {
                float2 x0 = As2[st][kc][wm + mi * 16 + lg][lt];
                float2 x1 = As2[st][kc][wm + mi * 16 + 8 + lg][lt];
                af[mi][0] = __float_as_uint(x0.x);
                af[mi][1] = __float_as_uint(x1.x);
                af[mi][2] = __float_as_uint(x0.y);
                af[mi][3] = __float_as_uint(x1.y);
            }
#pragma unroll
            for (int ni = 0; ni < 4; ni++) {
                float2 y = Bs2[st][kc][wn + ni * 8 + lg][lt];
                bf[ni][0] = __float_as_uint(y.x);
                bf[ni][1] = __float_as_uint(y.y);
            }
#pragma unroll
            for (int mi = 0; mi < 4; mi++)
#pragma unroll
                for (int ni = 0; ni < 4; ni++) mma8(acc[mi][ni], af[mi], bf[ni]);
        }
        if (more) {
            sts_row8(&As2[st ^ 1][skc][sm][0], a0, a1);
            sts_row8(&Bs2[st ^ 1][skc][sm][0], b0, b1);
        }
        __syncthreads();
    }

    // Epilogue: exp + rowsum + smem transpose + coalesced store
#pragma unroll
    for (int mi = 0; mi < 4; mi++) {
        int r0 = wm + mi * 16 + lg;
        float rs0 = 0.f, rs1 = 0.f;
#pragma unroll
        for (int ni = 0; ni < 4; ni++) {
            int c0 = wn + ni * 8 + 2 * lt;
            float e0 = __expf(acc[mi][ni][0]);
            float e1 = __expf(acc[mi][ni][1]);
            float e2 = __expf(acc[mi][ni][2]);
            float e3 = __expf(acc[mi][ni][3]);
            *reinterpret_cast<float2*>(&T[r0 * TSTRIDE + c0]) = make_float2(e0, e1);
            *reinterpret_cast<float2*>(&T[(r0 + 8) * TSTRIDE + c0]) = make_float2(e2, e3);
            rs0 += e0 + e1;
            rs1 += e2 + e3;
        }
        rs0 += __shfl_xor_sync(0xffffffffu, rs0, 1);
        rs0 += __shfl_xor_sync(0xffffffffu, rs0, 2);
        rs1 += __shfl_xor_sync(0xffffffffu, rs1, 1);
        rs1 += __shfl_xor_sync(0xffffffffu, rs1, 2);
        if (lt == 0) {
            atomicAdd(&g_rowsum[bh * Sq + q0 + r0], rs0);
            atomicAdd(&g_rowsum[bh * Sq + q0 + r0 + 8], rs1);
        }
    }
    __syncthreads();
#pragma unroll
    for (int pass = 0; pass < 16; pass++) {
        int row = pass * 8 + wid;
        float4 v = *reinterpret_cast<float4*>(&T[row * TSTRIDE + lane * 4]);
        *reinterpret_cast<float4*>(&out[(size_t)(q0 + row) * Sq + t0 + lane * 4]) = v;
    }
}

// ============================================================
// Kernel 5: fused normalize + z-partial = attn @ V.
// grid (Sq/128, 2 ksplit, BHq) = 512 CTAs, 256 thr, warp 32x32.
// Each (q0, ks) owns attn rows [q0,q0+128) cols [ks*1024, +1024).
// ============================================================
__global__ void __launch_bounds__(256, 2)
zv_fused_tc(float* __restrict__ attn) {
    __shared__ float2 As2[2][2][128][4];
    __shared__ float2 Bs2[2][2][64][4];

    const int bh = blockIdx.z;
    const int q0 = blockIdx.x * 128;
    const int ks = blockIdx.y;
    const int b = bh / Hq, h = bh % Hq;
    float* P = attn + (size_t)bh * Sq * Sq;
    const float* V = g_Vh + ((size_t)bh * Sq + ks * 1024) * DEPTHq;
    float* Zp = g_Zp[ks];

    const int tid = threadIdx.x;
    const int wid = tid >> 5, lane = tid & 31;
    const int wm = (wid >> 1) * 32, wn = (wid & 1) * 32;
    const int lg = lane >> 2, lt = lane & 3;

    const int sm = tid >> 1;
    const int skc = tid & 1;
    const int bk_ = tid >> 4;
    const int bn_ = (tid & 15) * 4;

    const float invs = 1.0f / g_rowsum[bh * Sq + q0 + sm];
    float* prow = P + (size_t)(q0 + sm) * Sq + ks * 1024 + skc * 8;

    float acc[2][4][4];
#pragma unroll
    for (int i = 0; i < 2; i++)
#pragma unroll
        for (int j = 0; j < 4; j++)
#pragma unroll
            for (int r = 0; r < 4; r++) acc[i][j][r] = 0.f;

    const int NIT = 1024 / 16;  // 64

    {
        float4 a0 = *(const float4*)(prow);
        float4 a1 = *(const float4*)(prow + 4);
        a0.x *= invs; a0.y *= invs; a0.z *= invs; a0.w *= invs;
        a1.x *= invs; a1.y *= invs; a1.z *= invs; a1.w *= invs;
        *(float4*)(prow)     = a0;
        *(float4*)(prow + 4) = a1;
        sts_row8(&As2[0][skc][sm][0], a0, a1);
        float4 bv = *(const float4*)(V + (size_t)bk_ * DEPTHq + bn_);
        int kc = bk_ >> 3, lts = bk_ & 3, half = (bk_ >> 2) & 1;
        float* d0 = (float*)&Bs2[0][kc][bn_][lts] + half;
        d0[0] = tfbits(bv.x); d0[8] = tfbits(bv.y); d0[16] = tfbits(bv.z); d0[24] = tfbits(bv.w);
    }
    __syncthreads();

    for (int it = 0; it < NIT; it++) {
        const int st = it & 1;
        float4 a0, a1, bv;
        const bool more = (it + 1 < NIT);
        if (more) {
            int k0 = (it + 1) * 16;
            a0 = *(const float4*)(prow + k0);
            a1 = *(const float4*)(prow + k0 + 4);
            a0.x *= invs; a0.y *= invs; a0.z *= invs; a0.w *= invs;
            a1.x *= invs; a1.y *= invs; a1.z *= invs; a1.w *= invs;
            *(float4*)(prow + k0)     = a0;
            *(float4*)(prow + k0 + 4) = a1;
            bv = *(const float4*)(V + (size_t)(k0 + bk_) * DEPTHq + bn_);
        }
#pragma unroll
        for (int kc = 0; kc < 2; kc++) {
            uint32_t af[2][4], bf[4][2];
#pragma unroll
            for (int mi = 0; mi < 2; mi++) {
                float2 x0 = As2[st][kc][wm + mi * 16 + lg][lt];
                float2 x1 = As2[st][kc][wm + mi * 16 + 8 + lg][lt];
                af[mi][0] = __float_as_uint(x0.x);
                af[mi][1] = __float_as_uint(x1.x);
                af[mi][2] = __float_as_uint(x0.y);
                af[mi][3] = __float_as_uint(x1.y);
            }
#pragma unroll
            for (int ni = 0; ni < 4; ni++) {
                float2 y = Bs2[st][kc][wn + ni * 8 + lg][lt];
                bf[ni][0] = __float_as_uint(y.x);
                bf[ni][1] = __float_as_uint(y.y);
            }
#pragma unroll
            for (int mi = 0; mi < 2; mi++)
#pragma unroll
                for (int ni = 0; ni < 4; ni++) mma8(acc[mi][ni], af[mi], bf[ni]);
        }
        if (more) {
            sts_row8(&As2[st ^ 1][skc][sm][0], a0, a1);
            int kc = bk_ >> 3, lts = bk_ & 3, half = (bk_ >> 2) & 1;
            float* d0 = (float*)&Bs2[st ^ 1][kc][bn_][lts] + half;
            d0[0] = tfbits(bv.x); d0[8] = tfbits(bv.y); d0[16] = tfbits(bv.z); d0[24] = tfbits(bv.w);
        }
        __syncthreads();
    }

#pragma unroll
    for (int mi = 0; mi < 2; mi++) {
        int r0 = q0 + wm + mi * 16 + lg;
#pragma unroll
        for (int ni = 0; ni < 4; ni++) {
            int c0 = wn + ni * 8 + 2 * lt;
            size_t base0 = ((size_t)b * Sq + r0) * DMq + h * DEPTHq + c0;
            size_t base1 = ((size_t)b * Sq + r0 + 8) * DMq + h * DEPTHq + c0;
            *reinterpret_cast<float2*>(&Zp[base0]) =
                make_float2(acc[mi][ni][0], acc[mi][ni][1]);
            *reinterpret_cast<float2*>(&Zp[base1]) =
                make_float2(acc[mi][ni][2], acc[mi][ni][3]);
        }
    }
}

// ============================================================
// Kernel 6: out = (Zp0+Zp1) @ Wo + bo
// ============================================================
__global__ void __launch_bounds__(256, 2)
out_gemm_tc(const float* __restrict__ Wo, const float* __restrict__ bo,
            float* __restrict__ out) {
    __shared__ float2 As2[2][2][128][4];
    __shared__ float2 Bs2[2][2][128][4];

    const int m0 = blockIdx.y * 128;
    const int n0 = blockIdx.x * 128;
    const int tid = threadIdx.x;
    const int wid = tid >> 5, lane = tid & 31;
    const int wm = (wid >> 2) * 64, wn = (wid & 3) * 32;
    const int lg = lane >> 2, lt = lane & 3;

    const int sm = tid >> 1;
    const int skc = tid & 1;
    const int bk_ = tid >> 4;
    const int bn_ = (tid & 15) * 8;

    float acc[4][4][4];
#pragma unroll
    for (int i = 0; i < 4; i++)
#pragma unroll
        for (int j = 0; j < 4; j++)
#pragma unroll
            for (int r = 0; r < 4; r++) acc[i][j][r] = 0.f;

    const int NIT = DMq / 16;

    {
        size_t aoff = (size_t)(m0 + sm) * DMq + skc * 8;
        float4 z0 = *(const float4*)(g_Zp[0] + aoff);
        float4 z1 = *(const float4*)(g_Zp[1] + aoff);
        float4 y0 = *(const float4*)(g_Zp[0] + aoff + 4);
        float4 y1 = *(const float4*)(g_Zp[1] + aoff + 4);
        float4 a0 = make_float4(z0.x + z1.x, z0.y + z1.y, z0.z + z1.z, z0.w + z1.w);
        float4 a1 = make_float4(y0.x + y1.x, y0.y + y1.y, y0.z + y1.z, y0.w + y1.w);
        sts_row8(&As2[0][skc][sm][0], a0, a1);
        const float* bp = Wo + (size_t)bk_ * DMq + n0 + bn_;
        float4 b0 = *(const float4*)(bp);
        float4 b1 = *(const float4*)(bp + 4);
        int kc = bk_ >> 3, lts = bk_ & 3, half = (bk_ >> 2) & 1;
        float* d0 = (float*)&Bs2[0][kc][bn_][lts] + half;
        d0[0] = tfbits(b0.x); d0[8] = tfbits(b0.y); d0[16] = tfbits(b0.z); d0[24] = tfbits(b0.w);
        d0[32] = tfbits(b1.x); d0[40] = tfbits(b1.y); d0[48] = tfbits(b1.z); d0[56] = tfbits(b1.w);
    }
    __syncthreads();

    for (int it = 0; it < NIT; it++) {
        const int st = it & 1;
        float4 a0, a1, b0, b1;
        const bool more = (it + 1 < NIT);
        if (more) {
            int k0 = (it + 1) * 16;
            size_t aoff = (size_t)(m0 + sm) * DMq + k0 + skc * 8;
            float4 z0 = *(const float4*)(g_Zp[0] + aoff);
            float4 z1 = *(const float4*)(g_Zp[1] + aoff);
            float4 y0 = *(const float4*)(g_Zp[0] + aoff + 4);
            float4 y1 = *(const float4*)(g_Zp[1] + aoff + 4);
            a0 = make_float4(z0.x + z1.x, z0.y + z1.y, z0.z + z1.z, z0.w + z1.w);
            a1 = make_float4(y0.x + y1.x, y0.y + y1.y, y0.z + y1.z, y0.w + y1.w);
            const float* bp = Wo + (size_t)(k0 + bk_) * DMq + n0 + bn_;
            b0 = *(const float4*)(bp);
            b1 = *(const float4*)(bp + 4);
        }
#pragma unroll
        for (int kc = 0; kc < 2; kc++) {
            uint32_t af[4][4], bf[4][2];
#pragma unroll
            for (int mi = 0; mi < 4; mi++) {
                float2 x0 = As2[st][kc][wm + mi * 16 + lg][lt];
                float2 x1 = As2[st][kc][wm + mi * 16 + 8 + lg][lt];
                af[mi][0] = __float_as_uint(x0.x);
                af[mi][1] = __float_as_uint(x1.x);
                af[mi][2] = __float_as_uint(x0.y);
                af[mi][3] = __float_as_uint(x1.y);
            }
#pragma unroll
            for (int ni = 0; ni < 4; ni++) {
                float2 y = Bs2[st][kc][wn + ni * 8 + lg][lt];
                bf[ni][0] = __float_as_uint(y.x);
                bf[ni][1] = __float_as_uint(y.y);
            }
#pragma unroll
            for (int mi = 0; mi < 4; mi++)
#pragma unroll
                for (int ni = 0; ni < 4; ni++) mma8(acc[mi][ni], af[mi], bf[ni]);
        }
        if (more) {
            sts_row8(&As2[st ^ 1][skc][sm][0], a0, a1);
            int kc = bk_ >> 3, lts = bk_ & 3, half = (bk_ >> 2) & 1;
            float* d0 = (float*)&Bs2[st ^ 1][kc][bn_][lts] + half;
            d0[0] = tfbits(b0.x); d0[8] = tfbits(b0.y); d0[16] = tfbits(b0.z); d0[24] = tfbits(b0.w);
            d0[32] = tfbits(b1.x); d0[40] = tfbits(b1.y); d0[48] = tfbits(b1.z); d0[56] = tfbits(b1.w);
        }
        __syncthreads();
    }

#pragma unroll
    for (int mi = 0; mi < 4; mi++) {
        int r0 = m0 + wm + mi * 16 + lg;
#pragma unroll
        for (int ni = 0; ni < 4; ni++) {
            int c0 = n0 + wn + ni * 8 + 2 * lt;
            float bv0 = bo[c0], bv1 = bo[c0 + 1];
            *reinterpret_cast<float2*>(&out[(size_t)r0 * DMq + c0]) =
                make_float2(acc[mi][ni][0] + bv0, acc[mi][ni][1] + bv1);
            *reinterpret_cast<float2*>(&out[(size_t)(r0 + 8) * DMq + c0]) =
                make_float2(acc[mi][ni][2] + bv0, acc[mi][ni][3] + bv1);
        }
    }
}

// ============================================================
// Launch
// ============================================================
extern "C" void kernel_launch(void* const* d_in, const int* in_sizes, int n_in,
                              void* d_out, int out_size) {
    const float* emb = (const float*)d_in[0];
    const float* pe  = (const float*)d_in[1];
    const float* Wq  = (const float*)d_in[2];
    const float* bq  = (const float*)d_in[3];
    const float* Wk  = (const float*)d_in[4];
    const float* bk  = (const float*)d_in[5];
    const float* Wv  = (const float*)d_in[6];
    const float* bv  = (const float*)d_in[7];
    const float* Wo  = (const float*)d_in[8];
    const float* bo  = (const float*)d_in[9];

    float* out = (float*)d_out;

    const long long need = (long long)NTOK * DMq + (long long)BHq * Sq * Sq;
    float* attn;
    if ((long long)out_size >= need) {
        attn = out + (size_t)NTOK * DMq;
    } else {
        float* p = nullptr;
        cudaGetSymbolAddress((void**)&p, g_attn_fallback);
        attn = p;
    }

    cudaFuncSetAttribute(proj_gemm_tc, cudaFuncAttributeMaxDynamicSharedMemorySize, DYN_SMEM);
    cudaFuncSetAttribute(logits_gemm_tc, cudaFuncAttributeMaxDynamicSharedMemorySize, DYN_SMEM);

    {
        dim3 grid(CC / 128, NROWS / 128);
        proj_gemm_tc<<<grid, 256, DYN_SMEM>>>(emb, pe, Wq, bq, Wk, bk, Wv, bv);
    }
    {
        int total = NTOK * DMq;
        rearrange_kernel<<<(total + 255) / 256, 256>>>();
    }
    {
        zero_rowsum<<<(BHq * Sq + 255) / 256, 256>>>();
    }
    {
        dim3 grid(Sq / 128, Sq / 128, BHq);
        logits_gemm_tc<<<grid, 256, DYN_SMEM>>>(attn);
    }
    {
        dim3 grid(Sq / 128, 2, BHq);
        zv_fused_tc<<<grid, 256>>>(attn);
    }
    {
        dim3 grid(DMq / 128, NTOK / 128);
        out_gemm_tc<<<grid, 256>>>(Wo, bo, out);
    }
}

// round 8
// speedup vs baseline: 1.0194x; 1.0194x over previous
#include <cuda_runtime.h>
#include <cstdint>

#define Bq 2
#define Sq 2048
#define Hq 8
#define DEPTHq 64
#define DMq 512
#define NTOK (Bq * Sq)
#define NROWS (2 * NTOK)
#define CC 1536
#define BHq (Bq * Hq)

// ---------------- device scratch ----------------
__device__ float g_C[NROWS * CC];
__device__ float g_Qh[BHq * Sq * 128];     // tf32-pre-rounded
__device__ float g_Kh[BHq * Sq * 128];     // tf32-pre-rounded
__device__ float g_Vh[BHq * Sq * DEPTHq];  // tf32-pre-rounded
__device__ float g_Zp[2][NTOK * DMq];
__device__ float g_rowsum[BHq * Sq];
__device__ float g_attn_fallback[(size_t)BHq * Sq * Sq];

// ---------------- tf32 helpers ----------------
__device__ __forceinline__ uint32_t f2tf32(float f) {
    uint32_t u;
    asm("cvt.rna.tf32.f32 %0, %1;" : "=r"(u) : "f"(f));
    return u;
}
__device__ __forceinline__ float tfbits(float f) {
    return __uint_as_float(f2tf32(f));
}
__device__ __forceinline__ void mma8(float* c, const uint32_t* a, const uint32_t* b) {
    asm volatile(
        "mma.sync.aligned.m16n8k8.row.col.f32.tf32.tf32.f32 "
        "{%0,%1,%2,%3}, {%4,%5,%6,%7}, {%8,%9}, {%0,%1,%2,%3};"
        : "+f"(c[0]), "+f"(c[1]), "+f"(c[2]), "+f"(c[3])
        : "r"(a[0]), "r"(a[1]), "r"(a[2]), "r"(a[3]),
          "r"(b[0]), "r"(b[1]));
}
// staging WITH rounding (for fp32 sources)
__device__ __forceinline__ void sts_row8(float2* base, float4 v0, float4 v1) {
    float4 w0 = make_float4(tfbits(v0.x), tfbits(v1.x), tfbits(v0.y), tfbits(v1.y));
    float4 w1 = make_float4(tfbits(v0.z), tfbits(v1.z), tfbits(v0.w), tfbits(v1.w));
    *reinterpret_cast<float4*>(base)     = w0;
    *reinterpret_cast<float4*>(base + 2) = w1;
}
// staging WITHOUT rounding (source already tf32 bits)
__device__ __forceinline__ void sts_row8_raw(float2* base, float4 v0, float4 v1) {
    *reinterpret_cast<float4*>(base)     = make_float4(v0.x, v1.x, v0.y, v1.y);
    *reinterpret_cast<float4*>(base + 2) = make_float4(v0.z, v1.z, v0.w, v1.w);
}

// ============================================================
// Kernel 1: proj  C[8192x1536] = [emb;pe] @ [Wq|Wk|Wv] + bias
// (R4 design, cvt kept — fp32 sources)
// ============================================================
__global__ void __launch_bounds__(256, 2)
proj_gemm_tc(const float* __restrict__ emb, const float* __restrict__ pe,
             const float* __restrict__ Wq, const float* __restrict__ bq,
             const float* __restrict__ Wk, const float* __restrict__ bk,
             const float* __restrict__ Wv, const float* __restrict__ bv) {
    __shared__ float2 As2[2][2][128][4];
    __shared__ float2 Bs2[2][2][128][4];

    const int m0 = blockIdx.y * 128;
    const int n0 = blockIdx.x * 128;
    const int tid = threadIdx.x;
    const int wid = tid >> 5, lane = tid & 31;
    const int wm = (wid >> 2) * 64, wn = (wid & 3) * 32;
    const int lg = lane >> 2, lt = lane & 3;

    const float* srcA = (m0 < NTOK) ? (emb + (size_t)m0 * DMq)
                                    : (pe + (size_t)(m0 - NTOK) * DMq);
    const float* W    = (n0 < 512) ? Wq : (n0 < 1024 ? Wk : Wv);
    const float* bias = (n0 < 512) ? bq : (n0 < 1024 ? bk : bv);
    const int colbase = n0 & 511;

    const int sm = tid >> 1;
    const int skc = tid & 1;
    const int bk_ = tid >> 4;
    const int bn_ = (tid & 15) * 8;

    float acc[4][4][4];
#pragma unroll
    for (int i = 0; i < 4; i++)
#pragma unroll
        for (int j = 0; j < 4; j++)
#pragma unroll
            for (int r = 0; r < 4; r++) acc[i][j][r] = 0.f;

    const int NIT = DMq / 16;

    {
        const float* ap = srcA + (size_t)sm * DMq + skc * 8;
        sts_row8(&As2[0][skc][sm][0], *(const float4*)ap, *(const float4*)(ap + 4));
        const float* bp = W + (size_t)bk_ * DMq + colbase + bn_;
        float4 b0 = *(const float4*)(bp);
        float4 b1 = *(const float4*)(bp + 4);
        int kc = bk_ >> 3, lts = bk_ & 3, half = (bk_ >> 2) & 1;
        float* d0 = (float*)&Bs2[0][kc][bn_][lts] + half;
        d0[0] = tfbits(b0.x); d0[8] = tfbits(b0.y); d0[16] = tfbits(b0.z); d0[24] = tfbits(b0.w);
        d0[32] = tfbits(b1.x); d0[40] = tfbits(b1.y); d0[48] = tfbits(b1.z); d0[56] = tfbits(b1.w);
    }
    __syncthreads();

    for (int it = 0; it < NIT; it++) {
        const int st = it & 1;
        float4 a0, a1, b0, b1;
        const bool more = (it + 1 < NIT);
        if (more) {
            int k0 = (it + 1) * 16;
            const float* ap = srcA + (size_t)sm * DMq + k0 + skc * 8;
            a0 = *(const float4*)(ap);
            a1 = *(const float4*)(ap + 4);
            const float* bp = W + (size_t)(k0 + bk_) * DMq + colbase + bn_;
            b0 = *(const float4*)(bp);
            b1 = *(const float4*)(bp + 4);
        }
#pragma unroll
        for (int kc = 0; kc < 2; kc++) {
            uint32_t af[4][4], bf[4][2];
#pragma unroll
            for (int mi = 0; mi < 4; mi++) {
                float2 x0 = As2[st][kc][wm + mi * 16 + lg][lt];
                float2 x1 = As2[st][kc][wm + mi * 16 + 8 + lg][lt];
                af[mi][0] = __float_as_uint(x0.x);
                af[mi][1] = __float_as_uint(x1.x);
                af[mi][2] = __float_as_uint(x0.y);
                af[mi][3] = __float_as_uint(x1.y);
            }
#pragma unroll
            for (int ni = 0; ni < 4; ni++) {
                float2 y = Bs2[st][kc][wn + ni * 8 + lg][lt];
                bf[ni][0] = __float_as_uint(y.x);
                bf[ni][1] = __float_as_uint(y.y);
            }
#pragma unroll
            for (int mi = 0; mi < 4; mi++)
#pragma unroll
                for (int ni = 0; ni < 4; ni++) mma8(acc[mi][ni], af[mi], bf[ni]);
        }
        if (more) {
            sts_row8(&As2[st ^ 1][skc][sm][0], a0, a1);
            int kc = bk_ >> 3, lts = bk_ & 3, half = (bk_ >> 2) & 1;
            float* d0 = (float*)&Bs2[st ^ 1][kc][bn_][lts] + half;
            d0[0] = tfbits(b0.x); d0[8] = tfbits(b0.y); d0[16] = tfbits(b0.z); d0[24] = tfbits(b0.w);
            d0[32] = tfbits(b1.x); d0[40] = tfbits(b1.y); d0[48] = tfbits(b1.z); d0[56] = tfbits(b1.w);
        }
        __syncthreads();
    }

#pragma unroll
    for (int mi = 0; mi < 4; mi++) {
        int r0 = m0 + wm + mi * 16 + lg;
#pragma unroll
        for (int ni = 0; ni < 4; ni++) {
            int c0 = n0 + wn + ni * 8 + 2 * lt;
            float bv0 = bias[(c0) & 511], bv1 = bias[(c0 + 1) & 511];
            *reinterpret_cast<float2*>(&g_C[(size_t)r0 * CC + c0]) =
                make_float2(acc[mi][ni][0] + bv0, acc[mi][ni][1] + bv1);
            *reinterpret_cast<float2*>(&g_C[(size_t)(r0 + 8) * CC + c0]) =
                make_float2(acc[mi][ni][2] + bv0, acc[mi][ni][3] + bv1);
        }
    }
}

// ============================================================
// Kernel 2: rearrange — outputs tf32-pre-rounded
// ============================================================
__global__ void rearrange_kernel() {
    int idx = blockIdx.x * blockDim.x + threadIdx.x;
    if (idx >= NTOK * DMq) return;
    int n = idx / DMq;
    int c = idx % DMq;
    int b = n / Sq, s = n % Sq;
    int h = c / DEPTHq, d = c % DEPTHq;

    float Qc = g_C[(size_t)n * CC + c];
    float Qr = g_C[(size_t)(NTOK + n) * CC + c];
    float Kc = g_C[(size_t)n * CC + 512 + c];
    float Kr = g_C[(size_t)(NTOK + n) * CC + 512 + c];
    float Vv = g_C[(size_t)n * CC + 1024 + c];

    size_t base = ((size_t)(b * Hq + h) * Sq + s) * 128;
    g_Qh[base + d]      = tfbits((Qc + Qr) * 0.125f);
    g_Qh[base + 64 + d] = tfbits(Qc * 0.125f);
    g_Kh[base + d]      = tfbits(Kc);
    g_Kh[base + 64 + d] = tfbits(Kr);
    g_Vh[((size_t)(b * Hq + h) * Sq + s) * DEPTHq + d] = tfbits(Vv);
}

__global__ void zero_rowsum() {
    int i = blockIdx.x * 256 + threadIdx.x;
    if (i < BHq * Sq) g_rowsum[i] = 0.f;
}

// ============================================================
// Kernel 3: logits + exp + rowsum. 128x128, BK=16 dbl-buf.
// Staging is cvt-free (sources pre-rounded). Stores exp pre-
// rounded to tf32 so zv can consume without cvt.
// ============================================================
__global__ void __launch_bounds__(256, 2)
logits_gemm_tc(float* __restrict__ attn) {
    __shared__ float2 As2[2][2][128][4];
    __shared__ float2 Bs2[2][2][128][4];

    const int bh = blockIdx.z;
    const int q0 = blockIdx.y * 128;
    const int t0 = blockIdx.x * 128;
    const float* Q = g_Qh + (size_t)bh * Sq * 128;
    const float* K = g_Kh + (size_t)bh * Sq * 128;
    float* out = attn + (size_t)bh * Sq * Sq;

    const int tid = threadIdx.x;
    const int wid = tid >> 5, lane = tid & 31;
    const int wm = (wid >> 2) * 64, wn = (wid & 3) * 32;
    const int lg = lane >> 2, lt = lane & 3;

    const int sm = tid >> 1;
    const int skc = tid & 1;

    float acc[4][4][4];
#pragma unroll
    for (int i = 0; i < 4; i++)
#pragma unroll
        for (int j = 0; j < 4; j++)
#pragma unroll
            for (int r = 0; r < 4; r++) acc[i][j][r] = 0.f;

    const int NIT = 128 / 16;

    {
        const float* ap = Q + (size_t)(q0 + sm) * 128 + skc * 8;
        sts_row8_raw(&As2[0][skc][sm][0], *(const float4*)ap, *(const float4*)(ap + 4));
        const float* bp = K + (size_t)(t0 + sm) * 128 + skc * 8;
        sts_row8_raw(&Bs2[0][skc][sm][0], *(const float4*)bp, *(const float4*)(bp + 4));
    }
    __syncthreads();

    for (int it = 0; it < NIT; it++) {
        const int st = it & 1;
        float4 a0, a1, b0, b1;
        const bool more = (it + 1 < NIT);
        if (more) {
            int k0 = (it + 1) * 16;
            const float* ap = Q + (size_t)(q0 + sm) * 128 + k0 + skc * 8;
            a0 = *(const float4*)(ap);
            a1 = *(const float4*)(ap + 4);
            const float* bp = K + (size_t)(t0 + sm) * 128 + k0 + skc * 8;
            b0 = *(const float4*)(bp);
            b1 = *(const float4*)(bp + 4);
        }
#pragma unroll
        for (int kc = 0; kc < 2; kc++) {
            uint32_t af[4][4], bf[4][2];
#pragma unroll
            for (int mi = 0; mi < 4; mi++) {
                float2 x0 = As2[st][kc][wm + mi * 16 + lg][lt];
                float2 x1 = As2[st][kc][wm + mi * 16 + 8 + lg][lt];
                af[mi][0] = __float_as_uint(x0.x);
                af[mi][1] = __float_as_uint(x1.x);
                af[mi][2] = __float_as_uint(x0.y);
                af[mi][3] = __float_as_uint(x1.y);
            }
#pragma unroll
            for (int ni = 0; ni < 4; ni++) {
                float2 y = Bs2[st][kc][wn + ni * 8 + lg][lt];
                bf[ni][0] = __float_as_uint(y.x);
                bf[ni][1] = __float_as_uint(y.y);
            }
#pragma unroll
            for (int mi = 0; mi < 4; mi++)
#pragma unroll
                for (int ni = 0; ni < 4; ni++) mma8(acc[mi][ni], af[mi], bf[ni]);
        }
        if (more) {
            sts_row8_raw(&As2[st ^ 1][skc][sm][0], a0, a1);
            sts_row8_raw(&Bs2[st ^ 1][skc][sm][0], b0, b1);
        }
        __syncthreads();
    }

    // Epilogue: exp (tf32-rounded) + store + rowsum partials
#pragma unroll
    for (int mi = 0; mi < 4; mi++) {
        int r0 = q0 + wm + mi * 16 + lg;
        float rs0 = 0.f, rs1 = 0.f;
#pragma unroll
        for (int ni = 0; ni < 4; ni++) {
            int c0 = t0 + wn + ni * 8 + 2 * lt;
            float e0 = tfbits(__expf(acc[mi][ni][0]));
            float e1 = tfbits(__expf(acc[mi][ni][1]));
            float e2 = tfbits(__expf(acc[mi][ni][2]));
            float e3 = tfbits(__expf(acc[mi][ni][3]));
            *reinterpret_cast<float2*>(&out[(size_t)r0 * Sq + c0]) = make_float2(e0, e1);
            *reinterpret_cast<float2*>(&out[(size_t)(r0 + 8) * Sq + c0]) = make_float2(e2, e3);
            rs0 += e0 + e1;
            rs1 += e2 + e3;
        }
        rs0 += __shfl_xor_sync(0xffffffffu, rs0, 1);
        rs0 += __shfl_xor_sync(0xffffffffu, rs0, 2);
        rs1 += __shfl_xor_sync(0xffffffffu, rs1, 1);
        rs1 += __shfl_xor_sync(0xffffffffu, rs1, 2);
        if (lt == 0) {
            atomicAdd(&g_rowsum[bh * Sq + r0], rs0);
            atomicAdd(&g_rowsum[bh * Sq + r0 + 8], rs1);
        }
    }
}

// ============================================================
// Kernel 5: zv — mma consumes RAW exp (pre-rounded tf32);
// normalized attn written in-place during staging; z scaled by
// 1/rowsum at epilogue. grid (Sq/128, 2 ksplit, BHq).
// ============================================================
__global__ void __launch_bounds__(256, 2)
zv_fused_tc(float* __restrict__ attn) {
    __shared__ float2 As2[2][2][128][4];
    __shared__ float2 Bs2[2][2][64][4];

    const int bh = blockIdx.z;
    const int q0 = blockIdx.x * 128;
    const int ks = blockIdx.y;
    const int b = bh / Hq, h = bh % Hq;
    float* P = attn + (size_t)bh * Sq * Sq;
    const float* V = g_Vh + ((size_t)bh * Sq + ks * 1024) * DEPTHq;
    float* Zp = g_Zp[ks];

    const int tid = threadIdx.x;
    const int wid = tid >> 5, lane = tid & 31;
    const int wm = (wid >> 1) * 32, wn = (wid & 1) * 32;
    const int lg = lane >> 2, lt = lane & 3;

    const int sm = tid >> 1;
    const int skc = tid & 1;
    const int bk_ = tid >> 4;
    const int bn_ = (tid & 15) * 4;

    const float invs = 1.0f / g_rowsum[bh * Sq + q0 + sm];
    float* prow = P + (size_t)(q0 + sm) * Sq + ks * 1024 + skc * 8;

    float acc[2][4][4];
#pragma unroll
    for (int i = 0; i < 2; i++)
#pragma unroll
        for (int j = 0; j < 4; j++)
#pragma unroll
            for (int r = 0; r < 4; r++) acc[i][j][r] = 0.f;

    const int NIT = 1024 / 16;  // 64

    {
        float4 a0 = *(const float4*)(prow);
        float4 a1 = *(const float4*)(prow + 4);
        // normalized attn out (in place)
        *(float4*)(prow) = make_float4(a0.x * invs, a0.y * invs, a0.z * invs, a0.w * invs);
        *(float4*)(prow + 4) = make_float4(a1.x * invs, a1.y * invs, a1.z * invs, a1.w * invs);
        sts_row8_raw(&As2[0][skc][sm][0], a0, a1);
        float4 bv = *(const float4*)(V + (size_t)bk_ * DEPTHq + bn_);
        int kc = bk_ >> 3, lts = bk_ & 3, half = (bk_ >> 2) & 1;
        float* d0 = (float*)&Bs2[0][kc][bn_][lts] + half;
        d0[0] = bv.x; d0[8] = bv.y; d0[16] = bv.z; d0[24] = bv.w;
    }
    __syncthreads();

    for (int it = 0; it < NIT; it++) {
        const int st = it & 1;
        float4 a0, a1, bv;
        const bool more = (it + 1 < NIT);
        if (more) {
            int k0 = (it + 1) * 16;
            a0 = *(const float4*)(prow + k0);
            a1 = *(const float4*)(prow + k0 + 4);
            *(float4*)(prow + k0) = make_float4(a0.x * invs, a0.y * invs, a0.z * invs, a0.w * invs);
            *(float4*)(prow + k0 + 4) = make_float4(a1.x * invs, a1.y * invs, a1.z * invs, a1.w * invs);
            bv = *(const float4*)(V + (size_t)(k0 + bk_) * DEPTHq + bn_);
        }
#pragma unroll
        for (int kc = 0; kc < 2; kc++) {
            uint32_t af[2][4], bf[4][2];
#pragma unroll
            for (int mi = 0; mi < 2; mi++) {
                float2 x0 = As2[st][kc][wm + mi * 16 + lg][lt];
                float2 x1 = As2[st][kc][wm + mi * 16 + 8 + lg][lt];
                af[mi][0] = __float_as_uint(x0.x);
                af[mi][1] = __float_as_uint(x1.x);
                af[mi][2] = __float_as_uint(x0.y);
                af[mi][3] = __float_as_uint(x1.y);
            }
#pragma unroll
            for (int ni = 0; ni < 4; ni++) {
                float2 y = Bs2[st][kc][wn + ni * 8 + lg][lt];
                bf[ni][0] = __float_as_uint(y.x);
                bf[ni][1] = __float_as_uint(y.y);
            }
#pragma unroll
            for (int mi = 0; mi < 2; mi++)
#pragma unroll
                for (int ni = 0; ni < 4; ni++) mma8(acc[mi][ni], af[mi], bf[ni]);
        }
        if (more) {
            sts_row8_raw(&As2[st ^ 1][skc][sm][0], a0, a1);
            int kc = bk_ >> 3, lts = bk_ & 3, half = (bk_ >> 2) & 1;
            float* d0 = (float*)&Bs2[st ^ 1][kc][bn_][lts] + half;
            d0[0] = bv.x; d0[8] = bv.y; d0[16] = bv.z; d0[24] = bv.w;
        }
        __syncthreads();
    }

    // Epilogue: scale z-partials by 1/rowsum (per output row)
#pragma unroll
    for (int mi = 0; mi < 2; mi++) {
        int r0 = q0 + wm + mi * 16 + lg;
        float iv0 = 1.0f / g_rowsum[bh * Sq + r0];
        float iv1 = 1.0f / g_rowsum[bh * Sq + r0 + 8];
#pragma unroll
        for (int ni = 0; ni < 4; ni++) {
            int c0 = wn + ni * 8 + 2 * lt;
            size_t base0 = ((size_t)b * Sq + r0) * DMq + h * DEPTHq + c0;
            size_t base1 = ((size_t)b * Sq + r0 + 8) * DMq + h * DEPTHq + c0;
            *reinterpret_cast<float2*>(&Zp[base0]) =
                make_float2(acc[mi][ni][0] * iv0, acc[mi][ni][1] * iv0);
            *reinterpret_cast<float2*>(&Zp[base1]) =
                make_float2(acc[mi][ni][2] * iv1, acc[mi][ni][3] * iv1);
        }
    }
}

// ============================================================
// Kernel 6: out = (Zp0+Zp1) @ Wo + bo
// ============================================================
__global__ void __launch_bounds__(256, 2)
out_gemm_tc(const float* __restrict__ Wo, const float* __restrict__ bo,
            float* __restrict__ out) {
    __shared__ float2 As2[2][2][128][4];
    __shared__ float2 Bs2[2][2][128][4];

    const int m0 = blockIdx.y * 128;
    const int n0 = blockIdx.x * 128;
    const int tid = threadIdx.x;
    const int wid = tid >> 5, lane = tid & 31;
    const int wm = (wid >> 2) * 64, wn = (wid & 3) * 32;
    const int lg = lane >> 2, lt = lane & 3;

    const int sm = tid >> 1;
    const int skc = tid & 1;
    const int bk_ = tid >> 4;
    const int bn_ = (tid & 15) * 8;

    float acc[4][4][4];
#pragma unroll
    for (int i = 0; i < 4; i++)
#pragma unroll
        for (int j = 0; j < 4; j++)
#pragma unroll
            for (int r = 0; r < 4; r++) acc[i][j][r] = 0.f;

    const int NIT = DMq / 16;

    {
        size_t aoff = (size_t)(m0 + sm) * DMq + skc * 8;
        float4 z0 = *(const float4*)(g_Zp[0] + aoff);
        float4 z1 = *(const float4*)(g_Zp[1] + aoff);
        float4 y0 = *(const float4*)(g_Zp[0] + aoff + 4);
        float4 y1 = *(const float4*)(g_Zp[1] + aoff + 4);
        float4 a0 = make_float4(z0.x + z1.x, z0.y + z1.y, z0.z + z1.z, z0.w + z1.w);
        float4 a1 = make_float4(y0.x + y1.x, y0.y + y1.y, y0.z + y1.z, y0.w + y1.w);
        sts_row8(&As2[0][skc][sm][0], a0, a1);
        const float* bp = Wo + (size_t)bk_ * DMq + n0 + bn_;
        float4 b0 = *(const float4*)(bp);
        float4 b1 = *(const float4*)(bp + 4);
        int kc = bk_ >> 3, lts = bk_ & 3, half = (bk_ >> 2) & 1;
        float* d0 = (float*)&Bs2[0][kc][bn_][lts] + half;
        d0[0] = tfbits(b0.x); d0[8] = tfbits(b0.y); d0[16] = tfbits(b0.z); d0[24] = tfbits(b0.w);
        d0[32] = tfbits(b1.x); d0[40] = tfbits(b1.y); d0[48] = tfbits(b1.z); d0[56] = tfbits(b1.w);
    }
    __syncthreads();

    for (int it = 0; it < NIT; it++) {
        const int st = it & 1;
        float4 a0, a1, b0, b1;
        const bool more = (it + 1 < NIT);
        if (more) {
            int k0 = (it + 1) * 16;
            size_t aoff = (size_t)(m0 + sm) * DMq + k0 + skc * 8;
            float4 z0 = *(const float4*)(g_Zp[0] + aoff);
            float4 z1 = *(const float4*)(g_Zp[1] + aoff);
            float4 y0 = *(const float4*)(g_Zp[0] + aoff + 4);
            float4 y1 = *(const float4*)(g_Zp[1] + aoff + 4);
            a0 = make_float4(z0.x + z1.x, z0.y + z1.y, z0.z + z1.z, z0.w + z1.w);
            a1 = make_float4(y0.x + y1.x, y0.y + y1.y, y0.z + y1.z, y0.w + y1.w);
            const float* bp = Wo + (size_t)(k0 + bk_) * DMq + n0 + bn_;
            b0 = *(const float4*)(bp);
            b1 = *(const float4*)(bp + 4);
        }
#pragma unroll
        for (int kc = 0; kc < 2; kc++) {
            uint32_t af[4][4], bf[4][2];
#pragma unroll
            for (int mi = 0; mi < 4; mi++) {
                float2 x0 = As2[st][kc][wm + mi * 16 + lg][lt];
                float2 x1 = As2[st][kc][wm + mi * 16 + 8 + lg][lt];
                af[mi][0] = __float_as_uint(x0.x);
                af[mi][1] = __float_as_uint(x1.x);
                af[mi][2] = __float_as_uint(x0.y);
                af[mi][3] = __float_as_uint(x1.y);
            }
#pragma unroll
            for (int ni = 0; ni < 4; ni++) {
                float2 y = Bs2[st][kc][wn + ni * 8 + lg][lt];
                bf[ni][0] = __float_as_uint(y.x);
                bf[ni][1] = __float_as_uint(y.y);
            }
#pragma unroll
            for (int mi = 0; mi < 4; mi++)
#pragma unroll
                for (int ni = 0; ni < 4; ni++) mma8(acc[mi][ni], af[mi], bf[ni]);
        }
        if (more) {
            sts_row8(&As2[st ^ 1][skc][sm][0], a0, a1);
            int kc = bk_ >> 3, lts = bk_ & 3, half = (bk_ >> 2) & 1;
            float* d0 = (float*)&Bs2[st ^ 1][kc][bn_][lts] + half;
            d0[0] = tfbits(b0.x); d0[8] = tfbits(b0.y); d0[16] = tfbits(b0.z); d0[24] = tfbits(b0.w);
            d0[32] = tfbits(b1.x); d0[40] = tfbits(b1.y); d0[48] = tfbits(b1.z); d0[56] = tfbits(b1.w);
        }
        __syncthreads();
    }

#pragma unroll
    for (int mi = 0; mi < 4; mi++) {
        int r0 = m0 + wm + mi * 16 + lg;
#pragma unroll
        for (int ni = 0; ni < 4; ni++) {
            int c0 = n0 + wn + ni * 8 + 2 * lt;
            float bv0 = bo[c0], bv1 = bo[c0 + 1];
            *reinterpret_cast<float2*>(&out[(size_t)r0 * DMq + c0]) =
                make_float2(acc[mi][ni][0] + bv0, acc[mi][ni][1] + bv1);
            *reinterpret_cast<float2*>(&out[(size_t)(r0 + 8) * DMq + c0]) =
                make_float2(acc[mi][ni][2] + bv0, acc[mi][ni][3] + bv1);
        }
    }
}

// ============================================================
// Launch
// ============================================================
extern "C" void kernel_launch(void* const* d_in, const int* in_sizes, int n_in,
                              void* d_out, int out_size) {
    const float* emb = (const float*)d_in[0];
    const float* pe  = (const float*)d_in[1];
    const float* Wq  = (const float*)d_in[2];
    const float* bq  = (const float*)d_in[3];
    const float* Wk  = (const float*)d_in[4];
    const float* bk  = (const float*)d_in[5];
    const float* Wv  = (const float*)d_in[6];
    const float* bv  = (const float*)d_in[7];
    const float* Wo  = (const float*)d_in[8];
    const float* bo  = (const float*)d_in[9];

    float* out = (float*)d_out;

    const long long need = (long long)NTOK * DMq + (long long)BHq * Sq * Sq;
    float* attn;
    if ((long long)out_size >= need) {
        attn = out + (size_t)NTOK * DMq;
    } else {
        float* p = nullptr;
        cudaGetSymbolAddress((void**)&p, g_attn_fallback);
        attn = p;
    }

    {
        dim3 grid(CC / 128, NROWS / 128);
        proj_gemm_tc<<<grid, 256>>>(emb, pe, Wq, bq, Wk, bk, Wv, bv);
    }
    {
        int total = NTOK * DMq;
        rearrange_kernel<<<(total + 255) / 256, 256>>>();
    }
    {
        zero_rowsum<<<(BHq * Sq + 255) / 256, 256>>>();
    }
    {
        dim3 grid(Sq / 128, Sq / 128, BHq);
        logits_gemm_tc<<<grid, 256>>>(attn);
    }
    {
        dim3 grid(Sq / 128, 2, BHq);
        zv_fused_tc<<<grid, 256>>>(attn);
    }
    {
        dim3 grid(DMq / 128, NTOK / 128);
        out_gemm_tc<<<grid, 256>>>(Wo, bo, out);
    }
}

// round 9
// speedup vs baseline: 1.3332x; 1.3079x over previous
#include <cuda_runtime.h>
#include <cuda_fp16.h>
#include <cstdint>

#define Bq 2
#define Sq 2048
#define Hq 8
#define DEPTHq 64
#define DMq 512
#define NTOK (Bq * Sq)
#define NROWS (2 * NTOK)
#define CC 1536
#define BHq (Bq * Hq)

// ---------------- device scratch ----------------
__device__ float  g_C[NROWS * CC];
__device__ __half g_Qh[BHq * Sq * 128];
__device__ __half g_Kh[BHq * Sq * 128];
__device__ __half g_Vh[BHq * Sq * DEPTHq];
__device__ __half g_attn_h[(size_t)BHq * Sq * Sq];   // raw exp, fp16
__device__ float  g_Zp[2][NTOK * DMq];
__device__ float  g_rowsum[BHq * Sq];
__device__ float  g_attn_fallback[(size_t)BHq * Sq * Sq];

// ---------------- fp16 helpers ----------------
__device__ __forceinline__ uint32_t ph2(float a, float b) {
    __half2 h = __floats2half2_rn(a, b);
    return *reinterpret_cast<uint32_t*>(&h);
}
__device__ __forceinline__ void mma16(float* c, const uint32_t* a, const uint32_t* b) {
    asm volatile(
        "mma.sync.aligned.m16n8k16.row.col.f32.f16.f16.f32 "
        "{%0,%1,%2,%3}, {%4,%5,%6,%7}, {%8,%9}, {%0,%1,%2,%3};"
        : "+f"(c[0]), "+f"(c[1]), "+f"(c[2]), "+f"(c[3])
        : "r"(a[0]), "r"(a[1]), "r"(a[2]), "r"(a[3]),
          "r"(b[0]), "r"(b[1]));
}
// smem slot layout per BK=16 chunk: S[row][8] uint32, slot s:
//   s even (=2i): half2 of k=(2i, 2i+1)     s odd (=2i+1): half2 of k=(2i+8, 2i+9)
// A-frag: lo=*(uint2*)&SA[row=lg][2lt], hi at row lg+8 -> a={lo.x,hi.x,lo.y,hi.y}
// B-frag: bb=*(uint2*)&SB[col=lg][2lt] -> b={bb.x,bb.y}

// stage one 8-float half-row (w = which half of the 16-k chunk) with cvt
__device__ __forceinline__ void stage_f32(uint32_t* rowp, int w, float4 v0, float4 v1) {
    rowp[0 + w] = ph2(v0.x, v0.y);
    rowp[2 + w] = ph2(v0.z, v0.w);
    rowp[4 + w] = ph2(v1.x, v1.y);
    rowp[6 + w] = ph2(v1.z, v1.w);
}
// stage one 8-half chunk (already fp16) — pure copy
__device__ __forceinline__ void stage_f16(uint32_t* rowp, int w, uint4 u) {
    rowp[0 + w] = u.x;
    rowp[2 + w] = u.y;
    rowp[4 + w] = u.z;
    rowp[6 + w] = u.w;
}

// ============================================================
// Kernel 1: proj  C[8192x1536] = [emb;pe] @ [Wq|Wk|Wv] + bias
// 128x128 tile, BK=16 dbl-buf, 8 warps 64x32, fp16 mma.
// ============================================================
__global__ void __launch_bounds__(256, 2)
proj_gemm_tc(const float* __restrict__ emb, const float* __restrict__ pe,
             const float* __restrict__ Wq, const float* __restrict__ bq,
             const float* __restrict__ Wk, const float* __restrict__ bk,
             const float* __restrict__ Wv, const float* __restrict__ bv) {
    __shared__ __align__(16) uint32_t SA[2][128][8];
    __shared__ __align__(16) uint32_t SB[2][128][8];

    const int m0 = blockIdx.y * 128;
    const int n0 = blockIdx.x * 128;
    const int tid = threadIdx.x;
    const int wid = tid >> 5, lane = tid & 31;
    const int wm = (wid >> 2) * 64, wn = (wid & 3) * 32;
    const int lg = lane >> 2, lt = lane & 3;

    const float* srcA = (m0 < NTOK) ? (emb + (size_t)m0 * DMq)
                                    : (pe + (size_t)(m0 - NTOK) * DMq);
    const float* W    = (n0 < 512) ? Wq : (n0 < 1024 ? Wk : Wv);
    const float* bias = (n0 < 512) ? bq : (n0 < 1024 ? bk : bv);
    const int colbase = n0 & 511;

    const int sm = tid >> 1, w = tid & 1;          // A staging
    const int kp = tid >> 5, bn_ = (tid & 31) * 4; // B staging
    const int slot = (kp < 4) ? 2 * kp : 2 * (kp - 4) + 1;

    float acc[4][4][4];
#pragma unroll
    for (int i = 0; i < 4; i++)
#pragma unroll
        for (int j = 0; j < 4; j++)
#pragma unroll
            for (int r = 0; r < 4; r++) acc[i][j][r] = 0.f;

    const int NIT = DMq / 16;  // 32

    {
        const float* ap = srcA + (size_t)sm * DMq + 8 * w;
        stage_f32(&SA[0][sm][0], w, *(const float4*)ap, *(const float4*)(ap + 4));
        const float* b0p = W + (size_t)(2 * kp) * DMq + colbase + bn_;
        const float* b1p = W + (size_t)(2 * kp + 1) * DMq + colbase + bn_;
        float4 r0 = *(const float4*)b0p, r1 = *(const float4*)b1p;
        SB[0][bn_ + 0][slot] = ph2(r0.x, r1.x);
        SB[0][bn_ + 1][slot] = ph2(r0.y, r1.y);
        SB[0][bn_ + 2][slot] = ph2(r0.z, r1.z);
        SB[0][bn_ + 3][slot] = ph2(r0.w, r1.w);
    }
    __syncthreads();

    for (int it = 0; it < NIT; it++) {
        const int st = it & 1;
        float4 a0, a1, r0, r1;
        const bool more = (it + 1 < NIT);
        if (more) {
            int k0 = (it + 1) * 16;
            const float* ap = srcA + (size_t)sm * DMq + k0 + 8 * w;
            a0 = *(const float4*)(ap);
            a1 = *(const float4*)(ap + 4);
            const float* b0p = W + (size_t)(k0 + 2 * kp) * DMq + colbase + bn_;
            const float* b1p = W + (size_t)(k0 + 2 * kp + 1) * DMq + colbase + bn_;
            r0 = *(const float4*)b0p;
            r1 = *(const float4*)b1p;
        }
        {
            uint32_t af[4][4], bf[4][2];
#pragma unroll
            for (int mi = 0; mi < 4; mi++) {
                uint2 lo = *(const uint2*)&SA[st][wm + mi * 16 + lg][2 * lt];
                uint2 hi = *(const uint2*)&SA[st][wm + mi * 16 + 8 + lg][2 * lt];
                af[mi][0] = lo.x; af[mi][1] = hi.x; af[mi][2] = lo.y; af[mi][3] = hi.y;
            }
#pragma unroll
            for (int ni = 0; ni < 4; ni++) {
                uint2 bb = *(const uint2*)&SB[st][wn + ni * 8 + lg][2 * lt];
                bf[ni][0] = bb.x; bf[ni][1] = bb.y;
            }
#pragma unroll
            for (int mi = 0; mi < 4; mi++)
#pragma unroll
                for (int ni = 0; ni < 4; ni++) mma16(acc[mi][ni], af[mi], bf[ni]);
        }
        if (more) {
            stage_f32(&SA[st ^ 1][sm][0], w, a0, a1);
            SB[st ^ 1][bn_ + 0][slot] = ph2(r0.x, r1.x);
            SB[st ^ 1][bn_ + 1][slot] = ph2(r0.y, r1.y);
            SB[st ^ 1][bn_ + 2][slot] = ph2(r0.z, r1.z);
            SB[st ^ 1][bn_ + 3][slot] = ph2(r0.w, r1.w);
        }
        __syncthreads();
    }

#pragma unroll
    for (int mi = 0; mi < 4; mi++) {
        int r0 = m0 + wm + mi * 16 + lg;
#pragma unroll
        for (int ni = 0; ni < 4; ni++) {
            int c0 = n0 + wn + ni * 8 + 2 * lt;
            float bv0 = bias[(c0) & 511], bv1 = bias[(c0 + 1) & 511];
            *reinterpret_cast<float2*>(&g_C[(size_t)r0 * CC + c0]) =
                make_float2(acc[mi][ni][0] + bv0, acc[mi][ni][1] + bv1);
            *reinterpret_cast<float2*>(&g_C[(size_t)(r0 + 8) * CC + c0]) =
                make_float2(acc[mi][ni][2] + bv0, acc[mi][ni][3] + bv1);
        }
    }
}

// ============================================================
// Kernel 2: rearrange — fp16 outputs
// ============================================================
__global__ void rearrange_kernel() {
    int idx = blockIdx.x * blockDim.x + threadIdx.x;
    if (idx >= NTOK * DMq) return;
    int n = idx / DMq;
    int c = idx % DMq;
    int b = n / Sq, s = n % Sq;
    int h = c / DEPTHq, d = c % DEPTHq;

    float Qc = g_C[(size_t)n * CC + c];
    float Qr = g_C[(size_t)(NTOK + n) * CC + c];
    float Kc = g_C[(size_t)n * CC + 512 + c];
    float Kr = g_C[(size_t)(NTOK + n) * CC + 512 + c];
    float Vv = g_C[(size_t)n * CC + 1024 + c];

    size_t base = ((size_t)(b * Hq + h) * Sq + s) * 128;
    g_Qh[base + d]      = __float2half_rn((Qc + Qr) * 0.125f);
    g_Qh[base + 64 + d] = __float2half_rn(Qc * 0.125f);
    g_Kh[base + d]      = __float2half_rn(Kc);
    g_Kh[base + 64 + d] = __float2half_rn(Kr);
    g_Vh[((size_t)(b * Hq + h) * Sq + s) * DEPTHq + d] = __float2half_rn(Vv);
}

__global__ void zero_rowsum() {
    int i = blockIdx.x * 256 + threadIdx.x;
    if (i < BHq * Sq) g_rowsum[i] = 0.f;
}

// ============================================================
// Kernel 3: logits + exp + rowsum. 128x128, BK=16 dbl-buf, fp16.
// Writes raw exp as fp16 to g_attn_h only.
// ============================================================
__global__ void __launch_bounds__(256, 2)
logits_gemm_tc() {
    __shared__ __align__(16) uint32_t SA[2][128][8];
    __shared__ __align__(16) uint32_t SB[2][128][8];

    const int bh = blockIdx.z;
    const int q0 = blockIdx.y * 128;
    const int t0 = blockIdx.x * 128;
    const __half* Q = g_Qh + (size_t)bh * Sq * 128;
    const __half* K = g_Kh + (size_t)bh * Sq * 128;
    __half* outh = g_attn_h + (size_t)bh * Sq * Sq;

    const int tid = threadIdx.x;
    const int wid = tid >> 5, lane = tid & 31;
    const int wm = (wid >> 2) * 64, wn = (wid & 3) * 32;
    const int lg = lane >> 2, lt = lane & 3;

    const int sm = tid >> 1, w = tid & 1;

    float acc[4][4][4];
#pragma unroll
    for (int i = 0; i < 4; i++)
#pragma unroll
        for (int j = 0; j < 4; j++)
#pragma unroll
            for (int r = 0; r < 4; r++) acc[i][j][r] = 0.f;

    const int NIT = 128 / 16;  // 8

    {
        stage_f16(&SA[0][sm][0], w, *(const uint4*)(Q + (size_t)(q0 + sm) * 128 + 8 * w));
        stage_f16(&SB[0][sm][0], w, *(const uint4*)(K + (size_t)(t0 + sm) * 128 + 8 * w));
    }
    __syncthreads();

    for (int it = 0; it < NIT; it++) {
        const int st = it & 1;
        uint4 ua, ub;
        const bool more = (it + 1 < NIT);
        if (more) {
            int k0 = (it + 1) * 16;
            ua = *(const uint4*)(Q + (size_t)(q0 + sm) * 128 + k0 + 8 * w);
            ub = *(const uint4*)(K + (size_t)(t0 + sm) * 128 + k0 + 8 * w);
        }
        {
            uint32_t af[4][4], bf[4][2];
#pragma unroll
            for (int mi = 0; mi < 4; mi++) {
                uint2 lo = *(const uint2*)&SA[st][wm + mi * 16 + lg][2 * lt];
                uint2 hi = *(const uint2*)&SA[st][wm + mi * 16 + 8 + lg][2 * lt];
                af[mi][0] = lo.x; af[mi][1] = hi.x; af[mi][2] = lo.y; af[mi][3] = hi.y;
            }
#pragma unroll
            for (int ni = 0; ni < 4; ni++) {
                uint2 bb = *(const uint2*)&SB[st][wn + ni * 8 + lg][2 * lt];
                bf[ni][0] = bb.x; bf[ni][1] = bb.y;
            }
#pragma unroll
            for (int mi = 0; mi < 4; mi++)
#pragma unroll
                for (int ni = 0; ni < 4; ni++) mma16(acc[mi][ni], af[mi], bf[ni]);
        }
        if (more) {
            stage_f16(&SA[st ^ 1][sm][0], w, ua);
            stage_f16(&SB[st ^ 1][sm][0], w, ub);
        }
        __syncthreads();
    }

    // Epilogue: exp -> fp16 store + rowsum of the rounded values
#pragma unroll
    for (int mi = 0; mi < 4; mi++) {
        int r0 = q0 + wm + mi * 16 + lg;
        float rs0 = 0.f, rs1 = 0.f;
#pragma unroll
        for (int ni = 0; ni < 4; ni++) {
            int c0 = t0 + wn + ni * 8 + 2 * lt;
            __half2 h01 = __floats2half2_rn(__expf(acc[mi][ni][0]), __expf(acc[mi][ni][1]));
            __half2 h23 = __floats2half2_rn(__expf(acc[mi][ni][2]), __expf(acc[mi][ni][3]));
            *reinterpret_cast<uint32_t*>(&outh[(size_t)r0 * Sq + c0]) =
                *reinterpret_cast<uint32_t*>(&h01);
            *reinterpret_cast<uint32_t*>(&outh[(size_t)(r0 + 8) * Sq + c0]) =
                *reinterpret_cast<uint32_t*>(&h23);
            float2 f01 = __half22float2(h01);
            float2 f23 = __half22float2(h23);
            rs0 += f01.x + f01.y;
            rs1 += f23.x + f23.y;
        }
        rs0 += __shfl_xor_sync(0xffffffffu, rs0, 1);
        rs0 += __shfl_xor_sync(0xffffffffu, rs0, 2);
        rs1 += __shfl_xor_sync(0xffffffffu, rs1, 1);
        rs1 += __shfl_xor_sync(0xffffffffu, rs1, 2);
        if (lt == 0) {
            atomicAdd(&g_rowsum[bh * Sq + r0], rs0);
            atomicAdd(&g_rowsum[bh * Sq + r0 + 8], rs1);
        }
    }
}

// ============================================================
// Kernel 5: zv — reads fp16 raw exp; writes normalized fp32 attn
// to d_out during staging; mma on raw fp16; z scaled by 1/rowsum.
// grid (Sq/128, 2 ksplit, BHq), 256 thr, warp 32x32.
// ============================================================
__global__ void __launch_bounds__(256, 2)
zv_fused_tc(float* __restrict__ attn) {
    __shared__ __align__(16) uint32_t SA[2][128][8];
    __shared__ __align__(16) uint32_t SB[2][64][8];

    const int bh = blockIdx.z;
    const int q0 = blockIdx.x * 128;
    const int ks = blockIdx.y;
    const int b = bh / Hq, h = bh % Hq;
    const __half* Ph = g_attn_h + (size_t)bh * Sq * Sq;
    float* Pout = attn + (size_t)bh * Sq * Sq;
    const __half* V = g_Vh + ((size_t)bh * Sq + ks * 1024) * DEPTHq;
    float* Zp = g_Zp[ks];

    const int tid = threadIdx.x;
    const int wid = tid >> 5, lane = tid & 31;
    const int wm = (wid >> 1) * 32, wn = (wid & 1) * 32;
    const int lg = lane >> 2, lt = lane & 3;

    const int sm = tid >> 1, w = tid & 1;
    const int kp = tid >> 5, bn_ = (tid & 31) * 2;
    const int slot = (kp < 4) ? 2 * kp : 2 * (kp - 4) + 1;

    const float invs = 1.0f / g_rowsum[bh * Sq + q0 + sm];
    const __half* prow = Ph + (size_t)(q0 + sm) * Sq + ks * 1024 + 8 * w;
    float* porow = Pout + (size_t)(q0 + sm) * Sq + ks * 1024 + 8 * w;

    float acc[2][4][4];
#pragma unroll
    for (int i = 0; i < 2; i++)
#pragma unroll
        for (int j = 0; j < 4; j++)
#pragma unroll
            for (int r = 0; r < 4; r++) acc[i][j][r] = 0.f;

    const int NIT = 1024 / 16;  // 64

    {
        uint4 u = *(const uint4*)(prow);
        stage_f16(&SA[0][sm][0], w, u);
        float2 p0 = __half22float2(*reinterpret_cast<__half2*>(&u.x));
        float2 p1 = __half22float2(*reinterpret_cast<__half2*>(&u.y));
        float2 p2 = __half22float2(*reinterpret_cast<__half2*>(&u.z));
        float2 p3 = __half22float2(*reinterpret_cast<__half2*>(&u.w));
        *(float4*)(porow)     = make_float4(p0.x * invs, p0.y * invs, p1.x * invs, p1.y * invs);
        *(float4*)(porow + 4) = make_float4(p2.x * invs, p2.y * invs, p3.x * invs, p3.y * invs);
        const __half* vp = V + (size_t)(2 * kp) * DEPTHq + bn_;
        uint32_t x0 = *(const uint32_t*)vp;
        uint32_t x1 = *(const uint32_t*)(vp + DEPTHq);
        SB[0][bn_][slot]     = __byte_perm(x0, x1, 0x5410);
        SB[0][bn_ + 1][slot] = __byte_perm(x0, x1, 0x7632);
    }
    __syncthreads();

    for (int it = 0; it < NIT; it++) {
        const int st = it & 1;
        uint4 ua;
        uint32_t x0, x1;
        const bool more = (it + 1 < NIT);
        if (more) {
            int k0 = (it + 1) * 16;
            ua = *(const uint4*)(prow + k0);
            float2 p0 = __half22float2(*reinterpret_cast<__half2*>(&ua.x));
            float2 p1 = __half22float2(*reinterpret_cast<__half2*>(&ua.y));
            float2 p2 = __half22float2(*reinterpret_cast<__half2*>(&ua.z));
            float2 p3 = __half22float2(*reinterpret_cast<__half2*>(&ua.w));
            *(float4*)(porow + k0)     = make_float4(p0.x * invs, p0.y * invs, p1.x * invs, p1.y * invs);
            *(float4*)(porow + k0 + 4) = make_float4(p2.x * invs, p2.y * invs, p3.x * invs, p3.y * invs);
            const __half* vp = V + (size_t)(k0 + 2 * kp) * DEPTHq + bn_;
            x0 = *(const uint32_t*)vp;
            x1 = *(const uint32_t*)(vp + DEPTHq);
        }
        {
            uint32_t af[2][4], bf[4][2];
#pragma unroll
            for (int mi = 0; mi < 2; mi++) {
                uint2 lo = *(const uint2*)&SA[st][wm + mi * 16 + lg][2 * lt];
                uint2 hi = *(const uint2*)&SA[st][wm + mi * 16 + 8 + lg][2 * lt];
                af[mi][0] = lo.x; af[mi][1] = hi.x; af[mi][2] = lo.y; af[mi][3] = hi.y;
            }
#pragma unroll
            for (int ni = 0; ni < 4; ni++) {
                uint2 bb = *(const uint2*)&SB[st][wn + ni * 8 + lg][2 * lt];
                bf[ni][0] = bb.x; bf[ni][1] = bb.y;
            }
#pragma unroll
            for (int mi = 0; mi < 2; mi++)
#pragma unroll
                for (int ni = 0; ni < 4; ni++) mma16(acc[mi][ni], af[mi], bf[ni]);
        }
        if (more) {
            stage_f16(&SA[st ^ 1][sm][0], w, ua);
            SB[st ^ 1][bn_][slot]     = __byte_perm(x0, x1, 0x5410);
            SB[st ^ 1][bn_ + 1][slot] = __byte_perm(x0, x1, 0x7632);
        }
        __syncthreads();
    }

    // Epilogue: scale z-partials by 1/rowsum
#pragma unroll
    for (int mi = 0; mi < 2; mi++) {
        int r0 = q0 + wm + mi * 16 + lg;
        float iv0 = 1.0f / g_rowsum[bh * Sq + r0];
        float iv1 = 1.0f / g_rowsum[bh * Sq + r0 + 8];
#pragma unroll
        for (int ni = 0; ni < 4; ni++) {
            int c0 = wn + ni * 8 + 2 * lt;
            size_t base0 = ((size_t)b * Sq + r0) * DMq + h * DEPTHq + c0;
            size_t base1 = ((size_t)b * Sq + r0 + 8) * DMq + h * DEPTHq + c0;
            *reinterpret_cast<float2*>(&Zp[base0]) =
                make_float2(acc[mi][ni][0] * iv0, acc[mi][ni][1] * iv0);
            *reinterpret_cast<float2*>(&Zp[base1]) =
                make_float2(acc[mi][ni][2] * iv1, acc[mi][ni][3] * iv1);
        }
    }
}

// ============================================================
// Kernel 6: out = (Zp0+Zp1) @ Wo + bo, fp16 mma
// ============================================================
__global__ void __launch_bounds__(256, 2)
out_gemm_tc(const float* __restrict__ Wo, const float* __restrict__ bo,
            float* __restrict__ out) {
    __shared__ __align__(16) uint32_t SA[2][128][8];
    __shared__ __align__(16) uint32_t SB[2][128][8];

    const int m0 = blockIdx.y * 128;
    const int n0 = blockIdx.x * 128;
    const int tid = threadIdx.x;
    const int wid = tid >> 5, lane = tid & 31;
    const int wm = (wid >> 2) * 64, wn = (wid & 3) * 32;
    const int lg = lane >> 2, lt = lane & 3;

    const int sm = tid >> 1, w = tid & 1;
    const int kp = tid >> 5, bn_ = (tid & 31) * 4;
    const int slot = (kp < 4) ? 2 * kp : 2 * (kp - 4) + 1;

    float acc[4][4][4];
#pragma unroll
    for (int i = 0; i < 4; i++)
#pragma unroll
        for (int j = 0; j < 4; j++)
#pragma unroll
            for (int r = 0; r < 4; r++) acc[i][j][r] = 0.f;

    const int NIT = DMq / 16;  // 32

    {
        size_t aoff = (size_t)(m0 + sm) * DMq + 8 * w;
        float4 z0 = *(const float4*)(g_Zp[0] + aoff);
        float4 z1 = *(const float4*)(g_Zp[1] + aoff);
        float4 y0 = *(const float4*)(g_Zp[0] + aoff + 4);
        float4 y1 = *(const float4*)(g_Zp[1] + aoff + 4);
        float4 a0 = make_float4(z0.x + z1.x, z0.y + z1.y, z0.z + z1.z, z0.w + z1.w);
        float4 a1 = make_float4(y0.x + y1.x, y0.y + y1.y, y0.z + y1.z, y0.w + y1.w);
        stage_f32(&SA[0][sm][0], w, a0, a1);
        const float* b0p = Wo + (size_t)(2 * kp) * DMq + n0 + bn_;
        const float* b1p = Wo + (size_t)(2 * kp + 1) * DMq + n0 + bn_;
        float4 r0 = *(const float4*)b0p, r1 = *(const float4*)b1p;
        SB[0][bn_ + 0][slot] = ph2(r0.x, r1.x);
        SB[0][bn_ + 1][slot] = ph2(r0.y, r1.y);
        SB[0][bn_ + 2][slot] = ph2(r0.z, r1.z);
        SB[0][bn_ + 3][slot] = ph2(r0.w, r1.w);
    }
    __syncthreads();

    for (int it = 0; it < NIT; it++) {
        const int st = it & 1;
        float4 a0, a1, r0, r1;
        const bool more = (it + 1 < NIT);
        if (more) {
            int k0 = (it + 1) * 16;
            size_t aoff = (size_t)(m0 + sm) * DMq + k0 + 8 * w;
            float4 z0 = *(const float4*)(g_Zp[0] + aoff);
            float4 z1 = *(const float4*)(g_Zp[1] + aoff);
            float4 y0 = *(const float4*)(g_Zp[0] + aoff + 4);
            float4 y1 = *(const float4*)(g_Zp[1] + aoff + 4);
            a0 = make_float4(z0.x + z1.x, z0.y + z1.y, z0.z + z1.z, z0.w + z1.w);
            a1 = make_float4(y0.x + y1.x, y0.y + y1.y, y0.z + y1.z, y0.w + y1.w);
            const float* b0p = Wo + (size_t)(k0 + 2 * kp) * DMq + n0 + bn_;
            const float* b1p = Wo + (size_t)(k0 + 2 * kp + 1) * DMq + n0 + bn_;
            r0 = *(const float4*)b0p;
            r1 = *(const float4*)b1p;
        }
        {
            uint32_t af[4][4], bf[4][2];
#pragma unroll
            for (int mi = 0; mi < 4; mi++) {
                uint2 lo = *(const uint2*)&SA[st][wm + mi * 16 + lg][2 * lt];
                uint2 hi = *(const uint2*)&SA[st][wm + mi * 16 + 8 + lg][2 * lt];
                af[mi][0] = lo.x; af[mi][1] = hi.x; af[mi][2] = lo.y; af[mi][3] = hi.y;
            }
#pragma unroll
            for (int ni = 0; ni < 4; ni++) {
                uint2 bb = *(const uint2*)&SB[st][wn + ni * 8 + lg][2 * lt];
                bf[ni][0] = bb.x; bf[ni][1] = bb.y;
            }
#pragma unroll
            for (int mi = 0; mi < 4; mi++)
#pragma unroll
                for (int ni = 0; ni < 4; ni++) mma16(acc[mi][ni], af[mi], bf[ni]);
        }
        if (more) {
            stage_f32(&SA[st ^ 1][sm][0], w, a0, a1);
            SB[st ^ 1][bn_ + 0][slot] = ph2(r0.x, r1.x);
            SB[st ^ 1][bn_ + 1][slot] = ph2(r0.y, r1.y);
            SB[st ^ 1][bn_ + 2][slot] = ph2(r0.z, r1.z);
            SB[st ^ 1][bn_ + 3][slot] = ph2(r0.w, r1.w);
        }
        __syncthreads();
    }

#pragma unroll
    for (int mi = 0; mi < 4; mi++) {
        int r0 = m0 + wm + mi * 16 + lg;
#pragma unroll
        for (int ni = 0; ni < 4; ni++) {
            int c0 = n0 + wn + ni * 8 + 2 * lt;
            float bv0 = bo[c0], bv1 = bo[c0 + 1];
            *reinterpret_cast<float2*>(&out[(size_t)r0 * DMq + c0]) =
                make_float2(acc[mi][ni][0] + bv0, acc[mi][ni][1] + bv1);
            *reinterpret_cast<float2*>(&out[(size_t)(r0 + 8) * DMq + c0]) =
                make_float2(acc[mi][ni][2] + bv0, acc[mi][ni][3] + bv1);
        }
    }
}

// ============================================================
// Launch
// ============================================================
extern "C" void kernel_launch(void* const* d_in, const int* in_sizes, int n_in,
                              void* d_out, int out_size) {
    const float* emb = (const float*)d_in[0];
    const float* pe  = (const float*)d_in[1];
    const float* Wq  = (const float*)d_in[2];
    const float* bq  = (const float*)d_in[3];
    const float* Wk  = (const float*)d_in[4];
    const float* bk  = (const float*)d_in[5];
    const float* Wv  = (const float*)d_in[6];
    const float* bv  = (const float*)d_in[7];
    const float* Wo  = (const float*)d_in[8];
    const float* bo  = (const float*)d_in[9];

    float* out = (float*)d_out;

    const long long need = (long long)NTOK * DMq + (long long)BHq * Sq * Sq;
    float* attn;
    if ((long long)out_size >= need) {
        attn = out + (size_t)NTOK * DMq;
    } else {
        float* p = nullptr;
        cudaGetSymbolAddress((void**)&p, g_attn_fallback);
        attn = p;
    }

    {
        dim3 grid(CC / 128, NROWS / 128);
        proj_gemm_tc<<<grid, 256>>>(emb, pe, Wq, bq, Wk, bk, Wv, bv);
    }
    {
        int total = NTOK * DMq;
        rearrange_kernel<<<(total + 255) / 256, 256>>>();
    }
    {
        zero_rowsum<<<(BHq * Sq + 255) / 256, 256>>>();
    }
    {
        dim3 grid(Sq / 128, Sq / 128, BHq);
        logits_gemm_tc<<<grid, 256>>>();
    }
    {
        dim3 grid(Sq / 128, 2, BHq);
        zv_fused_tc<<<grid, 256>>>(attn);
    }
    {
        dim3 grid(DMq / 128, NTOK / 128);
        out_gemm_tc<<<grid, 256>>>(Wo, bo, out);
    }
}

// round 10
// speedup vs baseline: 1.4786x; 1.1090x over previous
#include <cuda_runtime.h>
#include <cuda_fp16.h>
#include <cstdint>

#define Bq 2
#define Sq 2048
#define Hq 8
#define DEPTHq 64
#define DMq 512
#define NTOK (Bq * Sq)
#define NROWS (2 * NTOK)
#define CC 1536
#define BHq (Bq * Hq)

// ---------------- device scratch ----------------
__device__ float  g_C[NROWS * CC];
__device__ __half g_Qh[BHq * Sq * 128];
__device__ __half g_Kh[BHq * Sq * 128];
__device__ __half g_Vh[BHq * Sq * DEPTHq];
__device__ __half g_attn_h[(size_t)BHq * Sq * Sq];   // raw exp, fp16
__device__ float  g_Zp[2][NTOK * DMq];
__device__ float  g_rowsum[BHq * Sq];
__device__ float  g_attn_fallback[(size_t)BHq * Sq * Sq];

// ---------------- fp16 helpers ----------------
__device__ __forceinline__ uint32_t ph2(float a, float b) {
    __half2 h = __floats2half2_rn(a, b);
    return *reinterpret_cast<uint32_t*>(&h);
}
__device__ __forceinline__ void mma16(float* c, const uint32_t* a, const uint32_t* b) {
    asm volatile(
        "mma.sync.aligned.m16n8k16.row.col.f32.f16.f16.f32 "
        "{%0,%1,%2,%3}, {%4,%5,%6,%7}, {%8,%9}, {%0,%1,%2,%3};"
        : "+f"(c[0]), "+f"(c[1]), "+f"(c[2]), "+f"(c[3])
        : "r"(a[0]), "r"(a[1]), "r"(a[2]), "r"(a[3]),
          "r"(b[0]), "r"(b[1]));
}
__device__ __forceinline__ void stage_f32(uint32_t* rowp, int w, float4 v0, float4 v1) {
    rowp[0 + w] = ph2(v0.x, v0.y);
    rowp[2 + w] = ph2(v0.z, v0.w);
    rowp[4 + w] = ph2(v1.x, v1.y);
    rowp[6 + w] = ph2(v1.z, v1.w);
}
__device__ __forceinline__ void stage_f16(uint32_t* rowp, int w, uint4 u) {
    rowp[0 + w] = u.x;
    rowp[2 + w] = u.y;
    rowp[4 + w] = u.z;
    rowp[6 + w] = u.w;
}
__device__ __forceinline__ uint32_t smem_u32(const void* p) {
    uint32_t a;
    asm("{ .reg .u64 t; cvta.to.shared.u64 t, %1; cvt.u32.u64 %0, t; }" : "=r"(a) : "l"(p));
    return a;
}
__device__ __forceinline__ void cp16(uint32_t dst, const void* src) {
    asm volatile("cp.async.ca.shared.global [%0], [%1], 16;" :: "r"(dst), "l"(src));
}
__device__ __forceinline__ void ldsm4(uint32_t* r, uint32_t addr) {
    asm volatile("ldmatrix.sync.aligned.m8n8.x4.shared.b16 {%0,%1,%2,%3}, [%4];"
                 : "=r"(r[0]), "=r"(r[1]), "=r"(r[2]), "=r"(r[3]) : "r"(addr));
}

// ============================================================
// Kernel 1: proj (R9 fp16 design, unchanged)
// ============================================================
__global__ void __launch_bounds__(256, 2)
proj_gemm_tc(const float* __restrict__ emb, const float* __restrict__ pe,
             const float* __restrict__ Wq, const float* __restrict__ bq,
             const float* __restrict__ Wk, const float* __restrict__ bk,
             const float* __restrict__ Wv, const float* __restrict__ bv) {
    __shared__ __align__(16) uint32_t SA[2][128][8];
    __shared__ __align__(16) uint32_t SB[2][128][8];

    const int m0 = blockIdx.y * 128;
    const int n0 = blockIdx.x * 128;
    const int tid = threadIdx.x;
    const int wid = tid >> 5, lane = tid & 31;
    const int wm = (wid >> 2) * 64, wn = (wid & 3) * 32;
    const int lg = lane >> 2, lt = lane & 3;

    const float* srcA = (m0 < NTOK) ? (emb + (size_t)m0 * DMq)
                                    : (pe + (size_t)(m0 - NTOK) * DMq);
    const float* W    = (n0 < 512) ? Wq : (n0 < 1024 ? Wk : Wv);
    const float* bias = (n0 < 512) ? bq : (n0 < 1024 ? bk : bv);
    const int colbase = n0 & 511;

    const int sm = tid >> 1, w = tid & 1;
    const int kp = tid >> 5, bn_ = (tid & 31) * 4;
    const int slot = (kp < 4) ? 2 * kp : 2 * (kp - 4) + 1;

    float acc[4][4][4];
#pragma unroll
    for (int i = 0; i < 4; i++)
#pragma unroll
        for (int j = 0; j < 4; j++)
#pragma unroll
            for (int r = 0; r < 4; r++) acc[i][j][r] = 0.f;

    const int NIT = DMq / 16;

    {
        const float* ap = srcA + (size_t)sm * DMq + 8 * w;
        stage_f32(&SA[0][sm][0], w, *(const float4*)ap, *(const float4*)(ap + 4));
        const float* b0p = W + (size_t)(2 * kp) * DMq + colbase + bn_;
        const float* b1p = W + (size_t)(2 * kp + 1) * DMq + colbase + bn_;
        float4 r0 = *(const float4*)b0p, r1 = *(const float4*)b1p;
        SB[0][bn_ + 0][slot] = ph2(r0.x, r1.x);
        SB[0][bn_ + 1][slot] = ph2(r0.y, r1.y);
        SB[0][bn_ + 2][slot] = ph2(r0.z, r1.z);
        SB[0][bn_ + 3][slot] = ph2(r0.w, r1.w);
    }
    __syncthreads();

    for (int it = 0; it < NIT; it++) {
        const int st = it & 1;
        float4 a0, a1, r0, r1;
        const bool more = (it + 1 < NIT);
        if (more) {
            int k0 = (it + 1) * 16;
            const float* ap = srcA + (size_t)sm * DMq + k0 + 8 * w;
            a0 = *(const float4*)(ap);
            a1 = *(const float4*)(ap + 4);
            const float* b0p = W + (size_t)(k0 + 2 * kp) * DMq + colbase + bn_;
            const float* b1p = W + (size_t)(k0 + 2 * kp + 1) * DMq + colbase + bn_;
            r0 = *(const float4*)b0p;
            r1 = *(const float4*)b1p;
        }
        {
            uint32_t af[4][4], bf[4][2];
#pragma unroll
            for (int mi = 0; mi < 4; mi++) {
                uint2 lo = *(const uint2*)&SA[st][wm + mi * 16 + lg][2 * lt];
                uint2 hi = *(const uint2*)&SA[st][wm + mi * 16 + 8 + lg][2 * lt];
                af[mi][0] = lo.x; af[mi][1] = hi.x; af[mi][2] = lo.y; af[mi][3] = hi.y;
            }
#pragma unroll
            for (int ni = 0; ni < 4; ni++) {
                uint2 bb = *(const uint2*)&SB[st][wn + ni * 8 + lg][2 * lt];
                bf[ni][0] = bb.x; bf[ni][1] = bb.y;
            }
#pragma unroll
            for (int mi = 0; mi < 4; mi++)
#pragma unroll
                for (int ni = 0; ni < 4; ni++) mma16(acc[mi][ni], af[mi], bf[ni]);
        }
        if (more) {
            stage_f32(&SA[st ^ 1][sm][0], w, a0, a1);
            SB[st ^ 1][bn_ + 0][slot] = ph2(r0.x, r1.x);
            SB[st ^ 1][bn_ + 1][slot] = ph2(r0.y, r1.y);
            SB[st ^ 1][bn_ + 2][slot] = ph2(r0.z, r1.z);
            SB[st ^ 1][bn_ + 3][slot] = ph2(r0.w, r1.w);
        }
        __syncthreads();
    }

#pragma unroll
    for (int mi = 0; mi < 4; mi++) {
        int r0 = m0 + wm + mi * 16 + lg;
#pragma unroll
        for (int ni = 0; ni < 4; ni++) {
            int c0 = n0 + wn + ni * 8 + 2 * lt;
            float bv0 = bias[(c0) & 511], bv1 = bias[(c0 + 1) & 511];
            *reinterpret_cast<float2*>(&g_C[(size_t)r0 * CC + c0]) =
                make_float2(acc[mi][ni][0] + bv0, acc[mi][ni][1] + bv1);
            *reinterpret_cast<float2*>(&g_C[(size_t)(r0 + 8) * CC + c0]) =
                make_float2(acc[mi][ni][2] + bv0, acc[mi][ni][3] + bv1);
        }
    }
}

// ============================================================
// Kernel 2: rearrange — fp16 outputs
// ============================================================
__global__ void rearrange_kernel() {
    int idx = blockIdx.x * blockDim.x + threadIdx.x;
    if (idx >= NTOK * DMq) return;
    int n = idx / DMq;
    int c = idx % DMq;
    int b = n / Sq, s = n % Sq;
    int h = c / DEPTHq, d = c % DEPTHq;

    float Qc = g_C[(size_t)n * CC + c];
    float Qr = g_C[(size_t)(NTOK + n) * CC + c];
    float Kc = g_C[(size_t)n * CC + 512 + c];
    float Kr = g_C[(size_t)(NTOK + n) * CC + 512 + c];
    float Vv = g_C[(size_t)n * CC + 1024 + c];

    size_t base = ((size_t)(b * Hq + h) * Sq + s) * 128;
    g_Qh[base + d]      = __float2half_rn((Qc + Qr) * 0.125f);
    g_Qh[base + 64 + d] = __float2half_rn(Qc * 0.125f);
    g_Kh[base + d]      = __float2half_rn(Kc);
    g_Kh[base + 64 + d] = __float2half_rn(Kr);
    g_Vh[((size_t)(b * Hq + h) * Sq + s) * DEPTHq + d] = __float2half_rn(Vv);
}

__global__ void zero_rowsum() {
    int i = blockIdx.x * 256 + threadIdx.x;
    if (i < BHq * Sq) g_rowsum[i] = 0.f;
}

// ============================================================
// Kernel 3 (NEW): logits via whole-tile-resident smem.
// 4 warps (2x2) of 64x64 warp tiles, 128 threads.
// cp.async loads full 128x128 fp16 Q and K tiles once (68KB),
// then 8 fully unrolled k16 chunks of ldmatrix + HMMA.
// Row stride 272B => ldmatrix conflict-free (row r -> banks 4r..4r+3).
// ============================================================
#define ROWB 272
#define LOG_SMEM (2 * 128 * ROWB)   // 69632

__global__ void __launch_bounds__(128)
logits_gemm_tc() {
    extern __shared__ char dsm[];
    const uint32_t sa = smem_u32(dsm);
    const uint32_t sb = sa + 128 * ROWB;

    const int bh = blockIdx.z;
    const int q0 = blockIdx.y * 128;
    const int t0 = blockIdx.x * 128;
    const __half* Q = g_Qh + (size_t)bh * Sq * 128;
    const __half* K = g_Kh + (size_t)bh * Sq * 128;
    __half* outh = g_attn_h + (size_t)bh * Sq * Sq;

    const int tid = threadIdx.x;
    const int wid = tid >> 5, lane = tid & 31;
    const int wm = (wid >> 1) * 64, wn = (wid & 1) * 64;
    const int lg = lane >> 2, lt = lane & 3;

    // ---- prologue: cp.async full tiles ----
    {
        const int cr = tid >> 4;     // 0..7  (row within group of 8)
        const int cc = tid & 15;     // 0..15 (16B chunk within row)
#pragma unroll
        for (int i = 0; i < 16; i++) {
            int row = i * 8 + cr;
            cp16(sa + row * ROWB + cc * 16, Q + (size_t)(q0 + row) * 128 + cc * 8);
            cp16(sb + row * ROWB + cc * 16, K + (size_t)(t0 + row) * 128 + cc * 8);
        }
        asm volatile("cp.async.commit_group;" ::: "memory");
        asm volatile("cp.async.wait_group 0;" ::: "memory");
    }
    __syncthreads();

    float acc[4][8][4];
#pragma unroll
    for (int i = 0; i < 4; i++)
#pragma unroll
        for (int j = 0; j < 8; j++)
#pragma unroll
            for (int r = 0; r < 4; r++) acc[i][j][r] = 0.f;

    // ldmatrix lane addresses (chunk-invariant part)
    // A (16x16): lanes 0-15 rows, lanes 16-31 same rows k+8
    const uint32_t aAddrBase = sa + (uint32_t)(wm + (lane & 15)) * ROWB + ((lane >> 4) & 1) * 16;
    // B (two n8 x k16): n-col = wn + blk*8 + (lane&7); k-half sel by (lane>>3)&1
    const uint32_t bAddrBase = sb + (uint32_t)(wn + ((lane >> 4) & 1) * 8 + (lane & 7)) * ROWB +
                               ((lane >> 3) & 1) * 16;

#pragma unroll
    for (int c = 0; c < 8; c++) {
        const uint32_t coff = c * 32;   // 16 halves = 32 bytes
        uint32_t bf[8][2];
#pragma unroll
        for (int np = 0; np < 4; np++) {
            uint32_t r4[4];
            ldsm4(r4, bAddrBase + np * 16 * ROWB + coff);
            bf[2 * np][0] = r4[0];
            bf[2 * np][1] = r4[1];
            bf[2 * np + 1][0] = r4[2];
            bf[2 * np + 1][1] = r4[3];
        }
#pragma unroll
        for (int mi = 0; mi < 4; mi++) {
            uint32_t af[4];
            ldsm4(af, aAddrBase + mi * 16 * ROWB + coff);
#pragma unroll
            for (int ni = 0; ni < 8; ni++) mma16(acc[mi][ni], af, bf[ni]);
        }
    }

    // ---- epilogue: exp -> fp16 store + rowsum ----
#pragma unroll
    for (int mi = 0; mi < 4; mi++) {
        int r0 = q0 + wm + mi * 16 + lg;
        float rs0 = 0.f, rs1 = 0.f;
#pragma unroll
        for (int ni = 0; ni < 8; ni++) {
            int c0 = t0 + wn + ni * 8 + 2 * lt;
            __half2 h01 = __floats2half2_rn(__expf(acc[mi][ni][0]), __expf(acc[mi][ni][1]));
            __half2 h23 = __floats2half2_rn(__expf(acc[mi][ni][2]), __expf(acc[mi][ni][3]));
            *reinterpret_cast<uint32_t*>(&outh[(size_t)r0 * Sq + c0]) =
                *reinterpret_cast<uint32_t*>(&h01);
            *reinterpret_cast<uint32_t*>(&outh[(size_t)(r0 + 8) * Sq + c0]) =
                *reinterpret_cast<uint32_t*>(&h23);
            float2 f01 = __half22float2(h01);
            float2 f23 = __half22float2(h23);
            rs0 += f01.x + f01.y;
            rs1 += f23.x + f23.y;
        }
        rs0 += __shfl_xor_sync(0xffffffffu, rs0, 1);
        rs0 += __shfl_xor_sync(0xffffffffu, rs0, 2);
        rs1 += __shfl_xor_sync(0xffffffffu, rs1, 1);
        rs1 += __shfl_xor_sync(0xffffffffu, rs1, 2);
        if (lt == 0) {
            atomicAdd(&g_rowsum[bh * Sq + r0], rs0);
            atomicAdd(&g_rowsum[bh * Sq + r0 + 8], rs1);
        }
    }
}

// ============================================================
// Kernel 5: zv (R9 design, unchanged)
// ============================================================
__global__ void __launch_bounds__(256, 2)
zv_fused_tc(float* __restrict__ attn) {
    __shared__ __align__(16) uint32_t SA[2][128][8];
    __shared__ __align__(16) uint32_t SB[2][64][8];

    const int bh = blockIdx.z;
    const int q0 = blockIdx.x * 128;
    const int ks = blockIdx.y;
    const int b = bh / Hq, h = bh % Hq;
    const __half* Ph = g_attn_h + (size_t)bh * Sq * Sq;
    float* Pout = attn + (size_t)bh * Sq * Sq;
    const __half* V = g_Vh + ((size_t)bh * Sq + ks * 1024) * DEPTHq;
    float* Zp = g_Zp[ks];

    const int tid = threadIdx.x;
    const int wid = tid >> 5, lane = tid & 31;
    const int wm = (wid >> 1) * 32, wn = (wid & 1) * 32;
    const int lg = lane >> 2, lt = lane & 3;

    const int sm = tid >> 1, w = tid & 1;
    const int kp = tid >> 5, bn_ = (tid & 31) * 2;
    const int slot = (kp < 4) ? 2 * kp : 2 * (kp - 4) + 1;

    const float invs = 1.0f / g_rowsum[bh * Sq + q0 + sm];
    const __half* prow = Ph + (size_t)(q0 + sm) * Sq + ks * 1024 + 8 * w;
    float* porow = Pout + (size_t)(q0 + sm) * Sq + ks * 1024 + 8 * w;

    float acc[2][4][4];
#pragma unroll
    for (int i = 0; i < 2; i++)
#pragma unroll
        for (int j = 0; j < 4; j++)
#pragma unroll
            for (int r = 0; r < 4; r++) acc[i][j][r] = 0.f;

    const int NIT = 1024 / 16;

    {
        uint4 u = *(const uint4*)(prow);
        stage_f16(&SA[0][sm][0], w, u);
        float2 p0 = __half22float2(*reinterpret_cast<__half2*>(&u.x));
        float2 p1 = __half22float2(*reinterpret_cast<__half2*>(&u.y));
        float2 p2 = __half22float2(*reinterpret_cast<__half2*>(&u.z));
        float2 p3 = __half22float2(*reinterpret_cast<__half2*>(&u.w));
        *(float4*)(porow)     = make_float4(p0.x * invs, p0.y * invs, p1.x * invs, p1.y * invs);
        *(float4*)(porow + 4) = make_float4(p2.x * invs, p2.y * invs, p3.x * invs, p3.y * invs);
        const __half* vp = V + (size_t)(2 * kp) * DEPTHq + bn_;
        uint32_t x0 = *(const uint32_t*)vp;
        uint32_t x1 = *(const uint32_t*)(vp + DEPTHq);
        SB[0][bn_][slot]     = __byte_perm(x0, x1, 0x5410);
        SB[0][bn_ + 1][slot] = __byte_perm(x0, x1, 0x7632);
    }
    __syncthreads();

    for (int it = 0; it < NIT; it++) {
        const int st = it & 1;
        uint4 ua;
        uint32_t x0, x1;
        const bool more = (it + 1 < NIT);
        if (more) {
            int k0 = (it + 1) * 16;
            ua = *(const uint4*)(prow + k0);
            float2 p0 = __half22float2(*reinterpret_cast<__half2*>(&ua.x));
            float2 p1 = __half22float2(*reinterpret_cast<__half2*>(&ua.y));
            float2 p2 = __half22float2(*reinterpret_cast<__half2*>(&ua.z));
            float2 p3 = __half22float2(*reinterpret_cast<__half2*>(&ua.w));
            *(float4*)(porow + k0)     = make_float4(p0.x * invs, p0.y * invs, p1.x * invs, p1.y * invs);
            *(float4*)(porow + k0 + 4) = make_float4(p2.x * invs, p2.y * invs, p3.x * invs, p3.y * invs);
            const __half* vp = V + (size_t)(k0 + 2 * kp) * DEPTHq + bn_;
            x0 = *(const uint32_t*)vp;
            x1 = *(const uint32_t*)(vp + DEPTHq);
        }
        {
            uint32_t af[2][4], bf[4][2];
#pragma unroll
            for (int mi = 0; mi < 2; mi++) {
                uint2 lo = *(const uint2*)&SA[st][wm + mi * 16 + lg][2 * lt];
                uint2 hi = *(const uint2*)&SA[st][wm + mi * 16 + 8 + lg][2 * lt];
                af[mi][0] = lo.x; af[mi][1] = hi.x; af[mi][2] = lo.y; af[mi][3] = hi.y;
            }
#pragma unroll
            for (int ni = 0; ni < 4; ni++) {
                uint2 bb = *(const uint2*)&SB[st][wn + ni * 8 + lg][2 * lt];
                bf[ni][0] = bb.x; bf[ni][1] = bb.y;
            }
#pragma unroll
            for (int mi = 0; mi < 2; mi++)
#pragma unroll
                for (int ni = 0; ni < 4; ni++) mma16(acc[mi][ni], af[mi], bf[ni]);
        }
        if (more) {
            stage_f16(&SA[st ^ 1][sm][0], w, ua);
            SB[st ^ 1][bn_][slot]     = __byte_perm(x0, x1, 0x5410);
            SB[st ^ 1][bn_ + 1][slot] = __byte_perm(x0, x1, 0x7632);
        }
        __syncthreads();
    }

#pragma unroll
    for (int mi = 0; mi < 2; mi++) {
        int r0 = q0 + wm + mi * 16 + lg;
        float iv0 = 1.0f / g_rowsum[bh * Sq + r0];
        float iv1 = 1.0f / g_rowsum[bh * Sq + r0 + 8];
#pragma unroll
        for (int ni = 0; ni < 4; ni++) {
            int c0 = wn + ni * 8 + 2 * lt;
            size_t base0 = ((size_t)b * Sq + r0) * DMq + h * DEPTHq + c0;
            size_t base1 = ((size_t)b * Sq + r0 + 8) * DMq + h * DEPTHq + c0;
            *reinterpret_cast<float2*>(&Zp[base0]) =
                make_float2(acc[mi][ni][0] * iv0, acc[mi][ni][1] * iv0);
            *reinterpret_cast<float2*>(&Zp[base1]) =
                make_float2(acc[mi][ni][2] * iv1, acc[mi][ni][3] * iv1);
        }
    }
}

// ============================================================
// Kernel 6: out (R9 design, unchanged)
// ============================================================
__global__ void __launch_bounds__(256, 2)
out_gemm_tc(const float* __restrict__ Wo, const float* __restrict__ bo,
            float* __restrict__ out) {
    __shared__ __align__(16) uint32_t SA[2][128][8];
    __shared__ __align__(16) uint32_t SB[2][128][8];

    const int m0 = blockIdx.y * 128;
    const int n0 = blockIdx.x * 128;
    const int tid = threadIdx.x;
    const int wid = tid >> 5, lane = tid & 31;
    const int wm = (wid >> 2) * 64, wn = (wid & 3) * 32;
    const int lg = lane >> 2, lt = lane & 3;

    const int sm = tid >> 1, w = tid & 1;
    const int kp = tid >> 5, bn_ = (tid & 31) * 4;
    const int slot = (kp < 4) ? 2 * kp : 2 * (kp - 4) + 1;

    float acc[4][4][4];
#pragma unroll
    for (int i = 0; i < 4; i++)
#pragma unroll
        for (int j = 0; j < 4; j++)
#pragma unroll
            for (int r = 0; r < 4; r++) acc[i][j][r] = 0.f;

    const int NIT = DMq / 16;

    {
        size_t aoff = (size_t)(m0 + sm) * DMq + 8 * w;
        float4 z0 = *(const float4*)(g_Zp[0] + aoff);
        float4 z1 = *(const float4*)(g_Zp[1] + aoff);
        float4 y0 = *(const float4*)(g_Zp[0] + aoff + 4);
        float4 y1 = *(const float4*)(g_Zp[1] + aoff + 4);
        float4 a0 = make_float4(z0.x + z1.x, z0.y + z1.y, z0.z + z1.z, z0.w + z1.w);
        float4 a1 = make_float4(y0.x + y1.x, y0.y + y1.y, y0.z + y1.z, y0.w + y1.w);
        stage_f32(&SA[0][sm][0], w, a0, a1);
        const float* b0p = Wo + (size_t)(2 * kp) * DMq + n0 + bn_;
        const float* b1p = Wo + (size_t)(2 * kp + 1) * DMq + n0 + bn_;
        float4 r0 = *(const float4*)b0p, r1 = *(const float4*)b1p;
        SB[0][bn_ + 0][slot] = ph2(r0.x, r1.x);
        SB[0][bn_ + 1][slot] = ph2(r0.y, r1.y);
        SB[0][bn_ + 2][slot] = ph2(r0.z, r1.z);
        SB[0][bn_ + 3][slot] = ph2(r0.w, r1.w);
    }
    __syncthreads();

    for (int it = 0; it < NIT; it++) {
        const int st = it & 1;
        float4 a0, a1, r0, r1;
        const bool more = (it + 1 < NIT);
        if (more) {
            int k0 = (it + 1) * 16;
            size_t aoff = (size_t)(m0 + sm) * DMq + k0 + 8 * w;
            float4 z0 = *(const float4*)(g_Zp[0] + aoff);
            float4 z1 = *(const float4*)(g_Zp[1] + aoff);
            float4 y0 = *(const float4*)(g_Zp[0] + aoff + 4);
            float4 y1 = *(const float4*)(g_Zp[1] + aoff + 4);
            a0 = make_float4(z0.x + z1.x, z0.y + z1.y, z0.z + z1.z, z0.w + z1.w);
            a1 = make_float4(y0.x + y1.x, y0.y + y1.y, y0.z + y1.z, y0.w + y1.w);
            const float* b0p = Wo + (size_t)(k0 + 2 * kp) * DMq + n0 + bn_;
            const float* b1p = Wo + (size_t)(k0 + 2 * kp + 1) * DMq + n0 + bn_;
            r0 = *(const float4*)b0p;
            r1 = *(const float4*)b1p;
        }
        {
            uint32_t af[4][4], bf[4][2];
#pragma unroll
            for (int mi = 0; mi < 4; mi++) {
                uint2 lo = *(const uint2*)&SA[st][wm + mi * 16 + lg][2 * lt];
                uint2 hi = *(const uint2*)&SA[st][wm + mi * 16 + 8 + lg][2 * lt];
                af[mi][0] = lo.x; af[mi][1] = hi.x; af[mi][2] = lo.y; af[mi][3] = hi.y;
            }
#pragma unroll
            for (int ni = 0; ni < 4; ni++) {
                uint2 bb = *(const uint2*)&SB[st][wn + ni * 8 + lg][2 * lt];
                bf[ni][0] = bb.x; bf[ni][1] = bb.y;
            }
#pragma unroll
            for (int mi = 0; mi < 4; mi++)
#pragma unroll
                for (int ni = 0; ni < 4; ni++) mma16(acc[mi][ni], af[mi], bf[ni]);
        }
        if (more) {
            stage_f32(&SA[st ^ 1][sm][0], w, a0, a1);
            SB[st ^ 1][bn_ + 0][slot] = ph2(r0.x, r1.x);
            SB[st ^ 1][bn_ + 1][slot] = ph2(r0.y, r1.y);
            SB[st ^ 1][bn_ + 2][slot] = ph2(r0.z, r1.z);
            SB[st ^ 1][bn_ + 3][slot] = ph2(r0.w, r1.w);
        }
        __syncthreads();
    }

#pragma unroll
    for (int mi = 0; mi < 4; mi++) {
        int r0 = m0 + wm + mi * 16 + lg;
#pragma unroll
        for (int ni = 0; ni < 4; ni++) {
            int c0 = n0 + wn + ni * 8 + 2 * lt;
            float bv0 = bo[c0], bv1 = bo[c0 + 1];
            *reinterpret_cast<float2*>(&out[(size_t)r0 * DMq + c0]) =
                make_float2(acc[mi][ni][0] + bv0, acc[mi][ni][1] + bv1);
            *reinterpret_cast<float2*>(&out[(size_t)(r0 + 8) * DMq + c0]) =
                make_float2(acc[mi][ni][2] + bv0, acc[mi][ni][3] + bv1);
        }
    }
}

// ============================================================
// Launch
// ============================================================
extern "C" void kernel_launch(void* const* d_in, const int* in_sizes, int n_in,
                              void* d_out, int out_size) {
    const float* emb = (const float*)d_in[0];
    const float* pe  = (const float*)d_in[1];
    const float* Wq  = (const float*)d_in[2];
    const float* bq  = (const float*)d_in[3];
    const float* Wk  = (const float*)d_in[4];
    const float* bk  = (const float*)d_in[5];
    const float* Wv  = (const float*)d_in[6];
    const float* bv  = (const float*)d_in[7];
    const float* Wo  = (const float*)d_in[8];
    const float* bo  = (const float*)d_in[9];

    float* out = (float*)d_out;

    const long long need = (long long)NTOK * DMq + (long long)BHq * Sq * Sq;
    float* attn;
    if ((long long)out_size >= need) {
        attn = out + (size_t)NTOK * DMq;
    } else {
        float* p = nullptr;
        cudaGetSymbolAddress((void**)&p, g_attn_fallback);
        attn = p;
    }

    cudaFuncSetAttribute(logits_gemm_tc,
                         cudaFuncAttributeMaxDynamicSharedMemorySize, LOG_SMEM);

    {
        dim3 grid(CC / 128, NROWS / 128);
        proj_gemm_tc<<<grid, 256>>>(emb, pe, Wq, bq, Wk, bk, Wv, bv);
    }
    {
        int total = NTOK * DMq;
        rearrange_kernel<<<(total + 255) / 256, 256>>>();
    }
    {
        zero_rowsum<<<(BHq * Sq + 255) / 256, 256>>>();
    }
    {
        dim3 grid(Sq / 128, Sq / 128, BHq);
        logits_gemm_tc<<<grid, 128, LOG_SMEM>>>();
    }
    {
        dim3 grid(Sq / 128, 2, BHq);
        zv_fused_tc<<<grid, 256>>>(attn);
    }
    {
        dim3 grid(DMq / 128, NTOK / 128);
        out_gemm_tc<<<grid, 256>>>(Wo, bo, out);
    }
}

// round 11
// speedup vs baseline: 1.5501x; 1.0483x over previous
#include <cuda_runtime.h>
#include <cuda_fp16.h>
#include <cstdint>

#define Bq 2
#define Sq 2048
#define Hq 8
#define DEPTHq 64
#define DMq 512
#define NTOK (Bq * Sq)
#define NROWS (2 * NTOK)
#define CC 1536
#define BHq (Bq * Hq)

// ---------------- device scratch ----------------
__device__ float  g_C[NROWS * CC];
__device__ __half g_Qh[BHq * Sq * 128];
__device__ __half g_Kh[BHq * Sq * 128];
__device__ __half g_Vh[BHq * Sq * DEPTHq];
__device__ __half g_attn_h[(size_t)BHq * Sq * Sq];   // raw exp, fp16
__device__ float  g_Zp[2][NTOK * DMq];
__device__ float  g_rowsum[BHq * Sq];
__device__ float  g_attn_fallback[(size_t)BHq * Sq * Sq];

// ---------------- fp16 helpers ----------------
__device__ __forceinline__ uint32_t ph2(float a, float b) {
    __half2 h = __floats2half2_rn(a, b);
    return *reinterpret_cast<uint32_t*>(&h);
}
__device__ __forceinline__ void mma16(float* c, const uint32_t* a, const uint32_t* b) {
    asm volatile(
        "mma.sync.aligned.m16n8k16.row.col.f32.f16.f16.f32 "
        "{%0,%1,%2,%3}, {%4,%5,%6,%7}, {%8,%9}, {%0,%1,%2,%3};"
        : "+f"(c[0]), "+f"(c[1]), "+f"(c[2]), "+f"(c[3])
        : "r"(a[0]), "r"(a[1]), "r"(a[2]), "r"(a[3]),
          "r"(b[0]), "r"(b[1]));
}
__device__ __forceinline__ void stage_f32(uint32_t* rowp, int w, float4 v0, float4 v1) {
    rowp[0 + w] = ph2(v0.x, v0.y);
    rowp[2 + w] = ph2(v0.z, v0.w);
    rowp[4 + w] = ph2(v1.x, v1.y);
    rowp[6 + w] = ph2(v1.z, v1.w);
}
__device__ __forceinline__ void stage_f16(uint32_t* rowp, int w, uint4 u) {
    rowp[0 + w] = u.x;
    rowp[2 + w] = u.y;
    rowp[4 + w] = u.z;
    rowp[6 + w] = u.w;
}
__device__ __forceinline__ uint32_t smem_u32(const void* p) {
    uint32_t a;
    asm("{ .reg .u64 t; cvta.to.shared.u64 t, %1; cvt.u32.u64 %0, t; }" : "=r"(a) : "l"(p));
    return a;
}
__device__ __forceinline__ void cp16(uint32_t dst, const void* src) {
    asm volatile("cp.async.ca.shared.global [%0], [%1], 16;" :: "r"(dst), "l"(src));
}
__device__ __forceinline__ void ldsm4(uint32_t* r, uint32_t addr) {
    asm volatile("ldmatrix.sync.aligned.m8n8.x4.shared.b16 {%0,%1,%2,%3}, [%4];"
                 : "=r"(r[0]), "=r"(r[1]), "=r"(r[2]), "=r"(r[3]) : "r"(addr));
}

// ============================================================
// Kernel 1: proj (R9 fp16 design, unchanged)
// ============================================================
__global__ void __launch_bounds__(256, 2)
proj_gemm_tc(const float* __restrict__ emb, const float* __restrict__ pe,
             const float* __restrict__ Wq, const float* __restrict__ bq,
             const float* __restrict__ Wk, const float* __restrict__ bk,
             const float* __restrict__ Wv, const float* __restrict__ bv) {
    __shared__ __align__(16) uint32_t SA[2][128][8];
    __shared__ __align__(16) uint32_t SB[2][128][8];

    const int m0 = blockIdx.y * 128;
    const int n0 = blockIdx.x * 128;
    const int tid = threadIdx.x;
    const int wid = tid >> 5, lane = tid & 31;
    const int wm = (wid >> 2) * 64, wn = (wid & 3) * 32;
    const int lg = lane >> 2, lt = lane & 3;

    const float* srcA = (m0 < NTOK) ? (emb + (size_t)m0 * DMq)
                                    : (pe + (size_t)(m0 - NTOK) * DMq);
    const float* W    = (n0 < 512) ? Wq : (n0 < 1024 ? Wk : Wv);
    const float* bias = (n0 < 512) ? bq : (n0 < 1024 ? bk : bv);
    const int colbase = n0 & 511;

    const int sm = tid >> 1, w = tid & 1;
    const int kp = tid >> 5, bn_ = (tid & 31) * 4;
    const int slot = (kp < 4) ? 2 * kp : 2 * (kp - 4) + 1;

    float acc[4][4][4];
#pragma unroll
    for (int i = 0; i < 4; i++)
#pragma unroll
        for (int j = 0; j < 4; j++)
#pragma unroll
            for (int r = 0; r < 4; r++) acc[i][j][r] = 0.f;

    const int NIT = DMq / 16;

    {
        const float* ap = srcA + (size_t)sm * DMq + 8 * w;
        stage_f32(&SA[0][sm][0], w, *(const float4*)ap, *(const float4*)(ap + 4));
        const float* b0p = W + (size_t)(2 * kp) * DMq + colbase + bn_;
        const float* b1p = W + (size_t)(2 * kp + 1) * DMq + colbase + bn_;
        float4 r0 = *(const float4*)b0p, r1 = *(const float4*)b1p;
        SB[0][bn_ + 0][slot] = ph2(r0.x, r1.x);
        SB[0][bn_ + 1][slot] = ph2(r0.y, r1.y);
        SB[0][bn_ + 2][slot] = ph2(r0.z, r1.z);
        SB[0][bn_ + 3][slot] = ph2(r0.w, r1.w);
    }
    __syncthreads();

    for (int it = 0; it < NIT; it++) {
        const int st = it & 1;
        float4 a0, a1, r0, r1;
        const bool more = (it + 1 < NIT);
        if (more) {
            int k0 = (it + 1) * 16;
            const float* ap = srcA + (size_t)sm * DMq + k0 + 8 * w;
            a0 = *(const float4*)(ap);
            a1 = *(const float4*)(ap + 4);
            const float* b0p = W + (size_t)(k0 + 2 * kp) * DMq + colbase + bn_;
            const float* b1p = W + (size_t)(k0 + 2 * kp + 1) * DMq + colbase + bn_;
            r0 = *(const float4*)b0p;
            r1 = *(const float4*)b1p;
        }
        {
            uint32_t af[4][4], bf[4][2];
#pragma unroll
            for (int mi = 0; mi < 4; mi++) {
                uint2 lo = *(const uint2*)&SA[st][wm + mi * 16 + lg][2 * lt];
                uint2 hi = *(const uint2*)&SA[st][wm + mi * 16 + 8 + lg][2 * lt];
                af[mi][0] = lo.x; af[mi][1] = hi.x; af[mi][2] = lo.y; af[mi][3] = hi.y;
            }
#pragma unroll
            for (int ni = 0; ni < 4; ni++) {
                uint2 bb = *(const uint2*)&SB[st][wn + ni * 8 + lg][2 * lt];
                bf[ni][0] = bb.x; bf[ni][1] = bb.y;
            }
#pragma unroll
            for (int mi = 0; mi < 4; mi++)
#pragma unroll
                for (int ni = 0; ni < 4; ni++) mma16(acc[mi][ni], af[mi], bf[ni]);
        }
        if (more) {
            stage_f32(&SA[st ^ 1][sm][0], w, a0, a1);
            SB[st ^ 1][bn_ + 0][slot] = ph2(r0.x, r1.x);
            SB[st ^ 1][bn_ + 1][slot] = ph2(r0.y, r1.y);
            SB[st ^ 1][bn_ + 2][slot] = ph2(r0.z, r1.z);
            SB[st ^ 1][bn_ + 3][slot] = ph2(r0.w, r1.w);
        }
        __syncthreads();
    }

#pragma unroll
    for (int mi = 0; mi < 4; mi++) {
        int r0 = m0 + wm + mi * 16 + lg;
#pragma unroll
        for (int ni = 0; ni < 4; ni++) {
            int c0 = n0 + wn + ni * 8 + 2 * lt;
            float bv0 = bias[(c0) & 511], bv1 = bias[(c0 + 1) & 511];
            *reinterpret_cast<float2*>(&g_C[(size_t)r0 * CC + c0]) =
                make_float2(acc[mi][ni][0] + bv0, acc[mi][ni][1] + bv1);
            *reinterpret_cast<float2*>(&g_C[(size_t)(r0 + 8) * CC + c0]) =
                make_float2(acc[mi][ni][2] + bv0, acc[mi][ni][3] + bv1);
        }
    }
}

// ============================================================
// Kernel 2: rearrange — fp16 outputs
// ============================================================
__global__ void rearrange_kernel() {
    int idx = blockIdx.x * blockDim.x + threadIdx.x;
    if (idx >= NTOK * DMq) return;
    int n = idx / DMq;
    int c = idx % DMq;
    int b = n / Sq, s = n % Sq;
    int h = c / DEPTHq, d = c % DEPTHq;

    float Qc = g_C[(size_t)n * CC + c];
    float Qr = g_C[(size_t)(NTOK + n) * CC + c];
    float Kc = g_C[(size_t)n * CC + 512 + c];
    float Kr = g_C[(size_t)(NTOK + n) * CC + 512 + c];
    float Vv = g_C[(size_t)n * CC + 1024 + c];

    size_t base = ((size_t)(b * Hq + h) * Sq + s) * 128;
    g_Qh[base + d]      = __float2half_rn((Qc + Qr) * 0.125f);
    g_Qh[base + 64 + d] = __float2half_rn(Qc * 0.125f);
    g_Kh[base + d]      = __float2half_rn(Kc);
    g_Kh[base + 64 + d] = __float2half_rn(Kr);
    g_Vh[((size_t)(b * Hq + h) * Sq + s) * DEPTHq + d] = __float2half_rn(Vv);
}

__global__ void zero_rowsum() {
    int i = blockIdx.x * 256 + threadIdx.x;
    if (i < BHq * Sq) g_rowsum[i] = 0.f;
}

// ============================================================
// Kernel 3: logits (R10 whole-tile-resident design, unchanged)
// ============================================================
#define ROWB 272
#define LOG_SMEM (2 * 128 * ROWB)

__global__ void __launch_bounds__(128)
logits_gemm_tc() {
    extern __shared__ char dsm[];
    const uint32_t sa = smem_u32(dsm);
    const uint32_t sb = sa + 128 * ROWB;

    const int bh = blockIdx.z;
    const int q0 = blockIdx.y * 128;
    const int t0 = blockIdx.x * 128;
    const __half* Q = g_Qh + (size_t)bh * Sq * 128;
    const __half* K = g_Kh + (size_t)bh * Sq * 128;
    __half* outh = g_attn_h + (size_t)bh * Sq * Sq;

    const int tid = threadIdx.x;
    const int wid = tid >> 5, lane = tid & 31;
    const int wm = (wid >> 1) * 64, wn = (wid & 1) * 64;
    const int lg = lane >> 2, lt = lane & 3;

    {
        const int cr = tid >> 4;
        const int cc = tid & 15;
#pragma unroll
        for (int i = 0; i < 16; i++) {
            int row = i * 8 + cr;
            cp16(sa + row * ROWB + cc * 16, Q + (size_t)(q0 + row) * 128 + cc * 8);
            cp16(sb + row * ROWB + cc * 16, K + (size_t)(t0 + row) * 128 + cc * 8);
        }
        asm volatile("cp.async.commit_group;" ::: "memory");
        asm volatile("cp.async.wait_group 0;" ::: "memory");
    }
    __syncthreads();

    float acc[4][8][4];
#pragma unroll
    for (int i = 0; i < 4; i++)
#pragma unroll
        for (int j = 0; j < 8; j++)
#pragma unroll
            for (int r = 0; r < 4; r++) acc[i][j][r] = 0.f;

    const uint32_t aAddrBase = sa + (uint32_t)(wm + (lane & 15)) * ROWB + ((lane >> 4) & 1) * 16;
    const uint32_t bAddrBase = sb + (uint32_t)(wn + ((lane >> 4) & 1) * 8 + (lane & 7)) * ROWB +
                               ((lane >> 3) & 1) * 16;

#pragma unroll
    for (int c = 0; c < 8; c++) {
        const uint32_t coff = c * 32;
        uint32_t bf[8][2];
#pragma unroll
        for (int np = 0; np < 4; np++) {
            uint32_t r4[4];
            ldsm4(r4, bAddrBase + np * 16 * ROWB + coff);
            bf[2 * np][0] = r4[0];
            bf[2 * np][1] = r4[1];
            bf[2 * np + 1][0] = r4[2];
            bf[2 * np + 1][1] = r4[3];
        }
#pragma unroll
        for (int mi = 0; mi < 4; mi++) {
            uint32_t af[4];
            ldsm4(af, aAddrBase + mi * 16 * ROWB + coff);
#pragma unroll
            for (int ni = 0; ni < 8; ni++) mma16(acc[mi][ni], af, bf[ni]);
        }
    }

#pragma unroll
    for (int mi = 0; mi < 4; mi++) {
        int r0 = q0 + wm + mi * 16 + lg;
        float rs0 = 0.f, rs1 = 0.f;
#pragma unroll
        for (int ni = 0; ni < 8; ni++) {
            int c0 = t0 + wn + ni * 8 + 2 * lt;
            __half2 h01 = __floats2half2_rn(__expf(acc[mi][ni][0]), __expf(acc[mi][ni][1]));
            __half2 h23 = __floats2half2_rn(__expf(acc[mi][ni][2]), __expf(acc[mi][ni][3]));
            *reinterpret_cast<uint32_t*>(&outh[(size_t)r0 * Sq + c0]) =
                *reinterpret_cast<uint32_t*>(&h01);
            *reinterpret_cast<uint32_t*>(&outh[(size_t)(r0 + 8) * Sq + c0]) =
                *reinterpret_cast<uint32_t*>(&h23);
            float2 f01 = __half22float2(h01);
            float2 f23 = __half22float2(h23);
            rs0 += f01.x + f01.y;
            rs1 += f23.x + f23.y;
        }
        rs0 += __shfl_xor_sync(0xffffffffu, rs0, 1);
        rs0 += __shfl_xor_sync(0xffffffffu, rs0, 2);
        rs1 += __shfl_xor_sync(0xffffffffu, rs1, 1);
        rs1 += __shfl_xor_sync(0xffffffffu, rs1, 2);
        if (lt == 0) {
            atomicAdd(&g_rowsum[bh * Sq + r0], rs0);
            atomicAdd(&g_rowsum[bh * Sq + r0 + 8], rs1);
        }
    }
}

// ============================================================
// Kernel 5 (NEW): zv — A via cp.async + ldmatrix, V via slot path.
// grid (Sq/128, 2 ksplit, BHq), 256 thr = 8 warps (4x2), warp 32x32.
// A stage: [128 rows][48B] (32B data + 16B pad; bank-safe, 16B-aligned).
// Normalized fp32 attn written from the landed smem tile.
// ============================================================
#define AROWB 48
#define ZASTG (128 * AROWB)   // 6144 per stage

__global__ void __launch_bounds__(256, 2)
zv_fused_tc(float* __restrict__ attn) {
    __shared__ __align__(16) char  ZA[2 * ZASTG];          // 12 KB
    __shared__ __align__(16) uint32_t SB[2][64][8];        // 4 KB

    const int bh = blockIdx.z;
    const int q0 = blockIdx.x * 128;
    const int ks = blockIdx.y;
    const int b = bh / Hq, h = bh % Hq;
    const __half* Ph = g_attn_h + (size_t)bh * Sq * Sq;
    float* Pout = attn + (size_t)bh * Sq * Sq;
    const __half* V = g_Vh + ((size_t)bh * Sq + ks * 1024) * DEPTHq;
    float* Zp = g_Zp[ks];

    const int tid = threadIdx.x;
    const int wid = tid >> 5, lane = tid & 31;
    const int wm = (wid >> 1) * 32, wn = (wid & 1) * 32;
    const int lg = lane >> 2, lt = lane & 3;

    const uint32_t za = smem_u32(ZA);

    // A staging map: thread -> (row = tid>>1, half = tid&1)
    const int arow = tid >> 1, ahalf = tid & 1;
    const __half* agsrc = Ph + (size_t)(q0 + arow) * Sq + ks * 1024 + ahalf * 8;
    float* aout = Pout + (size_t)(q0 + arow) * Sq + ks * 1024 + ahalf * 8;
    const uint32_t adst = za + arow * AROWB + ahalf * 16;
    const float invs = 1.0f / g_rowsum[bh * Sq + q0 + arow];

    // V staging map (slot path)
    const int kp = tid >> 5, bn_ = (tid & 31) * 2;
    const int slot = (kp < 4) ? 2 * kp : 2 * (kp - 4) + 1;

    // ldmatrix A lane address (chunk-invariant)
    const uint32_t aAddrBase = za + (uint32_t)(wm + (lane & 15)) * AROWB + ((lane >> 4) & 1) * 16;

    float acc[2][4][4];
#pragma unroll
    for (int i = 0; i < 2; i++)
#pragma unroll
        for (int j = 0; j < 4; j++)
#pragma unroll
            for (int r = 0; r < 4; r++) acc[i][j][r] = 0.f;

    const int NIT = 1024 / 16;  // 64

    // prologue: stage 0
    {
        cp16(adst, agsrc);
        asm volatile("cp.async.commit_group;" ::: "memory");
        const __half* vp = V + (size_t)(2 * kp) * DEPTHq + bn_;
        uint32_t x0 = *(const uint32_t*)vp;
        uint32_t x1 = *(const uint32_t*)(vp + DEPTHq);
        SB[0][bn_][slot]     = __byte_perm(x0, x1, 0x5410);
        SB[0][bn_ + 1][slot] = __byte_perm(x0, x1, 0x7632);
        asm volatile("cp.async.wait_group 0;" ::: "memory");
    }
    __syncthreads();

    for (int it = 0; it < NIT; it++) {
        const int st = it & 1;
        const bool more = (it + 1 < NIT);
        uint32_t x0, x1;
        if (more) {
            int k0 = (it + 1) * 16;
            cp16(adst + (st ^ 1) * ZASTG, agsrc + k0);
            asm volatile("cp.async.commit_group;" ::: "memory");
            const __half* vp = V + (size_t)(k0 + 2 * kp) * DEPTHq + bn_;
            x0 = *(const uint32_t*)vp;
            x1 = *(const uint32_t*)(vp + DEPTHq);
        }

        // normalized fp32 attn write from landed smem tile
        {
            uint4 u = *reinterpret_cast<const uint4*>(ZA + st * ZASTG + arow * AROWB + ahalf * 16);
            float2 p0 = __half22float2(*reinterpret_cast<__half2*>(&u.x));
            float2 p1 = __half22float2(*reinterpret_cast<__half2*>(&u.y));
            float2 p2 = __half22float2(*reinterpret_cast<__half2*>(&u.z));
            float2 p3 = __half22float2(*reinterpret_cast<__half2*>(&u.w));
            *(float4*)(aout + it * 16)     = make_float4(p0.x * invs, p0.y * invs, p1.x * invs, p1.y * invs);
            *(float4*)(aout + it * 16 + 4) = make_float4(p2.x * invs, p2.y * invs, p3.x * invs, p3.y * invs);
        }

        // compute: ldmatrix A + slot-LDS V + mma
        {
            uint32_t af[2][4], bf[4][2];
#pragma unroll
            for (int mi = 0; mi < 2; mi++)
                ldsm4(af[mi], aAddrBase + st * ZASTG + mi * 16 * AROWB);
#pragma unroll
            for (int ni = 0; ni < 4; ni++) {
                uint2 bb = *(const uint2*)&SB[st][wn + ni * 8 + lg][2 * lt];
                bf[ni][0] = bb.x; bf[ni][1] = bb.y;
            }
#pragma unroll
            for (int mi = 0; mi < 2; mi++)
#pragma unroll
                for (int ni = 0; ni < 4; ni++) mma16(acc[mi][ni], af[mi], bf[ni]);
        }

        if (more) {
            SB[st ^ 1][bn_][slot]     = __byte_perm(x0, x1, 0x5410);
            SB[st ^ 1][bn_ + 1][slot] = __byte_perm(x0, x1, 0x7632);
            asm volatile("cp.async.wait_group 0;" ::: "memory");
        }
        __syncthreads();
    }

    // epilogue: scale z-partials by 1/rowsum
#pragma unroll
    for (int mi = 0; mi < 2; mi++) {
        int r0 = q0 + wm + mi * 16 + lg;
        float iv0 = 1.0f / g_rowsum[bh * Sq + r0];
        float iv1 = 1.0f / g_rowsum[bh * Sq + r0 + 8];
#pragma unroll
        for (int ni = 0; ni < 4; ni++) {
            int c0 = wn + ni * 8 + 2 * lt;
            size_t base0 = ((size_t)b * Sq + r0) * DMq + h * DEPTHq + c0;
            size_t base1 = ((size_t)b * Sq + r0 + 8) * DMq + h * DEPTHq + c0;
            *reinterpret_cast<float2*>(&Zp[base0]) =
                make_float2(acc[mi][ni][0] * iv0, acc[mi][ni][1] * iv0);
            *reinterpret_cast<float2*>(&Zp[base1]) =
                make_float2(acc[mi][ni][2] * iv1, acc[mi][ni][3] * iv1);
        }
    }
}

// ============================================================
// Kernel 6: out (R9 design, unchanged)
// ============================================================
__global__ void __launch_bounds__(256, 2)
out_gemm_tc(const float* __restrict__ Wo, const float* __restrict__ bo,
            float* __restrict__ out) {
    __shared__ __align__(16) uint32_t SA[2][128][8];
    __shared__ __align__(16) uint32_t SB[2][128][8];

    const int m0 = blockIdx.y * 128;
    const int n0 = blockIdx.x * 128;
    const int tid = threadIdx.x;
    const int wid = tid >> 5, lane = tid & 31;
    const int wm = (wid >> 2) * 64, wn = (wid & 3) * 32;
    const int lg = lane >> 2, lt = lane & 3;

    const int sm = tid >> 1, w = tid & 1;
    const int kp = tid >> 5, bn_ = (tid & 31) * 4;
    const int slot = (kp < 4) ? 2 * kp : 2 * (kp - 4) + 1;

    float acc[4][4][4];
#pragma unroll
    for (int i = 0; i < 4; i++)
#pragma unroll
        for (int j = 0; j < 4; j++)
#pragma unroll
            for (int r = 0; r < 4; r++) acc[i][j][r] = 0.f;

    const int NIT = DMq / 16;

    {
        size_t aoff = (size_t)(m0 + sm) * DMq + 8 * w;
        float4 z0 = *(const float4*)(g_Zp[0] + aoff);
        float4 z1 = *(const float4*)(g_Zp[1] + aoff);
        float4 y0 = *(const float4*)(g_Zp[0] + aoff + 4);
        float4 y1 = *(const float4*)(g_Zp[1] + aoff + 4);
        float4 a0 = make_float4(z0.x + z1.x, z0.y + z1.y, z0.z + z1.z, z0.w + z1.w);
        float4 a1 = make_float4(y0.x + y1.x, y0.y + y1.y, y0.z + y1.z, y0.w + y1.w);
        stage_f32(&SA[0][sm][0], w, a0, a1);
        const float* b0p = Wo + (size_t)(2 * kp) * DMq + n0 + bn_;
        const float* b1p = Wo + (size_t)(2 * kp + 1) * DMq + n0 + bn_;
        float4 r0 = *(const float4*)b0p, r1 = *(const float4*)b1p;
        SB[0][bn_ + 0][slot] = ph2(r0.x, r1.x);
        SB[0][bn_ + 1][slot] = ph2(r0.y, r1.y);
        SB[0][bn_ + 2][slot] = ph2(r0.z, r1.z);
        SB[0][bn_ + 3][slot] = ph2(r0.w, r1.w);
    }
    __syncthreads();

    for (int it = 0; it < NIT; it++) {
        const int st = it & 1;
        float4 a0, a1, r0, r1;
        const bool more = (it + 1 < NIT);
        if (more) {
            int k0 = (it + 1) * 16;
            size_t aoff = (size_t)(m0 + sm) * DMq + k0 + 8 * w;
            float4 z0 = *(const float4*)(g_Zp[0] + aoff);
            float4 z1 = *(const float4*)(g_Zp[1] + aoff);
            float4 y0 = *(const float4*)(g_Zp[0] + aoff + 4);
            float4 y1 = *(const float4*)(g_Zp[1] + aoff + 4);
            a0 = make_float4(z0.x + z1.x, z0.y + z1.y, z0.z + z1.z, z0.w + z1.w);
            a1 = make_float4(y0.x + y1.x, y0.y + y1.y, y0.z + y1.z, y0.w + y1.w);
            const float* b0p = Wo + (size_t)(k0 + 2 * kp) * DMq + n0 + bn_;
            const float* b1p = Wo + (size_t)(k0 + 2 * kp + 1) * DMq + n0 + bn_;
            r0 = *(const float4*)b0p;
            r1 = *(const float4*)b1p;
        }
        {
            uint32_t af[4][4], bf[4][2];
#pragma unroll
            for (int mi = 0; mi < 4; mi++) {
                uint2 lo = *(const uint2*)&SA[st][wm + mi * 16 + lg][2 * lt];
                uint2 hi = *(const uint2*)&SA[st][wm + mi * 16 + 8 + lg][2 * lt];
                af[mi][0] = lo.x; af[mi][1] = hi.x; af[mi][2] = lo.y; af[mi][3] = hi.y;
            }
#pragma unroll
            for (int ni = 0; ni < 4; ni++) {
                uint2 bb = *(const uint2*)&SB[st][wn + ni * 8 + lg][2 * lt];
                bf[ni][0] = bb.x; bf[ni][1] = bb.y;
            }
#pragma unroll
            for (int mi = 0; mi < 4; mi++)
#pragma unroll
                for (int ni = 0; ni < 4; ni++) mma16(acc[mi][ni], af[mi], bf[ni]);
        }
        if (more) {
            stage_f32(&SA[st ^ 1][sm][0], w, a0, a1);
            SB[st ^ 1][bn_ + 0][slot] = ph2(r0.x, r1.x);
            SB[st ^ 1][bn_ + 1][slot] = ph2(r0.y, r1.y);
            SB[st ^ 1][bn_ + 2][slot] = ph2(r0.z, r1.z);
            SB[st ^ 1][bn_ + 3][slot] = ph2(r0.w, r1.w);
        }
        __syncthreads();
    }

#pragma unroll
    for (int mi = 0; mi < 4; mi++) {
        int r0 = m0 + wm + mi * 16 + lg;
#pragma unroll
        for (int ni = 0; ni < 4; ni++) {
            int c0 = n0 + wn + ni * 8 + 2 * lt;
            float bv0 = bo[c0], bv1 = bo[c0 + 1];
            *reinterpret_cast<float2*>(&out[(size_t)r0 * DMq + c0]) =
                make_float2(acc[mi][ni][0] + bv0, acc[mi][ni][1] + bv1);
            *reinterpret_cast<float2*>(&out[(size_t)(r0 + 8) * DMq + c0]) =
                make_float2(acc[mi][ni][2] + bv0, acc[mi][ni][3] + bv1);
        }
    }
}

// ============================================================
// Launch
// ============================================================
extern "C" void kernel_launch(void* const* d_in, const int* in_sizes, int n_in,
                              void* d_out, int out_size) {
    const float* emb = (const float*)d_in[0];
    const float* pe  = (const float*)d_in[1];
    const float* Wq  = (const float*)d_in[2];
    const float* bq  = (const float*)d_in[3];
    const float* Wk  = (const float*)d_in[4];
    const float* bk  = (const float*)d_in[5];
    const float* Wv  = (const float*)d_in[6];
    const float* bv  = (const float*)d_in[7];
    const float* Wo  = (const float*)d_in[8];
    const float* bo  = (const float*)d_in[9];

    float* out = (float*)d_out;

    const long long need = (long long)NTOK * DMq + (long long)BHq * Sq * Sq;
    float* attn;
    if ((long long)out_size >= need) {
        attn = out + (size_t)NTOK * DMq;
    } else {
        float* p = nullptr;
        cudaGetSymbolAddress((void**)&p, g_attn_fallback);
        attn = p;
    }

    cudaFuncSetAttribute(logits_gemm_tc,
                         cudaFuncAttributeMaxDynamicSharedMemorySize, LOG_SMEM);

    {
        dim3 grid(CC / 128, NROWS / 128);
        proj_gemm_tc<<<grid, 256>>>(emb, pe, Wq, bq, Wk, bk, Wv, bv);
    }
    {
        int total = NTOK * DMq;
        rearrange_kernel<<<(total + 255) / 256, 256>>>();
    }
    {
        zero_rowsum<<<(BHq * Sq + 255) / 256, 256>>>();
    }
    {
        dim3 grid(Sq / 128, Sq / 128, BHq);
        logits_gemm_tc<<<grid, 128, LOG_SMEM>>>();
    }
    {
        dim3 grid(Sq / 128, 2, BHq);
        zv_fused_tc<<<grid, 256>>>(attn);
    }
    {
        dim3 grid(DMq / 128, NTOK / 128);
        out_gemm_tc<<<grid, 256>>>(Wo, bo, out);
    }
}

// round 12
// speedup vs baseline: 2.0644x; 1.3318x over previous
#include <cuda_runtime.h>
#include <cuda_fp16.h>
#include <cstdint>

#define Bq 2
#define Sq 2048
#define Hq 8
#define DEPTHq 64
#define DMq 512
#define NTOK (Bq * Sq)
#define NROWS (2 * NTOK)
#define CC 1536
#define BHq (Bq * Hq)

// ---------------- device scratch ----------------
__device__ float  g_C[NROWS * CC];
__device__ __half g_Ah[NROWS * DMq];       // fp16([emb;pe])
__device__ __half g_Wth[CC * DMq];         // fp16([Wq|Wk|Wv]^T): [n][k]
__device__ __half g_Qh[BHq * Sq * 128];
__device__ __half g_Kh[BHq * Sq * 128];
__device__ __half g_Vh[BHq * Sq * DEPTHq];
__device__ __half g_attn_h[(size_t)BHq * Sq * Sq];
__device__ float  g_Zp[2][NTOK * DMq];
__device__ float  g_rowsum[BHq * Sq];
__device__ float  g_attn_fallback[(size_t)BHq * Sq * Sq];

// ---------------- helpers ----------------
__device__ __forceinline__ uint32_t ph2(float a, float b) {
    __half2 h = __floats2half2_rn(a, b);
    return *reinterpret_cast<uint32_t*>(&h);
}
__device__ __forceinline__ void mma16(float* c, const uint32_t* a, const uint32_t* b) {
    asm volatile(
        "mma.sync.aligned.m16n8k16.row.col.f32.f16.f16.f32 "
        "{%0,%1,%2,%3}, {%4,%5,%6,%7}, {%8,%9}, {%0,%1,%2,%3};"
        : "+f"(c[0]), "+f"(c[1]), "+f"(c[2]), "+f"(c[3])
        : "r"(a[0]), "r"(a[1]), "r"(a[2]), "r"(a[3]),
          "r"(b[0]), "r"(b[1]));
}
__device__ __forceinline__ void stage_f32(uint32_t* rowp, int w, float4 v0, float4 v1) {
    rowp[0 + w] = ph2(v0.x, v0.y);
    rowp[2 + w] = ph2(v0.z, v0.w);
    rowp[4 + w] = ph2(v1.x, v1.y);
    rowp[6 + w] = ph2(v1.z, v1.w);
}
__device__ __forceinline__ uint32_t smem_u32(const void* p) {
    uint32_t a;
    asm("{ .reg .u64 t; cvta.to.shared.u64 t, %1; cvt.u32.u64 %0, t; }" : "=r"(a) : "l"(p));
    return a;
}
__device__ __forceinline__ void cp16(uint32_t dst, const void* src) {
    asm volatile("cp.async.ca.shared.global [%0], [%1], 16;" :: "r"(dst), "l"(src));
}
__device__ __forceinline__ void ldsm4(uint32_t* r, uint32_t addr) {
    asm volatile("ldmatrix.sync.aligned.m8n8.x4.shared.b16 {%0,%1,%2,%3}, [%4];"
                 : "=r"(r[0]), "=r"(r[1]), "=r"(r[2]), "=r"(r[3]) : "r"(addr));
}

// ============================================================
// Kernel 0a: convert [emb;pe] -> fp16
// ============================================================
__global__ void convert_A(const float* __restrict__ emb, const float* __restrict__ pe) {
    int idx = blockIdx.x * 256 + threadIdx.x;
    if (idx >= NROWS * DMq) return;
    float v = (idx < NTOK * DMq) ? emb[idx] : pe[idx - NTOK * DMq];
    g_Ah[idx] = __float2half_rn(v);
}

// ============================================================
// Kernel 0b: convert + transpose weights -> g_Wth[n][k] fp16
// 32x32 smem tile transpose; block (32,8), grid (CC/32, DMq/32).
// ============================================================
__global__ void convert_W(const float* __restrict__ Wq, const float* __restrict__ Wk,
                          const float* __restrict__ Wv) {
    __shared__ __half t[32][33];
    const int bn = blockIdx.x * 32;   // n tile
    const int bk = blockIdx.y * 32;   // k tile
    const int tx = threadIdx.x, ty = threadIdx.y;
    const float* W = (bn < 512) ? Wq : (bn < 1024 ? Wk : Wv);
    const int colbase = bn & 511;
#pragma unroll
    for (int i = 0; i < 32; i += 8)
        t[ty + i][tx] = __float2half_rn(W[(size_t)(bk + ty + i) * DMq + colbase + tx]);
    __syncthreads();
#pragma unroll
    for (int i = 0; i < 32; i += 8)
        g_Wth[(size_t)(bn + ty + i) * DMq + bk + tx] = t[tx][ty + i];
}

// ============================================================
// Kernel 1 (NEW): proj via cp.async + ldmatrix, fp16 operands.
// C[8192x1536] = Ah @ Wth^T + bias. 128x128 tile, K=512 in 8
// BK=64 double-buffered stages. 8 warps (2x4) of 64x32.
// Row stride 144B (odd 16B multiple -> ldsm conflict-free).
// ============================================================
#define PROWB 144
#define PSTG (128 * PROWB)             // 18432
#define PROJ_SMEM (4 * PSTG)           // 73728

__global__ void __launch_bounds__(256)
proj_gemm_v2(const float* __restrict__ bq, const float* __restrict__ bk,
             const float* __restrict__ bv) {
    extern __shared__ char dsm[];
    const uint32_t sa = smem_u32(dsm);               // A stages: sa, sa+PSTG
    const uint32_t sb = sa + 2 * PSTG;               // B stages: sb, sb+PSTG

    const int m0 = blockIdx.y * 128;
    const int n0 = blockIdx.x * 128;
    const int tid = threadIdx.x;
    const int wid = tid >> 5, lane = tid & 31;
    const int wm = (wid >> 2) * 64, wn = (wid & 3) * 32;
    const int lg = lane >> 2, lt = lane & 3;

    const float* bias = (n0 < 512) ? bq : (n0 < 1024 ? bk : bv);

    // cp.async map: fidx = tid + i*256, i<4 -> row = fidx>>3, cc = fidx&7
    const int crow = tid >> 3;       // advances by 32 per i
    const int ccc = tid & 7;

    float acc[4][4][4];
#pragma unroll
    for (int i = 0; i < 4; i++)
#pragma unroll
        for (int j = 0; j < 4; j++)
#pragma unroll
            for (int r = 0; r < 4; r++) acc[i][j][r] = 0.f;

    // prologue: stage 0 (k0=0)
    {
#pragma unroll
        for (int i = 0; i < 4; i++) {
            int row = crow + i * 32;
            cp16(sa + row * PROWB + ccc * 16, g_Ah + (size_t)(m0 + row) * DMq + ccc * 8);
            cp16(sb + row * PROWB + ccc * 16, g_Wth + (size_t)(n0 + row) * DMq + ccc * 8);
        }
        asm volatile("cp.async.commit_group;" ::: "memory");
        asm volatile("cp.async.wait_group 0;" ::: "memory");
    }
    __syncthreads();

    const uint32_t aAddrBase = (uint32_t)(wm + (lane & 15)) * PROWB + ((lane >> 4) & 1) * 16;
    const uint32_t bAddrBase = (uint32_t)(wn + ((lane >> 4) & 1) * 8 + (lane & 7)) * PROWB +
                               ((lane >> 3) & 1) * 16;

    const int NST = DMq / 64;  // 8 stages
    for (int s = 0; s < NST; s++) {
        const int st = s & 1;
        const bool more = (s + 1 < NST);
        if (more) {
            int k0 = (s + 1) * 64;
#pragma unroll
            for (int i = 0; i < 4; i++) {
                int row = crow + i * 32;
                cp16(sa + (st ^ 1) * PSTG + row * PROWB + ccc * 16,
                     g_Ah + (size_t)(m0 + row) * DMq + k0 + ccc * 8);
                cp16(sb + (st ^ 1) * PSTG + row * PROWB + ccc * 16,
                     g_Wth + (size_t)(n0 + row) * DMq + k0 + ccc * 8);
            }
            asm volatile("cp.async.commit_group;" ::: "memory");
        }
        // compute current stage: 4 k16 chunks
        const uint32_t sas = sa + st * PSTG;
        const uint32_t sbs = sb + st * PSTG;
#pragma unroll
        for (int c = 0; c < 4; c++) {
            const uint32_t coff = c * 32;
            uint32_t bf[4][2];
#pragma unroll
            for (int np = 0; np < 2; np++) {
                uint32_t r4[4];
                ldsm4(r4, sbs + bAddrBase + np * 16 * PROWB + coff);
                bf[2 * np][0] = r4[0];
                bf[2 * np][1] = r4[1];
                bf[2 * np + 1][0] = r4[2];
                bf[2 * np + 1][1] = r4[3];
            }
#pragma unroll
            for (int mi = 0; mi < 4; mi++) {
                uint32_t af[4];
                ldsm4(af, sas + aAddrBase + mi * 16 * PROWB + coff);
#pragma unroll
                for (int ni = 0; ni < 4; ni++) mma16(acc[mi][ni], af, bf[ni]);
            }
        }
        if (more) asm volatile("cp.async.wait_group 0;" ::: "memory");
        __syncthreads();
    }

#pragma unroll
    for (int mi = 0; mi < 4; mi++) {
        int r0 = m0 + wm + mi * 16 + lg;
#pragma unroll
        for (int ni = 0; ni < 4; ni++) {
            int c0 = n0 + wn + ni * 8 + 2 * lt;
            float bv0 = bias[(c0) & 511], bv1 = bias[(c0 + 1) & 511];
            *reinterpret_cast<float2*>(&g_C[(size_t)r0 * CC + c0]) =
                make_float2(acc[mi][ni][0] + bv0, acc[mi][ni][1] + bv1);
            *reinterpret_cast<float2*>(&g_C[(size_t)(r0 + 8) * CC + c0]) =
                make_float2(acc[mi][ni][2] + bv0, acc[mi][ni][3] + bv1);
        }
    }
}

// ============================================================
// Kernel 2: rearrange — fp16 outputs (unchanged)
// ============================================================
__global__ void rearrange_kernel() {
    int idx = blockIdx.x * blockDim.x + threadIdx.x;
    if (idx >= NTOK * DMq) return;
    int n = idx / DMq;
    int c = idx % DMq;
    int b = n / Sq, s = n % Sq;
    int h = c / DEPTHq, d = c % DEPTHq;

    float Qc = g_C[(size_t)n * CC + c];
    float Qr = g_C[(size_t)(NTOK + n) * CC + c];
    float Kc = g_C[(size_t)n * CC + 512 + c];
    float Kr = g_C[(size_t)(NTOK + n) * CC + 512 + c];
    float Vv = g_C[(size_t)n * CC + 1024 + c];

    size_t base = ((size_t)(b * Hq + h) * Sq + s) * 128;
    g_Qh[base + d]      = __float2half_rn((Qc + Qr) * 0.125f);
    g_Qh[base + 64 + d] = __float2half_rn(Qc * 0.125f);
    g_Kh[base + d]      = __float2half_rn(Kc);
    g_Kh[base + 64 + d] = __float2half_rn(Kr);
    g_Vh[((size_t)(b * Hq + h) * Sq + s) * DEPTHq + d] = __float2half_rn(Vv);
}

__global__ void zero_rowsum() {
    int i = blockIdx.x * 256 + threadIdx.x;
    if (i < BHq * Sq) g_rowsum[i] = 0.f;
}

// ============================================================
// Kernel 3: logits (R10 design, unchanged)
// ============================================================
#define ROWB 272
#define LOG_SMEM (2 * 128 * ROWB)

__global__ void __launch_bounds__(128)
logits_gemm_tc() {
    extern __shared__ char dsm[];
    const uint32_t sa = smem_u32(dsm);
    const uint32_t sb = sa + 128 * ROWB;

    const int bh = blockIdx.z;
    const int q0 = blockIdx.y * 128;
    const int t0 = blockIdx.x * 128;
    const __half* Q = g_Qh + (size_t)bh * Sq * 128;
    const __half* K = g_Kh + (size_t)bh * Sq * 128;
    __half* outh = g_attn_h + (size_t)bh * Sq * Sq;

    const int tid = threadIdx.x;
    const int wid = tid >> 5, lane = tid & 31;
    const int wm = (wid >> 1) * 64, wn = (wid & 1) * 64;
    const int lg = lane >> 2, lt = lane & 3;

    {
        const int cr = tid >> 4;
        const int cc = tid & 15;
#pragma unroll
        for (int i = 0; i < 16; i++) {
            int row = i * 8 + cr;
            cp16(sa + row * ROWB + cc * 16, Q + (size_t)(q0 + row) * 128 + cc * 8);
            cp16(sb + row * ROWB + cc * 16, K + (size_t)(t0 + row) * 128 + cc * 8);
        }
        asm volatile("cp.async.commit_group;" ::: "memory");
        asm volatile("cp.async.wait_group 0;" ::: "memory");
    }
    __syncthreads();

    float acc[4][8][4];
#pragma unroll
    for (int i = 0; i < 4; i++)
#pragma unroll
        for (int j = 0; j < 8; j++)
#pragma unroll
            for (int r = 0; r < 4; r++) acc[i][j][r] = 0.f;

    const uint32_t aAddrBase = sa + (uint32_t)(wm + (lane & 15)) * ROWB + ((lane >> 4) & 1) * 16;
    const uint32_t bAddrBase = sb + (uint32_t)(wn + ((lane >> 4) & 1) * 8 + (lane & 7)) * ROWB +
                               ((lane >> 3) & 1) * 16;

#pragma unroll
    for (int c = 0; c < 8; c++) {
        const uint32_t coff = c * 32;
        uint32_t bf[8][2];
#pragma unroll
        for (int np = 0; np < 4; np++) {
            uint32_t r4[4];
            ldsm4(r4, bAddrBase + np * 16 * ROWB + coff);
            bf[2 * np][0] = r4[0];
            bf[2 * np][1] = r4[1];
            bf[2 * np + 1][0] = r4[2];
            bf[2 * np + 1][1] = r4[3];
        }
#pragma unroll
        for (int mi = 0; mi < 4; mi++) {
            uint32_t af[4];
            ldsm4(af, aAddrBase + mi * 16 * ROWB + coff);
#pragma unroll
            for (int ni = 0; ni < 8; ni++) mma16(acc[mi][ni], af, bf[ni]);
        }
    }

#pragma unroll
    for (int mi = 0; mi < 4; mi++) {
        int r0 = q0 + wm + mi * 16 + lg;
        float rs0 = 0.f, rs1 = 0.f;
#pragma unroll
        for (int ni = 0; ni < 8; ni++) {
            int c0 = t0 + wn + ni * 8 + 2 * lt;
            __half2 h01 = __floats2half2_rn(__expf(acc[mi][ni][0]), __expf(acc[mi][ni][1]));
            __half2 h23 = __floats2half2_rn(__expf(acc[mi][ni][2]), __expf(acc[mi][ni][3]));
            *reinterpret_cast<uint32_t*>(&outh[(size_t)r0 * Sq + c0]) =
                *reinterpret_cast<uint32_t*>(&h01);
            *reinterpret_cast<uint32_t*>(&outh[(size_t)(r0 + 8) * Sq + c0]) =
                *reinterpret_cast<uint32_t*>(&h23);
            float2 f01 = __half22float2(h01);
            float2 f23 = __half22float2(h23);
            rs0 += f01.x + f01.y;
            rs1 += f23.x + f23.y;
        }
        rs0 += __shfl_xor_sync(0xffffffffu, rs0, 1);
        rs0 += __shfl_xor_sync(0xffffffffu, rs0, 2);
        rs1 += __shfl_xor_sync(0xffffffffu, rs1, 1);
        rs1 += __shfl_xor_sync(0xffffffffu, rs1, 2);
        if (lt == 0) {
            atomicAdd(&g_rowsum[bh * Sq + r0], rs0);
            atomicAdd(&g_rowsum[bh * Sq + r0 + 8], rs1);
        }
    }
}

// ============================================================
// Kernel 5: zv (R11 design, unchanged)
// ============================================================
#define AROWB 48
#define ZASTG (128 * AROWB)

__global__ void __launch_bounds__(256, 2)
zv_fused_tc(float* __restrict__ attn) {
    __shared__ __align__(16) char  ZA[2 * ZASTG];
    __shared__ __align__(16) uint32_t SB[2][64][8];

    const int bh = blockIdx.z;
    const int q0 = blockIdx.x * 128;
    const int ks = blockIdx.y;
    const int b = bh / Hq, h = bh % Hq;
    const __half* Ph = g_attn_h + (size_t)bh * Sq * Sq;
    float* Pout = attn + (size_t)bh * Sq * Sq;
    const __half* V = g_Vh + ((size_t)bh * Sq + ks * 1024) * DEPTHq;
    float* Zp = g_Zp[ks];

    const int tid = threadIdx.x;
    const int wid = tid >> 5, lane = tid & 31;
    const int wm = (wid >> 1) * 32, wn = (wid & 1) * 32;
    const int lg = lane >> 2, lt = lane & 3;

    const uint32_t za = smem_u32(ZA);

    const int arow = tid >> 1, ahalf = tid & 1;
    const __half* agsrc = Ph + (size_t)(q0 + arow) * Sq + ks * 1024 + ahalf * 8;
    float* aout = Pout + (size_t)(q0 + arow) * Sq + ks * 1024 + ahalf * 8;
    const uint32_t adst = za + arow * AROWB + ahalf * 16;
    const float invs = 1.0f / g_rowsum[bh * Sq + q0 + arow];

    const int kp = tid >> 5, bn_ = (tid & 31) * 2;
    const int slot = (kp < 4) ? 2 * kp : 2 * (kp - 4) + 1;

    const uint32_t aAddrBase = za + (uint32_t)(wm + (lane & 15)) * AROWB + ((lane >> 4) & 1) * 16;

    float acc[2][4][4];
#pragma unroll
    for (int i = 0; i < 2; i++)
#pragma unroll
        for (int j = 0; j < 4; j++)
#pragma unroll
            for (int r = 0; r < 4; r++) acc[i][j][r] = 0.f;

    const int NIT = 1024 / 16;

    {
        cp16(adst, agsrc);
        asm volatile("cp.async.commit_group;" ::: "memory");
        const __half* vp = V + (size_t)(2 * kp) * DEPTHq + bn_;
        uint32_t x0 = *(const uint32_t*)vp;
        uint32_t x1 = *(const uint32_t*)(vp + DEPTHq);
        SB[0][bn_][slot]     = __byte_perm(x0, x1, 0x5410);
        SB[0][bn_ + 1][slot] = __byte_perm(x0, x1, 0x7632);
        asm volatile("cp.async.wait_group 0;" ::: "memory");
    }
    __syncthreads();

    for (int it = 0; it < NIT; it++) {
        const int st = it & 1;
        const bool more = (it + 1 < NIT);
        uint32_t x0, x1;
        if (more) {
            int k0 = (it + 1) * 16;
            cp16(adst + (st ^ 1) * ZASTG, agsrc + k0);
            asm volatile("cp.async.commit_group;" ::: "memory");
            const __half* vp = V + (size_t)(k0 + 2 * kp) * DEPTHq + bn_;
            x0 = *(const uint32_t*)vp;
            x1 = *(const uint32_t*)(vp + DEPTHq);
        }

        {
            uint4 u = *reinterpret_cast<const uint4*>(ZA + st * ZASTG + arow * AROWB + ahalf * 16);
            float2 p0 = __half22float2(*reinterpret_cast<__half2*>(&u.x));
            float2 p1 = __half22float2(*reinterpret_cast<__half2*>(&u.y));
            float2 p2 = __half22float2(*reinterpret_cast<__half2*>(&u.z));
            float2 p3 = __half22float2(*reinterpret_cast<__half2*>(&u.w));
            *(float4*)(aout + it * 16)     = make_float4(p0.x * invs, p0.y * invs, p1.x * invs, p1.y * invs);
            *(float4*)(aout + it * 16 + 4) = make_float4(p2.x * invs, p2.y * invs, p3.x * invs, p3.y * invs);
        }

        {
            uint32_t af[2][4], bf[4][2];
#pragma unroll
            for (int mi = 0; mi < 2; mi++)
                ldsm4(af[mi], aAddrBase + st * ZASTG + mi * 16 * AROWB);
#pragma unroll
            for (int ni = 0; ni < 4; ni++) {
                uint2 bb = *(const uint2*)&SB[st][wn + ni * 8 + lg][2 * lt];
                bf[ni][0] = bb.x; bf[ni][1] = bb.y;
            }
#pragma unroll
            for (int mi = 0; mi < 2; mi++)
#pragma unroll
                for (int ni = 0; ni < 4; ni++) mma16(acc[mi][ni], af[mi], bf[ni]);
        }

        if (more) {
            SB[st ^ 1][bn_][slot]     = __byte_perm(x0, x1, 0x5410);
            SB[st ^ 1][bn_ + 1][slot] = __byte_perm(x0, x1, 0x7632);
            asm volatile("cp.async.wait_group 0;" ::: "memory");
        }
        __syncthreads();
    }

#pragma unroll
    for (int mi = 0; mi < 2; mi++) {
        int r0 = q0 + wm + mi * 16 + lg;
        float iv0 = 1.0f / g_rowsum[bh * Sq + r0];
        float iv1 = 1.0f / g_rowsum[bh * Sq + r0 + 8];
#pragma unroll
        for (int ni = 0; ni < 4; ni++) {
            int c0 = wn + ni * 8 + 2 * lt;
            size_t base0 = ((size_t)b * Sq + r0) * DMq + h * DEPTHq + c0;
            size_t base1 = ((size_t)b * Sq + r0 + 8) * DMq + h * DEPTHq + c0;
            *reinterpret_cast<float2*>(&Zp[base0]) =
                make_float2(acc[mi][ni][0] * iv0, acc[mi][ni][1] * iv0);
            *reinterpret_cast<float2*>(&Zp[base1]) =
                make_float2(acc[mi][ni][2] * iv1, acc[mi][ni][3] * iv1);
        }
    }
}

// ============================================================
// Kernel 6: out (R9 design, unchanged)
// ============================================================
__global__ void __launch_bounds__(256, 2)
out_gemm_tc(const float* __restrict__ Wo, const float* __restrict__ bo,
            float* __restrict__ out) {
    __shared__ __align__(16) uint32_t SA[2][128][8];
    __shared__ __align__(16) uint32_t SB[2][128][8];

    const int m0 = blockIdx.y * 128;
    const int n0 = blockIdx.x * 128;
    const int tid = threadIdx.x;
    const int wid = tid >> 5, lane = tid & 31;
    const int wm = (wid >> 2) * 64, wn = (wid & 3) * 32;
    const int lg = lane >> 2, lt = lane & 3;

    const int sm = tid >> 1, w = tid & 1;
    const int kp = tid >> 5, bn_ = (tid & 31) * 4;
    const int slot = (kp < 4) ? 2 * kp : 2 * (kp - 4) + 1;

    float acc[4][4][4];
#pragma unroll
    for (int i = 0; i < 4; i++)
#pragma unroll
        for (int j = 0; j < 4; j++)
#pragma unroll
            for (int r = 0; r < 4; r++) acc[i][j][r] = 0.f;

    const int NIT = DMq / 16;

    {
        size_t aoff = (size_t)(m0 + sm) * DMq + 8 * w;
        float4 z0 = *(const float4*)(g_Zp[0] + aoff);
        float4 z1 = *(const float4*)(g_Zp[1] + aoff);
        float4 y0 = *(const float4*)(g_Zp[0] + aoff + 4);
        float4 y1 = *(const float4*)(g_Zp[1] + aoff + 4);
        float4 a0 = make_float4(z0.x + z1.x, z0.y + z1.y, z0.z + z1.z, z0.w + z1.w);
        float4 a1 = make_float4(y0.x + y1.x, y0.y + y1.y, y0.z + y1.z, y0.w + y1.w);
        stage_f32((uint32_t*)&SA[0][sm][0], w, a0, a1);
        const float* b0p = Wo + (size_t)(2 * kp) * DMq + n0 + bn_;
        const float* b1p = Wo + (size_t)(2 * kp + 1) * DMq + n0 + bn_;
        float4 r0 = *(const float4*)b0p, r1 = *(const float4*)b1p;
        SB[0][bn_ + 0][slot] = ph2(r0.x, r1.x);
        SB[0][bn_ + 1][slot] = ph2(r0.y, r1.y);
        SB[0][bn_ + 2][slot] = ph2(r0.z, r1.z);
        SB[0][bn_ + 3][slot] = ph2(r0.w, r1.w);
    }
    __syncthreads();

    for (int it = 0; it < NIT; it++) {
        const int st = it & 1;
        float4 a0, a1, r0, r1;
        const bool more = (it + 1 < NIT);
        if (more) {
            int k0 = (it + 1) * 16;
            size_t aoff = (size_t)(m0 + sm) * DMq + k0 + 8 * w;
            float4 z0 = *(const float4*)(g_Zp[0] + aoff);
            float4 z1 = *(const float4*)(g_Zp[1] + aoff);
            float4 y0 = *(const float4*)(g_Zp[0] + aoff + 4);
            float4 y1 = *(const float4*)(g_Zp[1] + aoff + 4);
            a0 = make_float4(z0.x + z1.x, z0.y + z1.y, z0.z + z1.z, z0.w + z1.w);
            a1 = make_float4(y0.x + y1.x, y0.y + y1.y, y0.z + y1.z, y0.w + y1.w);
            const float* b0p = Wo + (size_t)(k0 + 2 * kp) * DMq + n0 + bn_;
            const float* b1p = Wo + (size_t)(k0 + 2 * kp + 1) * DMq + n0 + bn_;
            r0 = *(const float4*)b0p;
            r1 = *(const float4*)b1p;
        }
        {
            uint32_t af[4][4], bf[4][2];
#pragma unroll
            for (int mi = 0; mi < 4; mi++) {
                uint2 lo = *(const uint2*)&SA[st][wm + mi * 16 + lg][2 * lt];
                uint2 hi = *(const uint2*)&SA[st][wm + mi * 16 + 8 + lg][2 * lt];
                af[mi][0] = lo.x; af[mi][1] = hi.x; af[mi][2] = lo.y; af[mi][3] = hi.y;
            }
#pragma unroll
            for (int ni = 0; ni < 4; ni++) {
                uint2 bb = *(const uint2*)&SB[st][wn + ni * 8 + lg][2 * lt];
                bf[ni][0] = bb.x; bf[ni][1] = bb.y;
            }
#pragma unroll
            for (int mi = 0; mi < 4; mi++)
#pragma unroll
                for (int ni = 0; ni < 4; ni++) mma16(acc[mi][ni], af[mi], bf[ni]);
        }
        if (more) {
            stage_f32((uint32_t*)&SA[st ^ 1][sm][0], w, a0, a1);
            SB[st ^ 1][bn_ + 0][slot] = ph2(r0.x, r1.x);
            SB[st ^ 1][bn_ + 1][slot] = ph2(r0.y, r1.y);
            SB[st ^ 1][bn_ + 2][slot] = ph2(r0.z, r1.z);
            SB[st ^ 1][bn_ + 3][slot] = ph2(r0.w, r1.w);
        }
        __syncthreads();
    }

#pragma unroll
    for (int mi = 0; mi < 4; mi++) {
        int r0 = m0 + wm + mi * 16 + lg;
#pragma unroll
        for (int ni = 0; ni < 4; ni++) {
            int c0 = n0 + wn + ni * 8 + 2 * lt;
            float bv0 = bo[c0], bv1 = bo[c0 + 1];
            *reinterpret_cast<float2*>(&out[(size_t)r0 * DMq + c0]) =
                make_float2(acc[mi][ni][0] + bv0, acc[mi][ni][1] + bv1);
            *reinterpret_cast<float2*>(&out[(size_t)(r0 + 8) * DMq + c0]) =
                make_float2(acc[mi][ni][2] + bv0, acc[mi][ni][3] + bv1);
        }
    }
}

// ============================================================
// Launch
// ============================================================
extern "C" void kernel_launch(void* const* d_in, const int* in_sizes, int n_in,
                              void* d_out, int out_size) {
    const float* emb = (const float*)d_in[0];
    const float* pe  = (const float*)d_in[1];
    const float* Wq  = (const float*)d_in[2];
    const float* bq  = (const float*)d_in[3];
    const float* Wk  = (const float*)d_in[4];
    const float* bk  = (const float*)d_in[5];
    const float* Wv  = (const float*)d_in[6];
    const float* bv  = (const float*)d_in[7];
    const float* Wo  = (const float*)d_in[8];
    const float* bo  = (const float*)d_in[9];

    float* out = (float*)d_out;

    const long long need = (long long)NTOK * DMq + (long long)BHq * Sq * Sq;
    float* attn;
    if ((long long)out_size >= need) {
        attn = out + (size_t)NTOK * DMq;
    } else {
        float* p = nullptr;
        cudaGetSymbolAddress((void**)&p, g_attn_fallback);
        attn = p;
    }

    cudaFuncSetAttribute(logits_gemm_tc,
                         cudaFuncAttributeMaxDynamicSharedMemorySize, LOG_SMEM);
    cudaFuncSetAttribute(proj_gemm_v2,
                         cudaFuncAttributeMaxDynamicSharedMemorySize, PROJ_SMEM);

    {
        convert_A<<<(NROWS * DMq + 255) / 256, 256>>>(emb, pe);
    }
    {
        dim3 grid(CC / 32, DMq / 32);
        convert_W<<<grid, dim3(32, 8)>>>(Wq, Wk, Wv);
    }
    {
        dim3 grid(CC / 128, NROWS / 128);
        proj_gemm_v2<<<grid, 256, PROJ_SMEM>>>(bq, bk, bv);
    }
    {
        int total = NTOK * DMq;
        rearrange_kernel<<<(total + 255) / 256, 256>>>();
    }
    {
        zero_rowsum<<<(BHq * Sq + 255) / 256, 256>>>();
    }
    {
        dim3 grid(Sq / 128, Sq / 128, BHq);
        logits_gemm_tc<<<grid, 128, LOG_SMEM>>>();
    }
    {
        dim3 grid(Sq / 128, 2, BHq);
        zv_fused_tc<<<grid, 256>>>(attn);
    }
    {
        dim3 grid(DMq / 128, NTOK / 128);
        out_gemm_tc<<<grid, 256>>>(Wo, bo, out);
    }
}

// round 13
// speedup vs baseline: 2.3164x; 1.1221x over previous
#include <cuda_runtime.h>
#include <cuda_fp16.h>
#include <cstdint>

#define Bq 2
#define Sq 2048
#define Hq 8
#define DEPTHq 64
#define DMq 512
#define NTOK (Bq * Sq)
#define NROWS (2 * NTOK)
#define CC 1536
#define BHq (Bq * Hq)

// ---------------- device scratch ----------------
__device__ float  g_C[NROWS * CC];
__device__ __half g_Ah[NROWS * DMq];
__device__ __half g_Wth[CC * DMq];         // fp16([Wq|Wk|Wv]^T)
__device__ __half g_Woth[DMq * DMq];       // fp16(Wo^T)
__device__ __half g_Qh[BHq * Sq * 128];
__device__ __half g_Kh[BHq * Sq * 128];
__device__ __half g_Vh[BHq * Sq * DEPTHq];
__device__ __half g_attn_h[(size_t)BHq * Sq * Sq];
__device__ __half g_Zh[NTOK * DMq];        // z, fp16
__device__ float  g_rowsum[BHq * Sq];
__device__ float  g_attn_fallback[(size_t)BHq * Sq * Sq];

// ---------------- helpers ----------------
__device__ __forceinline__ uint32_t ph2(float a, float b) {
    __half2 h = __floats2half2_rn(a, b);
    return *reinterpret_cast<uint32_t*>(&h);
}
__device__ __forceinline__ void mma16(float* c, const uint32_t* a, const uint32_t* b) {
    asm volatile(
        "mma.sync.aligned.m16n8k16.row.col.f32.f16.f16.f32 "
        "{%0,%1,%2,%3}, {%4,%5,%6,%7}, {%8,%9}, {%0,%1,%2,%3};"
        : "+f"(c[0]), "+f"(c[1]), "+f"(c[2]), "+f"(c[3])
        : "r"(a[0]), "r"(a[1]), "r"(a[2]), "r"(a[3]),
          "r"(b[0]), "r"(b[1]));
}
__device__ __forceinline__ uint32_t smem_u32(const void* p) {
    uint32_t a;
    asm("{ .reg .u64 t; cvta.to.shared.u64 t, %1; cvt.u32.u64 %0, t; }" : "=r"(a) : "l"(p));
    return a;
}
__device__ __forceinline__ void cp16(uint32_t dst, const void* src) {
    asm volatile("cp.async.ca.shared.global [%0], [%1], 16;" :: "r"(dst), "l"(src));
}
__device__ __forceinline__ void ldsm4(uint32_t* r, uint32_t addr) {
    asm volatile("ldmatrix.sync.aligned.m8n8.x4.shared.b16 {%0,%1,%2,%3}, [%4];"
                 : "=r"(r[0]), "=r"(r[1]), "=r"(r[2]), "=r"(r[3]) : "r"(addr));
}

// ============================================================
// Kernel 0a: convert [emb;pe] -> fp16
// ============================================================
__global__ void convert_A(const float* __restrict__ emb, const float* __restrict__ pe) {
    int idx = blockIdx.x * 256 + threadIdx.x;
    if (idx >= NROWS * DMq) return;
    float v = (idx < NTOK * DMq) ? emb[idx] : pe[idx - NTOK * DMq];
    g_Ah[idx] = __float2half_rn(v);
}

// ============================================================
// Kernel 0b: convert + transpose QKV weights -> g_Wth[n][k]
// ============================================================
__global__ void convert_W(const float* __restrict__ Wq, const float* __restrict__ Wk,
                          const float* __restrict__ Wv) {
    __shared__ __half t[32][33];
    const int bn = blockIdx.x * 32;
    const int bk = blockIdx.y * 32;
    const int tx = threadIdx.x, ty = threadIdx.y;
    const float* W = (bn < 512) ? Wq : (bn < 1024 ? Wk : Wv);
    const int colbase = bn & 511;
#pragma unroll
    for (int i = 0; i < 32; i += 8)
        t[ty + i][tx] = __float2half_rn(W[(size_t)(bk + ty + i) * DMq + colbase + tx]);
    __syncthreads();
#pragma unroll
    for (int i = 0; i < 32; i += 8)
        g_Wth[(size_t)(bn + ty + i) * DMq + bk + tx] = t[tx][ty + i];
}

// ============================================================
// Kernel 0c: convert + transpose Wo -> g_Woth[n][k]
// ============================================================
__global__ void convert_Wo(const float* __restrict__ Wo) {
    __shared__ __half t[32][33];
    const int bn = blockIdx.x * 32;
    const int bk = blockIdx.y * 32;
    const int tx = threadIdx.x, ty = threadIdx.y;
#pragma unroll
    for (int i = 0; i < 32; i += 8)
        t[ty + i][tx] = __float2half_rn(Wo[(size_t)(bk + ty + i) * DMq + bn + tx]);
    __syncthreads();
#pragma unroll
    for (int i = 0; i < 32; i += 8)
        g_Woth[(size_t)(bn + ty + i) * DMq + bk + tx] = t[tx][ty + i];
}

// ============================================================
// Shared GEMM template constants
// ============================================================
#define PROWB 144
#define PSTG (128 * PROWB)
#define PROJ_SMEM (4 * PSTG)

// ============================================================
// Kernel 1: proj via cp.async + ldmatrix (R12 design)
// ============================================================
__global__ void __launch_bounds__(256)
proj_gemm_v2(const float* __restrict__ bq, const float* __restrict__ bk,
             const float* __restrict__ bv) {
    extern __shared__ char dsm[];
    const uint32_t sa = smem_u32(dsm);
    const uint32_t sb = sa + 2 * PSTG;

    const int m0 = blockIdx.y * 128;
    const int n0 = blockIdx.x * 128;
    const int tid = threadIdx.x;
    const int wid = tid >> 5, lane = tid & 31;
    const int wm = (wid >> 2) * 64, wn = (wid & 3) * 32;
    const int lg = lane >> 2, lt = lane & 3;

    const float* bias = (n0 < 512) ? bq : (n0 < 1024 ? bk : bv);

    const int crow = tid >> 3;
    const int ccc = tid & 7;

    float acc[4][4][4];
#pragma unroll
    for (int i = 0; i < 4; i++)
#pragma unroll
        for (int j = 0; j < 4; j++)
#pragma unroll
            for (int r = 0; r < 4; r++) acc[i][j][r] = 0.f;

    {
#pragma unroll
        for (int i = 0; i < 4; i++) {
            int row = crow + i * 32;
            cp16(sa + row * PROWB + ccc * 16, g_Ah + (size_t)(m0 + row) * DMq + ccc * 8);
            cp16(sb + row * PROWB + ccc * 16, g_Wth + (size_t)(n0 + row) * DMq + ccc * 8);
        }
        asm volatile("cp.async.commit_group;" ::: "memory");
        asm volatile("cp.async.wait_group 0;" ::: "memory");
    }
    __syncthreads();

    const uint32_t aAddrBase = (uint32_t)(wm + (lane & 15)) * PROWB + ((lane >> 4) & 1) * 16;
    const uint32_t bAddrBase = (uint32_t)(wn + ((lane >> 4) & 1) * 8 + (lane & 7)) * PROWB +
                               ((lane >> 3) & 1) * 16;

    const int NST = DMq / 64;
    for (int s = 0; s < NST; s++) {
        const int st = s & 1;
        const bool more = (s + 1 < NST);
        if (more) {
            int k0 = (s + 1) * 64;
#pragma unroll
            for (int i = 0; i < 4; i++) {
                int row = crow + i * 32;
                cp16(sa + (st ^ 1) * PSTG + row * PROWB + ccc * 16,
                     g_Ah + (size_t)(m0 + row) * DMq + k0 + ccc * 8);
                cp16(sb + (st ^ 1) * PSTG + row * PROWB + ccc * 16,
                     g_Wth + (size_t)(n0 + row) * DMq + k0 + ccc * 8);
            }
            asm volatile("cp.async.commit_group;" ::: "memory");
        }
        const uint32_t sas = sa + st * PSTG;
        const uint32_t sbs = sb + st * PSTG;
#pragma unroll
        for (int c = 0; c < 4; c++) {
            const uint32_t coff = c * 32;
            uint32_t bf[4][2];
#pragma unroll
            for (int np = 0; np < 2; np++) {
                uint32_t r4[4];
                ldsm4(r4, sbs + bAddrBase + np * 16 * PROWB + coff);
                bf[2 * np][0] = r4[0];
                bf[2 * np][1] = r4[1];
                bf[2 * np + 1][0] = r4[2];
                bf[2 * np + 1][1] = r4[3];
            }
#pragma unroll
            for (int mi = 0; mi < 4; mi++) {
                uint32_t af[4];
                ldsm4(af, sas + aAddrBase + mi * 16 * PROWB + coff);
#pragma unroll
                for (int ni = 0; ni < 4; ni++) mma16(acc[mi][ni], af, bf[ni]);
            }
        }
        if (more) asm volatile("cp.async.wait_group 0;" ::: "memory");
        __syncthreads();
    }

#pragma unroll
    for (int mi = 0; mi < 4; mi++) {
        int r0 = m0 + wm + mi * 16 + lg;
#pragma unroll
        for (int ni = 0; ni < 4; ni++) {
            int c0 = n0 + wn + ni * 8 + 2 * lt;
            float bv0 = bias[(c0) & 511], bv1 = bias[(c0 + 1) & 511];
            *reinterpret_cast<float2*>(&g_C[(size_t)r0 * CC + c0]) =
                make_float2(acc[mi][ni][0] + bv0, acc[mi][ni][1] + bv1);
            *reinterpret_cast<float2*>(&g_C[(size_t)(r0 + 8) * CC + c0]) =
                make_float2(acc[mi][ni][2] + bv0, acc[mi][ni][3] + bv1);
        }
    }
}

// ============================================================
// Kernel 2: rearrange (unchanged)
// ============================================================
__global__ void rearrange_kernel() {
    int idx = blockIdx.x * blockDim.x + threadIdx.x;
    if (idx >= NTOK * DMq) return;
    int n = idx / DMq;
    int c = idx % DMq;
    int b = n / Sq, s = n % Sq;
    int h = c / DEPTHq, d = c % DEPTHq;

    float Qc = g_C[(size_t)n * CC + c];
    float Qr = g_C[(size_t)(NTOK + n) * CC + c];
    float Kc = g_C[(size_t)n * CC + 512 + c];
    float Kr = g_C[(size_t)(NTOK + n) * CC + 512 + c];
    float Vv = g_C[(size_t)n * CC + 1024 + c];

    size_t base = ((size_t)(b * Hq + h) * Sq + s) * 128;
    g_Qh[base + d]      = __float2half_rn((Qc + Qr) * 0.125f);
    g_Qh[base + 64 + d] = __float2half_rn(Qc * 0.125f);
    g_Kh[base + d]      = __float2half_rn(Kc);
    g_Kh[base + 64 + d] = __float2half_rn(Kr);
    g_Vh[((size_t)(b * Hq + h) * Sq + s) * DEPTHq + d] = __float2half_rn(Vv);
}

__global__ void zero_rowsum() {
    int i = blockIdx.x * 256 + threadIdx.x;
    if (i < BHq * Sq) g_rowsum[i] = 0.f;
}

// ============================================================
// Kernel 3: logits (R10 design, unchanged)
// ============================================================
#define ROWB 272
#define LOG_SMEM (2 * 128 * ROWB)

__global__ void __launch_bounds__(128)
logits_gemm_tc() {
    extern __shared__ char dsm[];
    const uint32_t sa = smem_u32(dsm);
    const uint32_t sb = sa + 128 * ROWB;

    const int bh = blockIdx.z;
    const int q0 = blockIdx.y * 128;
    const int t0 = blockIdx.x * 128;
    const __half* Q = g_Qh + (size_t)bh * Sq * 128;
    const __half* K = g_Kh + (size_t)bh * Sq * 128;
    __half* outh = g_attn_h + (size_t)bh * Sq * Sq;

    const int tid = threadIdx.x;
    const int wid = tid >> 5, lane = tid & 31;
    const int wm = (wid >> 1) * 64, wn = (wid & 1) * 64;
    const int lg = lane >> 2, lt = lane & 3;

    {
        const int cr = tid >> 4;
        const int cc = tid & 15;
#pragma unroll
        for (int i = 0; i < 16; i++) {
            int row = i * 8 + cr;
            cp16(sa + row * ROWB + cc * 16, Q + (size_t)(q0 + row) * 128 + cc * 8);
            cp16(sb + row * ROWB + cc * 16, K + (size_t)(t0 + row) * 128 + cc * 8);
        }
        asm volatile("cp.async.commit_group;" ::: "memory");
        asm volatile("cp.async.wait_group 0;" ::: "memory");
    }
    __syncthreads();

    float acc[4][8][4];
#pragma unroll
    for (int i = 0; i < 4; i++)
#pragma unroll
        for (int j = 0; j < 8; j++)
#pragma unroll
            for (int r = 0; r < 4; r++) acc[i][j][r] = 0.f;

    const uint32_t aAddrBase = sa + (uint32_t)(wm + (lane & 15)) * ROWB + ((lane >> 4) & 1) * 16;
    const uint32_t bAddrBase = sb + (uint32_t)(wn + ((lane >> 4) & 1) * 8 + (lane & 7)) * ROWB +
                               ((lane >> 3) & 1) * 16;

#pragma unroll
    for (int c = 0; c < 8; c++) {
        const uint32_t coff = c * 32;
        uint32_t bf[8][2];
#pragma unroll
        for (int np = 0; np < 4; np++) {
            uint32_t r4[4];
            ldsm4(r4, bAddrBase + np * 16 * ROWB + coff);
            bf[2 * np][0] = r4[0];
            bf[2 * np][1] = r4[1];
            bf[2 * np + 1][0] = r4[2];
            bf[2 * np + 1][1] = r4[3];
        }
#pragma unroll
        for (int mi = 0; mi < 4; mi++) {
            uint32_t af[4];
            ldsm4(af, aAddrBase + mi * 16 * ROWB + coff);
#pragma unroll
            for (int ni = 0; ni < 8; ni++) mma16(acc[mi][ni], af, bf[ni]);
        }
    }

#pragma unroll
    for (int mi = 0; mi < 4; mi++) {
        int r0 = q0 + wm + mi * 16 + lg;
        float rs0 = 0.f, rs1 = 0.f;
#pragma unroll
        for (int ni = 0; ni < 8; ni++) {
            int c0 = t0 + wn + ni * 8 + 2 * lt;
            __half2 h01 = __floats2half2_rn(__expf(acc[mi][ni][0]), __expf(acc[mi][ni][1]));
            __half2 h23 = __floats2half2_rn(__expf(acc[mi][ni][2]), __expf(acc[mi][ni][3]));
            *reinterpret_cast<uint32_t*>(&outh[(size_t)r0 * Sq + c0]) =
                *reinterpret_cast<uint32_t*>(&h01);
            *reinterpret_cast<uint32_t*>(&outh[(size_t)(r0 + 8) * Sq + c0]) =
                *reinterpret_cast<uint32_t*>(&h23);
            float2 f01 = __half22float2(h01);
            float2 f23 = __half22float2(h23);
            rs0 += f01.x + f01.y;
            rs1 += f23.x + f23.y;
        }
        rs0 += __shfl_xor_sync(0xffffffffu, rs0, 1);
        rs0 += __shfl_xor_sync(0xffffffffu, rs0, 2);
        rs1 += __shfl_xor_sync(0xffffffffu, rs1, 1);
        rs1 += __shfl_xor_sync(0xffffffffu, rs1, 2);
        if (lt == 0) {
            atomicAdd(&g_rowsum[bh * Sq + r0], rs0);
            atomicAdd(&g_rowsum[bh * Sq + r0 + 8], rs1);
        }
    }
}

// ============================================================
// Kernel 5: zv — full K per CTA (no ksplit), z written fp16.
// grid (Sq/128, BHq) = 256 CTAs, 256 thr, warp 32x32.
// ============================================================
#define AROWB 48
#define ZASTG (128 * AROWB)

__global__ void __launch_bounds__(256, 2)
zv_fused_tc(float* __restrict__ attn) {
    __shared__ __align__(16) char  ZA[2 * ZASTG];
    __shared__ __align__(16) uint32_t SB[2][64][8];

    const int bh = blockIdx.y;
    const int q0 = blockIdx.x * 128;
    const int b = bh / Hq, h = bh % Hq;
    const __half* Ph = g_attn_h + (size_t)bh * Sq * Sq;
    float* Pout = attn + (size_t)bh * Sq * Sq;
    const __half* V = g_Vh + (size_t)bh * Sq * DEPTHq;

    const int tid = threadIdx.x;
    const int wid = tid >> 5, lane = tid & 31;
    const int wm = (wid >> 1) * 32, wn = (wid & 1) * 32;
    const int lg = lane >> 2, lt = lane & 3;

    const uint32_t za = smem_u32(ZA);

    const int arow = tid >> 1, ahalf = tid & 1;
    const __half* agsrc = Ph + (size_t)(q0 + arow) * Sq + ahalf * 8;
    float* aout = Pout + (size_t)(q0 + arow) * Sq + ahalf * 8;
    const uint32_t adst = za + arow * AROWB + ahalf * 16;
    const float invs = 1.0f / g_rowsum[bh * Sq + q0 + arow];

    const int kp = tid >> 5, bn_ = (tid & 31) * 2;
    const int slot = (kp < 4) ? 2 * kp : 2 * (kp - 4) + 1;

    const uint32_t aAddrBase = za + (uint32_t)(wm + (lane & 15)) * AROWB + ((lane >> 4) & 1) * 16;

    float acc[2][4][4];
#pragma unroll
    for (int i = 0; i < 2; i++)
#pragma unroll
        for (int j = 0; j < 4; j++)
#pragma unroll
            for (int r = 0; r < 4; r++) acc[i][j][r] = 0.f;

    const int NIT = Sq / 16;  // 128

    {
        cp16(adst, agsrc);
        asm volatile("cp.async.commit_group;" ::: "memory");
        const __half* vp = V + (size_t)(2 * kp) * DEPTHq + bn_;
        uint32_t x0 = *(const uint32_t*)vp;
        uint32_t x1 = *(const uint32_t*)(vp + DEPTHq);
        SB[0][bn_][slot]     = __byte_perm(x0, x1, 0x5410);
        SB[0][bn_ + 1][slot] = __byte_perm(x0, x1, 0x7632);
        asm volatile("cp.async.wait_group 0;" ::: "memory");
    }
    __syncthreads();

    for (int it = 0; it < NIT; it++) {
        const int st = it & 1;
        const bool more = (it + 1 < NIT);
        uint32_t x0, x1;
        if (more) {
            int k0 = (it + 1) * 16;
            cp16(adst + (st ^ 1) * ZASTG, agsrc + k0);
            asm volatile("cp.async.commit_group;" ::: "memory");
            const __half* vp = V + (size_t)(k0 + 2 * kp) * DEPTHq + bn_;
            x0 = *(const uint32_t*)vp;
            x1 = *(const uint32_t*)(vp + DEPTHq);
        }

        {
            uint4 u = *reinterpret_cast<const uint4*>(ZA + st * ZASTG + arow * AROWB + ahalf * 16);
            float2 p0 = __half22float2(*reinterpret_cast<__half2*>(&u.x));
            float2 p1 = __half22float2(*reinterpret_cast<__half2*>(&u.y));
            float2 p2 = __half22float2(*reinterpret_cast<__half2*>(&u.z));
            float2 p3 = __half22float2(*reinterpret_cast<__half2*>(&u.w));
            *(float4*)(aout + it * 16)     = make_float4(p0.x * invs, p0.y * invs, p1.x * invs, p1.y * invs);
            *(float4*)(aout + it * 16 + 4) = make_float4(p2.x * invs, p2.y * invs, p3.x * invs, p3.y * invs);
        }

        {
            uint32_t af[2][4], bf[4][2];
#pragma unroll
            for (int mi = 0; mi < 2; mi++)
                ldsm4(af[mi], aAddrBase + st * ZASTG + mi * 16 * AROWB);
#pragma unroll
            for (int ni = 0; ni < 4; ni++) {
                uint2 bb = *(const uint2*)&SB[st][wn + ni * 8 + lg][2 * lt];
                bf[ni][0] = bb.x; bf[ni][1] = bb.y;
            }
#pragma unroll
            for (int mi = 0; mi < 2; mi++)
#pragma unroll
                for (int ni = 0; ni < 4; ni++) mma16(acc[mi][ni], af[mi], bf[ni]);
        }

        if (more) {
            SB[st ^ 1][bn_][slot]     = __byte_perm(x0, x1, 0x5410);
            SB[st ^ 1][bn_ + 1][slot] = __byte_perm(x0, x1, 0x7632);
            asm volatile("cp.async.wait_group 0;" ::: "memory");
        }
        __syncthreads();
    }

    // epilogue: scale by 1/rowsum, write z as fp16
#pragma unroll
    for (int mi = 0; mi < 2; mi++) {
        int r0 = q0 + wm + mi * 16 + lg;
        float iv0 = 1.0f / g_rowsum[bh * Sq + r0];
        float iv1 = 1.0f / g_rowsum[bh * Sq + r0 + 8];
#pragma unroll
        for (int ni = 0; ni < 4; ni++) {
            int c0 = wn + ni * 8 + 2 * lt;
            size_t base0 = ((size_t)b * Sq + r0) * DMq + h * DEPTHq + c0;
            size_t base1 = ((size_t)b * Sq + r0 + 8) * DMq + h * DEPTHq + c0;
            *reinterpret_cast<uint32_t*>(&g_Zh[base0]) =
                ph2(acc[mi][ni][0] * iv0, acc[mi][ni][1] * iv0);
            *reinterpret_cast<uint32_t*>(&g_Zh[base1]) =
                ph2(acc[mi][ni][2] * iv1, acc[mi][ni][3] * iv1);
        }
    }
}

// ============================================================
// Kernel 6 (NEW): out = Zh @ Woth^T + bo via proj_v2 template.
// grid (DMq/128=4, NTOK/128=32).
// ============================================================
__global__ void __launch_bounds__(256)
out_gemm_v2(const float* __restrict__ bo, float* __restrict__ out) {
    extern __shared__ char dsm[];
    const uint32_t sa = smem_u32(dsm);
    const uint32_t sb = sa + 2 * PSTG;

    const int m0 = blockIdx.y * 128;
    const int n0 = blockIdx.x * 128;
    const int tid = threadIdx.x;
    const int wid = tid >> 5, lane = tid & 31;
    const int wm = (wid >> 2) * 64, wn = (wid & 3) * 32;
    const int lg = lane >> 2, lt = lane & 3;

    const int crow = tid >> 3;
    const int ccc = tid & 7;

    float acc[4][4][4];
#pragma unroll
    for (int i = 0; i < 4; i++)
#pragma unroll
        for (int j = 0; j < 4; j++)
#pragma unroll
            for (int r = 0; r < 4; r++) acc[i][j][r] = 0.f;

    {
#pragma unroll
        for (int i = 0; i < 4; i++) {
            int row = crow + i * 32;
            cp16(sa + row * PROWB + ccc * 16, g_Zh + (size_t)(m0 + row) * DMq + ccc * 8);
            cp16(sb + row * PROWB + ccc * 16, g_Woth + (size_t)(n0 + row) * DMq + ccc * 8);
        }
        asm volatile("cp.async.commit_group;" ::: "memory");
        asm volatile("cp.async.wait_group 0;" ::: "memory");
    }
    __syncthreads();

    const uint32_t aAddrBase = (uint32_t)(wm + (lane & 15)) * PROWB + ((lane >> 4) & 1) * 16;
    const uint32_t bAddrBase = (uint32_t)(wn + ((lane >> 4) & 1) * 8 + (lane & 7)) * PROWB +
                               ((lane >> 3) & 1) * 16;

    const int NST = DMq / 64;
    for (int s = 0; s < NST; s++) {
        const int st = s & 1;
        const bool more = (s + 1 < NST);
        if (more) {
            int k0 = (s + 1) * 64;
#pragma unroll
            for (int i = 0; i < 4; i++) {
                int row = crow + i * 32;
                cp16(sa + (st ^ 1) * PSTG + row * PROWB + ccc * 16,
                     g_Zh + (size_t)(m0 + row) * DMq + k0 + ccc * 8);
                cp16(sb + (st ^ 1) * PSTG + row * PROWB + ccc * 16,
                     g_Woth + (size_t)(n0 + row) * DMq + k0 + ccc * 8);
            }
            asm volatile("cp.async.commit_group;" ::: "memory");
        }
        const uint32_t sas = sa + st * PSTG;
        const uint32_t sbs = sb + st * PSTG;
#pragma unroll
        for (int c = 0; c < 4; c++) {
            const uint32_t coff = c * 32;
            uint32_t bf[4][2];
#pragma unroll
            for (int np = 0; np < 2; np++) {
                uint32_t r4[4];
                ldsm4(r4, sbs + bAddrBase + np * 16 * PROWB + coff);
                bf[2 * np][0] = r4[0];
                bf[2 * np][1] = r4[1];
                bf[2 * np + 1][0] = r4[2];
                bf[2 * np + 1][1] = r4[3];
            }
#pragma unroll
            for (int mi = 0; mi < 4; mi++) {
                uint32_t af[4];
                ldsm4(af, sas + aAddrBase + mi * 16 * PROWB + coff);
#pragma unroll
                for (int ni = 0; ni < 4; ni++) mma16(acc[mi][ni], af, bf[ni]);
            }
        }
        if (more) asm volatile("cp.async.wait_group 0;" ::: "memory");
        __syncthreads();
    }

#pragma unroll
    for (int mi = 0; mi < 4; mi++) {
        int r0 = m0 + wm + mi * 16 + lg;
#pragma unroll
        for (int ni = 0; ni < 4; ni++) {
            int c0 = n0 + wn + ni * 8 + 2 * lt;
            float bv0 = bo[c0], bv1 = bo[c0 + 1];
            *reinterpret_cast<float2*>(&out[(size_t)r0 * DMq + c0]) =
                make_float2(acc[mi][ni][0] + bv0, acc[mi][ni][1] + bv1);
            *reinterpret_cast<float2*>(&out[(size_t)(r0 + 8) * DMq + c0]) =
                make_float2(acc[mi][ni][2] + bv0, acc[mi][ni][3] + bv1);
        }
    }
}

// ============================================================
// Launch
// ============================================================
extern "C" void kernel_launch(void* const* d_in, const int* in_sizes, int n_in,
                              void* d_out, int out_size) {
    const float* emb = (const float*)d_in[0];
    const float* pe  = (const float*)d_in[1];
    const float* Wq  = (const float*)d_in[2];
    const float* bq  = (const float*)d_in[3];
    const float* Wk  = (const float*)d_in[4];
    const float* bk  = (const float*)d_in[5];
    const float* Wv  = (const float*)d_in[6];
    const float* bv  = (const float*)d_in[7];
    const float* Wo  = (const float*)d_in[8];
    const float* bo  = (const float*)d_in[9];

    float* out = (float*)d_out;

    const long long need = (long long)NTOK * DMq + (long long)BHq * Sq * Sq;
    float* attn;
    if ((long long)out_size >= need) {
        attn = out + (size_t)NTOK * DMq;
    } else {
        float* p = nullptr;
        cudaGetSymbolAddress((void**)&p, g_attn_fallback);
        attn = p;
    }

    cudaFuncSetAttribute(logits_gemm_tc,
                         cudaFuncAttributeMaxDynamicSharedMemorySize, LOG_SMEM);
    cudaFuncSetAttribute(proj_gemm_v2,
                         cudaFuncAttributeMaxDynamicSharedMemorySize, PROJ_SMEM);
    cudaFuncSetAttribute(out_gemm_v2,
                         cudaFuncAttributeMaxDynamicSharedMemorySize, PROJ_SMEM);

    {
        convert_A<<<(NROWS * DMq + 255) / 256, 256>>>(emb, pe);
    }
    {
        dim3 grid(CC / 32, DMq / 32);
        convert_W<<<grid, dim3(32, 8)>>>(Wq, Wk, Wv);
    }
    {
        dim3 grid(DMq / 32, DMq / 32);
        convert_Wo<<<grid, dim3(32, 8)>>>(Wo);
    }
    {
        dim3 grid(CC / 128, NROWS / 128);
        proj_gemm_v2<<<grid, 256, PROJ_SMEM>>>(bq, bk, bv);
    }
    {
        int total = NTOK * DMq;
        rearrange_kernel<<<(total + 255) / 256, 256>>>();
    }
    {
        zero_rowsum<<<(BHq * Sq + 255) / 256, 256>>>();
    }
    {
        dim3 grid(Sq / 128, Sq / 128, BHq);
        logits_gemm_tc<<<grid, 128, LOG_SMEM>>>();
    }
    {
        dim3 grid(Sq / 128, BHq);
        zv_fused_tc<<<grid, 256>>>(attn);
    }
    {
        dim3 grid(DMq / 128, NTOK / 128);
        out_gemm_v2<<<grid, 256, PROJ_SMEM>>>(bo, out);
    }
}

// round 14
// speedup vs baseline: 2.3353x; 1.0082x over previous
#include <cuda_runtime.h>
#include <cuda_fp16.h>
#include <cstdint>

#define Bq 2
#define Sq 2048
#define Hq 8
#define DEPTHq 64
#define DMq 512
#define NTOK (Bq * Sq)
#define NROWS (2 * NTOK)
#define CC 1536
#define BHq (Bq * Hq)

// ---------------- device scratch ----------------
__device__ __half g_Ch[NROWS * CC];        // proj output, fp16
__device__ __half g_Ah[NROWS * DMq];
__device__ __half g_Wth[CC * DMq];
__device__ __half g_Woth[DMq * DMq];
__device__ __half g_Qh[BHq * Sq * 128];
__device__ __half g_Kh[BHq * Sq * 128];
__device__ __half g_Vh[BHq * Sq * DEPTHq];
__device__ __half g_attn_h[(size_t)BHq * Sq * Sq];
__device__ __half g_Zh[NTOK * DMq];
__device__ float  g_rowsum[BHq * Sq];
__device__ float  g_attn_fallback[(size_t)BHq * Sq * Sq];

// ---------------- helpers ----------------
__device__ __forceinline__ uint32_t ph2(float a, float b) {
    __half2 h = __floats2half2_rn(a, b);
    return *reinterpret_cast<uint32_t*>(&h);
}
__device__ __forceinline__ void mma16(float* c, const uint32_t* a, const uint32_t* b) {
    asm volatile(
        "mma.sync.aligned.m16n8k16.row.col.f32.f16.f16.f32 "
        "{%0,%1,%2,%3}, {%4,%5,%6,%7}, {%8,%9}, {%0,%1,%2,%3};"
        : "+f"(c[0]), "+f"(c[1]), "+f"(c[2]), "+f"(c[3])
        : "r"(a[0]), "r"(a[1]), "r"(a[2]), "r"(a[3]),
          "r"(b[0]), "r"(b[1]));
}
__device__ __forceinline__ uint32_t smem_u32(const void* p) {
    uint32_t a;
    asm("{ .reg .u64 t; cvta.to.shared.u64 t, %1; cvt.u32.u64 %0, t; }" : "=r"(a) : "l"(p));
    return a;
}
__device__ __forceinline__ void cp16(uint32_t dst, const void* src) {
    asm volatile("cp.async.ca.shared.global [%0], [%1], 16;" :: "r"(dst), "l"(src));
}
__device__ __forceinline__ void ldsm4(uint32_t* r, uint32_t addr) {
    asm volatile("ldmatrix.sync.aligned.m8n8.x4.shared.b16 {%0,%1,%2,%3}, [%4];"
                 : "=r"(r[0]), "=r"(r[1]), "=r"(r[2]), "=r"(r[3]) : "r"(addr));
}

// ============================================================
// Kernel 0a: convert [emb;pe] -> fp16
// ============================================================
__global__ void convert_A(const float* __restrict__ emb, const float* __restrict__ pe) {
    int idx = blockIdx.x * 256 + threadIdx.x;
    if (idx >= NROWS * DMq) return;
    float v = (idx < NTOK * DMq) ? emb[idx] : pe[idx - NTOK * DMq];
    g_Ah[idx] = __float2half_rn(v);
}

// ============================================================
// Kernel 0b/0c: weight transposes
// ============================================================
__global__ void convert_W(const float* __restrict__ Wq, const float* __restrict__ Wk,
                          const float* __restrict__ Wv) {
    __shared__ __half t[32][33];
    const int bn = blockIdx.x * 32;
    const int bk = blockIdx.y * 32;
    const int tx = threadIdx.x, ty = threadIdx.y;
    const float* W = (bn < 512) ? Wq : (bn < 1024 ? Wk : Wv);
    const int colbase = bn & 511;
#pragma unroll
    for (int i = 0; i < 32; i += 8)
        t[ty + i][tx] = __float2half_rn(W[(size_t)(bk + ty + i) * DMq + colbase + tx]);
    __syncthreads();
#pragma unroll
    for (int i = 0; i < 32; i += 8)
        g_Wth[(size_t)(bn + ty + i) * DMq + bk + tx] = t[tx][ty + i];
}

__global__ void convert_Wo(const float* __restrict__ Wo) {
    __shared__ __half t[32][33];
    const int bn = blockIdx.x * 32;
    const int bk = blockIdx.y * 32;
    const int tx = threadIdx.x, ty = threadIdx.y;
#pragma unroll
    for (int i = 0; i < 32; i += 8)
        t[ty + i][tx] = __float2half_rn(Wo[(size_t)(bk + ty + i) * DMq + bn + tx]);
    __syncthreads();
#pragma unroll
    for (int i = 0; i < 32; i += 8)
        g_Woth[(size_t)(bn + ty + i) * DMq + bk + tx] = t[tx][ty + i];
}

// ============================================================
// Shared GEMM template constants
// ============================================================
#define PROWB 144
#define PSTG (128 * PROWB)
#define PROJ_SMEM (4 * PSTG)

// ============================================================
// Kernel 1: proj — fp16 epilogue into g_Ch
// ============================================================
__global__ void __launch_bounds__(256)
proj_gemm_v2(const float* __restrict__ bq, const float* __restrict__ bk,
             const float* __restrict__ bv) {
    extern __shared__ char dsm[];
    const uint32_t sa = smem_u32(dsm);
    const uint32_t sb = sa + 2 * PSTG;

    const int m0 = blockIdx.y * 128;
    const int n0 = blockIdx.x * 128;
    const int tid = threadIdx.x;
    const int wid = tid >> 5, lane = tid & 31;
    const int wm = (wid >> 2) * 64, wn = (wid & 3) * 32;
    const int lg = lane >> 2, lt = lane & 3;

    const float* bias = (n0 < 512) ? bq : (n0 < 1024 ? bk : bv);

    const int crow = tid >> 3;
    const int ccc = tid & 7;

    float acc[4][4][4];
#pragma unroll
    for (int i = 0; i < 4; i++)
#pragma unroll
        for (int j = 0; j < 4; j++)
#pragma unroll
            for (int r = 0; r < 4; r++) acc[i][j][r] = 0.f;

    {
#pragma unroll
        for (int i = 0; i < 4; i++) {
            int row = crow + i * 32;
            cp16(sa + row * PROWB + ccc * 16, g_Ah + (size_t)(m0 + row) * DMq + ccc * 8);
            cp16(sb + row * PROWB + ccc * 16, g_Wth + (size_t)(n0 + row) * DMq + ccc * 8);
        }
        asm volatile("cp.async.commit_group;" ::: "memory");
        asm volatile("cp.async.wait_group 0;" ::: "memory");
    }
    __syncthreads();

    const uint32_t aAddrBase = (uint32_t)(wm + (lane & 15)) * PROWB + ((lane >> 4) & 1) * 16;
    const uint32_t bAddrBase = (uint32_t)(wn + ((lane >> 4) & 1) * 8 + (lane & 7)) * PROWB +
                               ((lane >> 3) & 1) * 16;

    const int NST = DMq / 64;
    for (int s = 0; s < NST; s++) {
        const int st = s & 1;
        const bool more = (s + 1 < NST);
        if (more) {
            int k0 = (s + 1) * 64;
#pragma unroll
            for (int i = 0; i < 4; i++) {
                int row = crow + i * 32;
                cp16(sa + (st ^ 1) * PSTG + row * PROWB + ccc * 16,
                     g_Ah + (size_t)(m0 + row) * DMq + k0 + ccc * 8);
                cp16(sb + (st ^ 1) * PSTG + row * PROWB + ccc * 16,
                     g_Wth + (size_t)(n0 + row) * DMq + k0 + ccc * 8);
            }
            asm volatile("cp.async.commit_group;" ::: "memory");
        }
        const uint32_t sas = sa + st * PSTG;
        const uint32_t sbs = sb + st * PSTG;
#pragma unroll
        for (int c = 0; c < 4; c++) {
            const uint32_t coff = c * 32;
            uint32_t bf[4][2];
#pragma unroll
            for (int np = 0; np < 2; np++) {
                uint32_t r4[4];
                ldsm4(r4, sbs + bAddrBase + np * 16 * PROWB + coff);
                bf[2 * np][0] = r4[0];
                bf[2 * np][1] = r4[1];
                bf[2 * np + 1][0] = r4[2];
                bf[2 * np + 1][1] = r4[3];
            }
#pragma unroll
            for (int mi = 0; mi < 4; mi++) {
                uint32_t af[4];
                ldsm4(af, sas + aAddrBase + mi * 16 * PROWB + coff);
#pragma unroll
                for (int ni = 0; ni < 4; ni++) mma16(acc[mi][ni], af, bf[ni]);
            }
        }
        if (more) asm volatile("cp.async.wait_group 0;" ::: "memory");
        __syncthreads();
    }

#pragma unroll
    for (int mi = 0; mi < 4; mi++) {
        int r0 = m0 + wm + mi * 16 + lg;
#pragma unroll
        for (int ni = 0; ni < 4; ni++) {
            int c0 = n0 + wn + ni * 8 + 2 * lt;
            float bv0 = bias[(c0) & 511], bv1 = bias[(c0 + 1) & 511];
            *reinterpret_cast<uint32_t*>(&g_Ch[(size_t)r0 * CC + c0]) =
                ph2(acc[mi][ni][0] + bv0, acc[mi][ni][1] + bv1);
            *reinterpret_cast<uint32_t*>(&g_Ch[(size_t)(r0 + 8) * CC + c0]) =
                ph2(acc[mi][ni][2] + bv0, acc[mi][ni][3] + bv1);
        }
    }
}

// ============================================================
// Kernel 2: rearrange — fp16 in/out, half2-vectorized
// ============================================================
__global__ void rearrange_kernel() {
    int idx = blockIdx.x * blockDim.x + threadIdx.x;
    if (idx >= NTOK * (DMq / 2)) return;
    int n = idx / (DMq / 2);
    int c = (idx % (DMq / 2)) * 2;
    int b = n / Sq, s = n % Sq;
    int h = c / DEPTHq, d = c % DEPTHq;

    float2 qc = __half22float2(*(const __half2*)&g_Ch[(size_t)n * CC + c]);
    float2 qr = __half22float2(*(const __half2*)&g_Ch[(size_t)(NTOK + n) * CC + c]);
    __half2 kc = *(const __half2*)&g_Ch[(size_t)n * CC + 512 + c];
    __half2 kr = *(const __half2*)&g_Ch[(size_t)(NTOK + n) * CC + 512 + c];
    __half2 vv = *(const __half2*)&g_Ch[(size_t)n * CC + 1024 + c];

    size_t base = ((size_t)(b * Hq + h) * Sq + s) * 128;
    *reinterpret_cast<uint32_t*>(&g_Qh[base + d]) =
        ph2((qc.x + qr.x) * 0.125f, (qc.y + qr.y) * 0.125f);
    *reinterpret_cast<uint32_t*>(&g_Qh[base + 64 + d]) =
        ph2(qc.x * 0.125f, qc.y * 0.125f);
    *(__half2*)&g_Kh[base + d] = kc;
    *(__half2*)&g_Kh[base + 64 + d] = kr;
    *(__half2*)&g_Vh[((size_t)(b * Hq + h) * Sq + s) * DEPTHq + d] = vv;
}

__global__ void zero_rowsum() {
    int i = blockIdx.x * 256 + threadIdx.x;
    if (i < BHq * Sq) g_rowsum[i] = 0.f;
}

// ============================================================
// Kernel 3: logits (R10 design, unchanged)
// ============================================================
#define ROWB 272
#define LOG_SMEM (2 * 128 * ROWB)

__global__ void __launch_bounds__(128)
logits_gemm_tc() {
    extern __shared__ char dsm[];
    const uint32_t sa = smem_u32(dsm);
    const uint32_t sb = sa + 128 * ROWB;

    const int bh = blockIdx.z;
    const int q0 = blockIdx.y * 128;
    const int t0 = blockIdx.x * 128;
    const __half* Q = g_Qh + (size_t)bh * Sq * 128;
    const __half* K = g_Kh + (size_t)bh * Sq * 128;
    __half* outh = g_attn_h + (size_t)bh * Sq * Sq;

    const int tid = threadIdx.x;
    const int wid = tid >> 5, lane = tid & 31;
    const int wm = (wid >> 1) * 64, wn = (wid & 1) * 64;
    const int lg = lane >> 2, lt = lane & 3;

    {
        const int cr = tid >> 4;
        const int cc = tid & 15;
#pragma unroll
        for (int i = 0; i < 16; i++) {
            int row = i * 8 + cr;
            cp16(sa + row * ROWB + cc * 16, Q + (size_t)(q0 + row) * 128 + cc * 8);
            cp16(sb + row * ROWB + cc * 16, K + (size_t)(t0 + row) * 128 + cc * 8);
        }
        asm volatile("cp.async.commit_group;" ::: "memory");
        asm volatile("cp.async.wait_group 0;" ::: "memory");
    }
    __syncthreads();

    float acc[4][8][4];
#pragma unroll
    for (int i = 0; i < 4; i++)
#pragma unroll
        for (int j = 0; j < 8; j++)
#pragma unroll
            for (int r = 0; r < 4; r++) acc[i][j][r] = 0.f;

    const uint32_t aAddrBase = sa + (uint32_t)(wm + (lane & 15)) * ROWB + ((lane >> 4) & 1) * 16;
    const uint32_t bAddrBase = sb + (uint32_t)(wn + ((lane >> 4) & 1) * 8 + (lane & 7)) * ROWB +
                               ((lane >> 3) & 1) * 16;

#pragma unroll
    for (int c = 0; c < 8; c++) {
        const uint32_t coff = c * 32;
        uint32_t bf[8][2];
#pragma unroll
        for (int np = 0; np < 4; np++) {
            uint32_t r4[4];
            ldsm4(r4, bAddrBase + np * 16 * ROWB + coff);
            bf[2 * np][0] = r4[0];
            bf[2 * np][1] = r4[1];
            bf[2 * np + 1][0] = r4[2];
            bf[2 * np + 1][1] = r4[3];
        }
#pragma unroll
        for (int mi = 0; mi < 4; mi++) {
            uint32_t af[4];
            ldsm4(af, aAddrBase + mi * 16 * ROWB + coff);
#pragma unroll
            for (int ni = 0; ni < 8; ni++) mma16(acc[mi][ni], af, bf[ni]);
        }
    }

#pragma unroll
    for (int mi = 0; mi < 4; mi++) {
        int r0 = q0 + wm + mi * 16 + lg;
        float rs0 = 0.f, rs1 = 0.f;
#pragma unroll
        for (int ni = 0; ni < 8; ni++) {
            int c0 = t0 + wn + ni * 8 + 2 * lt;
            __half2 h01 = __floats2half2_rn(__expf(acc[mi][ni][0]), __expf(acc[mi][ni][1]));
            __half2 h23 = __floats2half2_rn(__expf(acc[mi][ni][2]), __expf(acc[mi][ni][3]));
            *reinterpret_cast<uint32_t*>(&outh[(size_t)r0 * Sq + c0]) =
                *reinterpret_cast<uint32_t*>(&h01);
            *reinterpret_cast<uint32_t*>(&outh[(size_t)(r0 + 8) * Sq + c0]) =
                *reinterpret_cast<uint32_t*>(&h23);
            float2 f01 = __half22float2(h01);
            float2 f23 = __half22float2(h23);
            rs0 += f01.x + f01.y;
            rs1 += f23.x + f23.y;
        }
        rs0 += __shfl_xor_sync(0xffffffffu, rs0, 1);
        rs0 += __shfl_xor_sync(0xffffffffu, rs0, 2);
        rs1 += __shfl_xor_sync(0xffffffffu, rs1, 1);
        rs1 += __shfl_xor_sync(0xffffffffu, rs1, 2);
        if (lt == 0) {
            atomicAdd(&g_rowsum[bh * Sq + r0], rs0);
            atomicAdd(&g_rowsum[bh * Sq + r0 + 8], rs1);
        }
    }
}

// ============================================================
// Kernel 5: zv (R13 design, unchanged)
// ============================================================
#define AROWB 48
#define ZASTG (128 * AROWB)

__global__ void __launch_bounds__(256, 2)
zv_fused_tc(float* __restrict__ attn) {
    __shared__ __align__(16) char  ZA[2 * ZASTG];
    __shared__ __align__(16) uint32_t SB[2][64][8];

    const int bh = blockIdx.y;
    const int q0 = blockIdx.x * 128;
    const int b = bh / Hq, h = bh % Hq;
    const __half* Ph = g_attn_h + (size_t)bh * Sq * Sq;
    float* Pout = attn + (size_t)bh * Sq * Sq;
    const __half* V = g_Vh + (size_t)bh * Sq * DEPTHq;

    const int tid = threadIdx.x;
    const int wid = tid >> 5, lane = tid & 31;
    const int wm = (wid >> 1) * 32, wn = (wid & 1) * 32;
    const int lg = lane >> 2, lt = lane & 3;

    const uint32_t za = smem_u32(ZA);

    const int arow = tid >> 1, ahalf = tid & 1;
    const __half* agsrc = Ph + (size_t)(q0 + arow) * Sq + ahalf * 8;
    float* aout = Pout + (size_t)(q0 + arow) * Sq + ahalf * 8;
    const uint32_t adst = za + arow * AROWB + ahalf * 16;
    const float invs = 1.0f / g_rowsum[bh * Sq + q0 + arow];

    const int kp = tid >> 5, bn_ = (tid & 31) * 2;
    const int slot = (kp < 4) ? 2 * kp : 2 * (kp - 4) + 1;

    const uint32_t aAddrBase = za + (uint32_t)(wm + (lane & 15)) * AROWB + ((lane >> 4) & 1) * 16;

    float acc[2][4][4];
#pragma unroll
    for (int i = 0; i < 2; i++)
#pragma unroll
        for (int j = 0; j < 4; j++)
#pragma unroll
            for (int r = 0; r < 4; r++) acc[i][j][r] = 0.f;

    const int NIT = Sq / 16;

    {
        cp16(adst, agsrc);
        asm volatile("cp.async.commit_group;" ::: "memory");
        const __half* vp = V + (size_t)(2 * kp) * DEPTHq + bn_;
        uint32_t x0 = *(const uint32_t*)vp;
        uint32_t x1 = *(const uint32_t*)(vp + DEPTHq);
        SB[0][bn_][slot]     = __byte_perm(x0, x1, 0x5410);
        SB[0][bn_ + 1][slot] = __byte_perm(x0, x1, 0x7632);
        asm volatile("cp.async.wait_group 0;" ::: "memory");
    }
    __syncthreads();

    for (int it = 0; it < NIT; it++) {
        const int st = it & 1;
        const bool more = (it + 1 < NIT);
        uint32_t x0, x1;
        if (more) {
            int k0 = (it + 1) * 16;
            cp16(adst + (st ^ 1) * ZASTG, agsrc + k0);
            asm volatile("cp.async.commit_group;" ::: "memory");
            const __half* vp = V + (size_t)(k0 + 2 * kp) * DEPTHq + bn_;
            x0 = *(const uint32_t*)vp;
            x1 = *(const uint32_t*)(vp + DEPTHq);
        }

        {
            uint4 u = *reinterpret_cast<const uint4*>(ZA + st * ZASTG + arow * AROWB + ahalf * 16);
            float2 p0 = __half22float2(*reinterpret_cast<__half2*>(&u.x));
            float2 p1 = __half22float2(*reinterpret_cast<__half2*>(&u.y));
            float2 p2 = __half22float2(*reinterpret_cast<__half2*>(&u.z));
            float2 p3 = __half22float2(*reinterpret_cast<__half2*>(&u.w));
            *(float4*)(aout + it * 16)     = make_float4(p0.x * invs, p0.y * invs, p1.x * invs, p1.y * invs);
            *(float4*)(aout + it * 16 + 4) = make_float4(p2.x * invs, p2.y * invs, p3.x * invs, p3.y * invs);
        }

        {
            uint32_t af[2][4], bf[4][2];
#pragma unroll
            for (int mi = 0; mi < 2; mi++)
                ldsm4(af[mi], aAddrBase + st * ZASTG + mi * 16 * AROWB);
#pragma unroll
            for (int ni = 0; ni < 4; ni++) {
                uint2 bb = *(const uint2*)&SB[st][wn + ni * 8 + lg][2 * lt];
                bf[ni][0] = bb.x; bf[ni][1] = bb.y;
            }
#pragma unroll
            for (int mi = 0; mi < 2; mi++)
#pragma unroll
                for (int ni = 0; ni < 4; ni++) mma16(acc[mi][ni], af[mi], bf[ni]);
        }

        if (more) {
            SB[st ^ 1][bn_][slot]     = __byte_perm(x0, x1, 0x5410);
            SB[st ^ 1][bn_ + 1][slot] = __byte_perm(x0, x1, 0x7632);
            asm volatile("cp.async.wait_group 0;" ::: "memory");
        }
        __syncthreads();
    }

#pragma unroll
    for (int mi = 0; mi < 2; mi++) {
        int r0 = q0 + wm + mi * 16 + lg;
        float iv0 = 1.0f / g_rowsum[bh * Sq + r0];
        float iv1 = 1.0f / g_rowsum[bh * Sq + r0 + 8];
#pragma unroll
        for (int ni = 0; ni < 4; ni++) {
            int c0 = wn + ni * 8 + 2 * lt;
            size_t base0 = ((size_t)b * Sq + r0) * DMq + h * DEPTHq + c0;
            size_t base1 = ((size_t)b * Sq + r0 + 8) * DMq + h * DEPTHq + c0;
            *reinterpret_cast<uint32_t*>(&g_Zh[base0]) =
                ph2(acc[mi][ni][0] * iv0, acc[mi][ni][1] * iv0);
            *reinterpret_cast<uint32_t*>(&g_Zh[base1]) =
                ph2(acc[mi][ni][2] * iv1, acc[mi][ni][3] * iv1);
        }
    }
}

// ============================================================
// Kernel 6: out (R13 design, unchanged)
// ============================================================
__global__ void __launch_bounds__(256)
out_gemm_v2(const float* __restrict__ bo, float* __restrict__ out) {
    extern __shared__ char dsm[];
    const uint32_t sa = smem_u32(dsm);
    const uint32_t sb = sa + 2 * PSTG;

    const int m0 = blockIdx.y * 128;
    const int n0 = blockIdx.x * 128;
    const int tid = threadIdx.x;
    const int wid = tid >> 5, lane = tid & 31;
    const int wm = (wid >> 2) * 64, wn = (wid & 3) * 32;
    const int lg = lane >> 2, lt = lane & 3;

    const int crow = tid >> 3;
    const int ccc = tid & 7;

    float acc[4][4][4];
#pragma unroll
    for (int i = 0; i < 4; i++)
#pragma unroll
        for (int j = 0; j < 4; j++)
#pragma unroll
            for (int r = 0; r < 4; r++) acc[i][j][r] = 0.f;

    {
#pragma unroll
        for (int i = 0; i < 4; i++) {
            int row = crow + i * 32;
            cp16(sa + row * PROWB + ccc * 16, g_Zh + (size_t)(m0 + row) * DMq + ccc * 8);
            cp16(sb + row * PROWB + ccc * 16, g_Woth + (size_t)(n0 + row) * DMq + ccc * 8);
        }
        asm volatile("cp.async.commit_group;" ::: "memory");
        asm volatile("cp.async.wait_group 0;" ::: "memory");
    }
    __syncthreads();

    const uint32_t aAddrBase = (uint32_t)(wm + (lane & 15)) * PROWB + ((lane >> 4) & 1) * 16;
    const uint32_t bAddrBase = (uint32_t)(wn + ((lane >> 4) & 1) * 8 + (lane & 7)) * PROWB +
                               ((lane >> 3) & 1) * 16;

    const int NST = DMq / 64;
    for (int s = 0; s < NST; s++) {
        const int st = s & 1;
        const bool more = (s + 1 < NST);
        if (more) {
            int k0 = (s + 1) * 64;
#pragma unroll
            for (int i = 0; i < 4; i++) {
                int row = crow + i * 32;
                cp16(sa + (st ^ 1) * PSTG + row * PROWB + ccc * 16,
                     g_Zh + (size_t)(m0 + row) * DMq + k0 + ccc * 8);
                cp16(sb + (st ^ 1) * PSTG + row * PROWB + ccc * 16,
                     g_Woth + (size_t)(n0 + row) * DMq + k0 + ccc * 8);
            }
            asm volatile("cp.async.commit_group;" ::: "memory");
        }
        const uint32_t sas = sa + st * PSTG;
        const uint32_t sbs = sb + st * PSTG;
#pragma unroll
        for (int c = 0; c < 4; c++) {
            const uint32_t coff = c * 32;
            uint32_t bf[4][2];
#pragma unroll
            for (int np = 0; np < 2; np++) {
                uint32_t r4[4];
                ldsm4(r4, sbs + bAddrBase + np * 16 * PROWB + coff);
                bf[2 * np][0] = r4[0];
                bf[2 * np][1] = r4[1];
                bf[2 * np + 1][0] = r4[2];
                bf[2 * np + 1][1] = r4[3];
            }
#pragma unroll
            for (int mi = 0; mi < 4; mi++) {
                uint32_t af[4];
                ldsm4(af, sas + aAddrBase + mi * 16 * PROWB + coff);
#pragma unroll
                for (int ni = 0; ni < 4; ni++) mma16(acc[mi][ni], af, bf[ni]);
            }
        }
        if (more) asm volatile("cp.async.wait_group 0;" ::: "memory");
        __syncthreads();
    }

#pragma unroll
    for (int mi = 0; mi < 4; mi++) {
        int r0 = m0 + wm + mi * 16 + lg;
#pragma unroll
        for (int ni = 0; ni < 4; ni++) {
            int c0 = n0 + wn + ni * 8 + 2 * lt;
            float bv0 = bo[c0], bv1 = bo[c0 + 1];
            *reinterpret_cast<float2*>(&out[(size_t)r0 * DMq + c0]) =
                make_float2(acc[mi][ni][0] + bv0, acc[mi][ni][1] + bv1);
            *reinterpret_cast<float2*>(&out[(size_t)(r0 + 8) * DMq + c0]) =
                make_float2(acc[mi][ni][2] + bv0, acc[mi][ni][3] + bv1);
        }
    }
}

// ============================================================
// Launch
// ============================================================
extern "C" void kernel_launch(void* const* d_in, const int* in_sizes, int n_in,
                              void* d_out, int out_size) {
    const float* emb = (const float*)d_in[0];
    const float* pe  = (const float*)d_in[1];
    const float* Wq  = (const float*)d_in[2];
    const float* bq  = (const float*)d_in[3];
    const float* Wk  = (const float*)d_in[4];
    const float* bk  = (const float*)d_in[5];
    const float* Wv  = (const float*)d_in[6];
    const float* bv  = (const float*)d_in[7];
    const float* Wo  = (const float*)d_in[8];
    const float* bo  = (const float*)d_in[9];

    float* out = (float*)d_out;

    const long long need = (long long)NTOK * DMq + (long long)BHq * Sq * Sq;
    float* attn;
    if ((long long)out_size >= need) {
        attn = out + (size_t)NTOK * DMq;
    } else {
        float* p = nullptr;
        cudaGetSymbolAddress((void**)&p, g_attn_fallback);
        attn = p;
    }

    cudaFuncSetAttribute(logits_gemm_tc,
                         cudaFuncAttributeMaxDynamicSharedMemorySize, LOG_SMEM);
    cudaFuncSetAttribute(proj_gemm_v2,
                         cudaFuncAttributeMaxDynamicSharedMemorySize, PROJ_SMEM);
    cudaFuncSetAttribute(out_gemm_v2,
                         cudaFuncAttributeMaxDynamicSharedMemorySize, PROJ_SMEM);

    {
        convert_A<<<(NROWS * DMq + 255) / 256, 256>>>(emb, pe);
    }
    {
        dim3 grid(CC / 32, DMq / 32);
        convert_W<<<grid, dim3(32, 8)>>>(Wq, Wk, Wv);
    }
    {
        dim3 grid(DMq / 32, DMq / 32);
        convert_Wo<<<grid, dim3(32, 8)>>>(Wo);
    }
    {
        dim3 grid(CC / 128, NROWS / 128);
        proj_gemm_v2<<<grid, 256, PROJ_SMEM>>>(bq, bk, bv);
    }
    {
        int total = NTOK * (DMq / 2);
        rearrange_kernel<<<(total + 255) / 256, 256>>>();
    }
    {
        zero_rowsum<<<(BHq * Sq + 255) / 256, 256>>>();
    }
    {
        dim3 grid(Sq / 128, Sq / 128, BHq);
        logits_gemm_tc<<<grid, 128, LOG_SMEM>>>();
    }
    {
        dim3 grid(Sq / 128, BHq);
        zv_fused_tc<<<grid, 256>>>(attn);
    }
    {
        dim3 grid(DMq / 128, NTOK / 128);
        out_gemm_v2<<<grid, 256, PROJ_SMEM>>>(bo, out);
    }
}